// round 4
// baseline (speedup 1.0000x reference)
#include <cuda_runtime.h>
#include <math.h>

#define Bc 8
#define Nn 2048
#define DFc 128
#define Ec 128
#define Hc 4

// ---------------- scratch (static device arrays; no allocation) ----------------
__device__ float g_g[Bc * Ec * DFc];                     // [b][e][d]
__device__ float g_emb[Bc * Nn * Ec];                    // [b][n][e]
__device__ float g_q[(size_t)Bc * Hc * Nn * Ec];         // [b][h][n][f]
__device__ float g_v[(size_t)Bc * Hc * Nn * Ec];         // [b][h][n][f]
__device__ float g_u[Bc * Hc * DFc * Ec];                // [b][h][d][f]
__device__ float g_r[(size_t)Bc * Hc * Nn * DFc];        // [b][h][n][d]
__device__ float g_h[(size_t)Bc * Nn * Hc * Ec];         // hcat [b][n][h][f]
// hi/lo split operands for the attention kernel (tf32 bit patterns stored as float)
__device__ float g_rhi[(size_t)Bc * Hc * Nn * DFc];
__device__ float g_rlo[(size_t)Bc * Hc * Nn * DFc];
__device__ float g_vhi[(size_t)Bc * Hc * Nn * Ec];
__device__ float g_vlo[(size_t)Bc * Hc * Nn * Ec];
__device__ float g_xhi[Bc * Nn * DFc];
__device__ float g_xlo[Bc * Nn * DFc];

// ---------------- zero init ----------------
__global__ void zero_kernel(float* p, int n) {
    int i = blockIdx.x * blockDim.x + threadIdx.x;
    if (i < n) p[i] = 0.0f;
}

// ---------------- tf32 helpers ----------------
__device__ __forceinline__ unsigned f2tf(float f) {
    unsigned u;
    asm("cvt.rna.tf32.f32 %0, %1;" : "=r"(u) : "f"(f));
    return u;
}

__device__ __forceinline__ void mma_tf32(float c[4], const unsigned a[4], const unsigned b[2]) {
    asm volatile(
        "mma.sync.aligned.m16n8k8.row.col.f32.tf32.tf32.f32 "
        "{%0,%1,%2,%3}, {%4,%5,%6,%7}, {%8,%9}, {%0,%1,%2,%3};"
        : "+f"(c[0]), "+f"(c[1]), "+f"(c[2]), "+f"(c[3])
        : "r"(a[0]), "r"(a[1]), "r"(a[2]), "r"(a[3]), "r"(b[0]), "r"(b[1]));
}

__device__ __forceinline__ float tanh_fast(float x) {
    float y;
    asm("tanh.approx.f32 %0, %1;" : "=f"(y) : "f"(x));
    return y;
}

// ---------------- elementwise hi/lo split (for x) ----------------
__global__ void split_kernel(const float* __restrict__ in,
                             float* __restrict__ hi, float* __restrict__ lo, int n4) {
    int i = blockIdx.x * blockDim.x + threadIdx.x;
    if (i >= n4) return;
    float4 v = ((const float4*)in)[i];
    float4 h4, l4;
    unsigned u;
    u = f2tf(v.x); h4.x = __uint_as_float(u); l4.x = __uint_as_float(f2tf(v.x - h4.x));
    u = f2tf(v.y); h4.y = __uint_as_float(u); l4.y = __uint_as_float(f2tf(v.y - h4.y));
    u = f2tf(v.z); h4.z = __uint_as_float(u); l4.z = __uint_as_float(f2tf(v.z - h4.z));
    u = f2tf(v.w); h4.w = __uint_as_float(u); l4.w = __uint_as_float(f2tf(v.w - h4.w));
    ((float4*)hi)[i] = h4;
    ((float4*)lo)[i] = l4;
}

// ================= unified 3xTF32 tensor GEMM =================
// C[M,N=128] = act( sum_k A[m,k] B[n,k] + bias[n] ); optional hi/lo split outputs.
__global__ __launch_bounds__(256, 1) void tf32_gemm(
    const float* __restrict__ A, long a_sb, int a_div, int a_sm, int a_sk,
    const float* __restrict__ Bm, long b_sb, int b_mod, int b_sn, int b_sk,
    const float* __restrict__ bias, int bias_sb,
    float* __restrict__ C, long c_sb,
    float* __restrict__ Chi, float* __restrict__ Clo,
    int K, int ksplit, int act)
{
    __shared__ float As[128 * 36];
    __shared__ float Bs[128 * 36];

    int by = blockIdx.y;
    int m0 = blockIdx.x * 128;
    const float* Ab = A + (long)(by / a_div) * a_sb + (long)m0 * a_sm;
    const float* Bb = Bm + (long)(by % b_mod) * b_sb;
    long cbase = (long)by * c_sb + (long)m0 * 128;
    float* Cb = C + cbase;

    int Kper = K / ksplit;
    int k0base = blockIdx.z * Kper;

    int t = threadIdx.x;
    int warp = t >> 5;
    int lane = t & 31;
    int g = lane >> 2;
    int q = lane & 3;
    int wm = warp >> 1;
    int wn = warp & 1;

    float acc[2][8][4];
#pragma unroll
    for (int mt = 0; mt < 2; mt++)
#pragma unroll
        for (int nt = 0; nt < 8; nt++)
#pragma unroll
            for (int c = 0; c < 4; c++) acc[mt][nt][c] = 0.0f;

    for (int kc0 = 0; kc0 < Kper; kc0 += 32) {
        int k0 = k0base + kc0;
        __syncthreads();
        if (a_sk == 1) {
            int row = t >> 1;
            int c4 = (t & 1) * 16;
            const float* src = Ab + (long)row * a_sm + k0 + c4;
            float4 v0 = *(const float4*)(src);
            float4 v1 = *(const float4*)(src + 4);
            float4 v2 = *(const float4*)(src + 8);
            float4 v3 = *(const float4*)(src + 12);
            float* dst = &As[row * 36 + c4];
            *(float4*)(dst) = v0; *(float4*)(dst + 4) = v1;
            *(float4*)(dst + 8) = v2; *(float4*)(dst + 12) = v3;
        } else {
            int row = t & 127;
            int kb = (t >> 7) * 16;
#pragma unroll
            for (int e = 0; e < 16; e++)
                As[row * 36 + kb + e] = Ab[(long)row * a_sm + (long)(k0 + kb + e) * a_sk];
        }
        if (b_sk == 1) {
            int row = t >> 1;
            int c4 = (t & 1) * 16;
            const float* src = Bb + (long)row * b_sn + k0 + c4;
            float4 v0 = *(const float4*)(src);
            float4 v1 = *(const float4*)(src + 4);
            float4 v2 = *(const float4*)(src + 8);
            float4 v3 = *(const float4*)(src + 12);
            float* dst = &Bs[row * 36 + c4];
            *(float4*)(dst) = v0; *(float4*)(dst + 4) = v1;
            *(float4*)(dst + 8) = v2; *(float4*)(dst + 12) = v3;
        } else {
            int row = t & 127;
            int kb = (t >> 7) * 16;
#pragma unroll
            for (int e = 0; e < 16; e++)
                Bs[row * 36 + kb + e] = Bb[(long)row * b_sn + (long)(k0 + kb + e) * b_sk];
        }
        __syncthreads();

#pragma unroll
        for (int kc = 0; kc < 4; kc++) {
            int k8 = kc * 8;
            unsigned ah[2][4], al[2][4];
#pragma unroll
            for (int mt = 0; mt < 2; mt++) {
                int mr = wm * 32 + mt * 16;
                float e0 = As[(mr + g) * 36 + k8 + q];
                float e1 = As[(mr + g + 8) * 36 + k8 + q];
                float e2 = As[(mr + g) * 36 + k8 + q + 4];
                float e3 = As[(mr + g + 8) * 36 + k8 + q + 4];
                ah[mt][0] = f2tf(e0); al[mt][0] = f2tf(e0 - __uint_as_float(ah[mt][0]));
                ah[mt][1] = f2tf(e1); al[mt][1] = f2tf(e1 - __uint_as_float(ah[mt][1]));
                ah[mt][2] = f2tf(e2); al[mt][2] = f2tf(e2 - __uint_as_float(ah[mt][2]));
                ah[mt][3] = f2tf(e3); al[mt][3] = f2tf(e3 - __uint_as_float(ah[mt][3]));
            }
            unsigned bh[8][2], bl[8][2];
#pragma unroll
            for (int nt = 0; nt < 8; nt++) {
                int nr = wn * 64 + nt * 8 + g;
                float e0 = Bs[nr * 36 + k8 + q];
                float e1 = Bs[nr * 36 + k8 + q + 4];
                bh[nt][0] = f2tf(e0); bl[nt][0] = f2tf(e0 - __uint_as_float(bh[nt][0]));
                bh[nt][1] = f2tf(e1); bl[nt][1] = f2tf(e1 - __uint_as_float(bh[nt][1]));
            }
#pragma unroll
            for (int mt = 0; mt < 2; mt++)
#pragma unroll
                for (int nt = 0; nt < 8; nt++) {
                    mma_tf32(acc[mt][nt], ah[mt], bh[nt]);
                    mma_tf32(acc[mt][nt], ah[mt], bl[nt]);
                    mma_tf32(acc[mt][nt], al[mt], bh[nt]);
                }
        }
    }

    if (ksplit > 1) {
#pragma unroll
        for (int mt = 0; mt < 2; mt++)
#pragma unroll
            for (int nt = 0; nt < 8; nt++) {
                int mr = wm * 32 + mt * 16 + g;
                int nc = wn * 64 + nt * 8 + 2 * q;
                atomicAdd(&Cb[(long)mr * 128 + nc], acc[mt][nt][0]);
                atomicAdd(&Cb[(long)mr * 128 + nc + 1], acc[mt][nt][1]);
                atomicAdd(&Cb[(long)(mr + 8) * 128 + nc], acc[mt][nt][2]);
                atomicAdd(&Cb[(long)(mr + 8) * 128 + nc + 1], acc[mt][nt][3]);
            }
    } else {
        const float* bp = bias ? (bias + (long)(by % b_mod) * bias_sb) : nullptr;
#pragma unroll
        for (int mt = 0; mt < 2; mt++)
#pragma unroll
            for (int nt = 0; nt < 8; nt++) {
                int mr = wm * 32 + mt * 16 + g;
                int nc = wn * 64 + nt * 8 + 2 * q;
                float b0 = bp ? bp[nc] : 0.0f;
                float b1 = bp ? bp[nc + 1] : 0.0f;
                float o00 = acc[mt][nt][0] + b0, o01 = acc[mt][nt][1] + b1;
                float o10 = acc[mt][nt][2] + b0, o11 = acc[mt][nt][3] + b1;
                if (act == 1) {
                    o00 = fmaxf(o00, 0.0f); o01 = fmaxf(o01, 0.0f);
                    o10 = fmaxf(o10, 0.0f); o11 = fmaxf(o11, 0.0f);
                }
                long i0 = (long)mr * 128 + nc;
                long i1 = (long)(mr + 8) * 128 + nc;
                *(float2*)&Cb[i0] = make_float2(o00, o01);
                *(float2*)&Cb[i1] = make_float2(o10, o11);
                if (Chi) {
                    float h00 = __uint_as_float(f2tf(o00)), h01 = __uint_as_float(f2tf(o01));
                    float h10 = __uint_as_float(f2tf(o10)), h11 = __uint_as_float(f2tf(o11));
                    *(float2*)&Chi[cbase + i0] = make_float2(h00, h01);
                    *(float2*)&Chi[cbase + i1] = make_float2(h10, h11);
                    *(float2*)&Clo[cbase + i0] = make_float2(
                        __uint_as_float(f2tf(o00 - h00)), __uint_as_float(f2tf(o01 - h01)));
                    *(float2*)&Clo[cbase + i1] = make_float2(
                        __uint_as_float(f2tf(o10 - h10)), __uint_as_float(f2tf(o11 - h11)));
                }
            }
    }
}

// ================= pre-split tensor-core fused attention =================
// h = tanh( (r x^T)/sqrt(E) ) v per (b,h); all operands pre-split hi/lo (tf32 bits).
// Block: 64 m-rows, p-tiles of 64, 512 threads (16 warps).
// Warp layout: wm = warp>>2 (m16 tile), wq = warp&3 (p16 for S-gemm / f32 for GEMM2).
#define AT2_RSH 0
#define AT2_RSL (64 * 132)
#define AT2_XSH (2 * 64 * 132)
#define AT2_XSL (3 * 64 * 132)
#define AT2_VSH (4 * 64 * 132)
#define AT2_VSL (4 * 64 * 132 + 64 * 136)
#define AT2_SS  (4 * 64 * 132 + 2 * 64 * 136)
#define AT2_FLOATS (AT2_SS + 64 * 68)

__global__ __launch_bounds__(512, 1) void attn_mma2_kernel(
    const float* __restrict__ rhi, const float* __restrict__ rlo,
    const float* __restrict__ xhi, const float* __restrict__ xlo,
    const float* __restrict__ vhi, const float* __restrict__ vlo,
    float* __restrict__ hcat)
{
    extern __shared__ float sm[];
    float* rsh = sm + AT2_RSH;   // [m][k] stride 132
    float* rsl = sm + AT2_RSL;
    float* xsh = sm + AT2_XSH;   // [p][k] stride 132
    float* xsl = sm + AT2_XSL;
    float* vsh = sm + AT2_VSH;   // [p][f] stride 136
    float* vsl = sm + AT2_VSL;
    float* Ss  = sm + AT2_SS;    // [m][p] stride 68 (tf32 bits of attn)

    const float inv_scale = 0.08838834764831845f;  // 1/sqrt(128)

    int by = blockIdx.y;
    int b = by >> 2;
    int h = by & 3;
    int m0 = blockIdx.x * 64;

    const float* rhb = rhi + (long)by * Nn * DFc + (long)m0 * DFc;
    const float* rlb = rlo + (long)by * Nn * DFc + (long)m0 * DFc;
    const float* xhb = xhi + (long)b * Nn * DFc;
    const float* xlb = xlo + (long)b * Nn * DFc;
    const float* vhb = vhi + (long)by * Nn * Ec;
    const float* vlb = vlo + (long)by * Nn * Ec;

    int t = threadIdx.x;
    int warp = t >> 5;
    int lane = t & 31;
    int g = lane >> 2;
    int q = lane & 3;
    int wm = warp >> 2;     // 0..3 -> m tile at wm*16
    int wq = warp & 3;      // 0..3 -> p16 (S) / f32 (GEMM2)
    int mr = wm * 16;

    // load r tiles [64 m][128 k] hi/lo
    {
        int row = t >> 3;            // 0..63
        int cb = (t & 7) * 16;       // 0..112
#pragma unroll
        for (int j = 0; j < 4; j++) {
            float4 vh = *(const float4*)(rhb + (long)row * DFc + cb + j * 4);
            *(float4*)&rsh[row * 132 + cb + j * 4] = vh;
            float4 vl = *(const float4*)(rlb + (long)row * DFc + cb + j * 4);
            *(float4*)&rsl[row * 132 + cb + j * 4] = vl;
        }
    }

    float hacc[4][4];
#pragma unroll
    for (int nt = 0; nt < 4; nt++)
#pragma unroll
        for (int c = 0; c < 4; c++) hacc[nt][c] = 0.0f;

    for (int pt = 0; pt < Nn / 64; pt++) {
        int p0 = pt * 64;
        __syncthreads();
        // load x/v tiles hi/lo
        {
            int row = t >> 3;
            int cb = (t & 7) * 16;
#pragma unroll
            for (int j = 0; j < 4; j++) {
                float4 a0 = *(const float4*)(xhb + (long)(p0 + row) * DFc + cb + j * 4);
                *(float4*)&xsh[row * 132 + cb + j * 4] = a0;
                float4 a1 = *(const float4*)(xlb + (long)(p0 + row) * DFc + cb + j * 4);
                *(float4*)&xsl[row * 132 + cb + j * 4] = a1;
                float4 a2 = *(const float4*)(vhb + (long)(p0 + row) * Ec + cb + j * 4);
                *(float4*)&vsh[row * 136 + cb + j * 4] = a2;
                float4 a3 = *(const float4*)(vlb + (long)(p0 + row) * Ec + cb + j * 4);
                *(float4*)&vsl[row * 136 + cb + j * 4] = a3;
            }
        }
        __syncthreads();

        // ---- S-gemm: warp m16 x p16, 3xTF32, pure LDS+MMA ----
        float sacc[2][4];
#pragma unroll
        for (int nt = 0; nt < 2; nt++)
#pragma unroll
            for (int c = 0; c < 4; c++) sacc[nt][c] = 0.0f;

#pragma unroll
        for (int kc = 0; kc < 16; kc++) {
            int k0 = kc * 8;
            unsigned ah[4], al[4];
            ah[0] = __float_as_uint(rsh[(mr + g) * 132 + k0 + q]);
            ah[1] = __float_as_uint(rsh[(mr + g + 8) * 132 + k0 + q]);
            ah[2] = __float_as_uint(rsh[(mr + g) * 132 + k0 + q + 4]);
            ah[3] = __float_as_uint(rsh[(mr + g + 8) * 132 + k0 + q + 4]);
            al[0] = __float_as_uint(rsl[(mr + g) * 132 + k0 + q]);
            al[1] = __float_as_uint(rsl[(mr + g + 8) * 132 + k0 + q]);
            al[2] = __float_as_uint(rsl[(mr + g) * 132 + k0 + q + 4]);
            al[3] = __float_as_uint(rsl[(mr + g + 8) * 132 + k0 + q + 4]);
#pragma unroll
            for (int nt = 0; nt < 2; nt++) {
                int pr = wq * 16 + nt * 8 + g;
                unsigned bh[2], bl[2];
                bh[0] = __float_as_uint(xsh[pr * 132 + k0 + q]);
                bh[1] = __float_as_uint(xsh[pr * 132 + k0 + q + 4]);
                bl[0] = __float_as_uint(xsl[pr * 132 + k0 + q]);
                bl[1] = __float_as_uint(xsl[pr * 132 + k0 + q + 4]);
                mma_tf32(sacc[nt], ah, bh);
                mma_tf32(sacc[nt], ah, bl);
                mma_tf32(sacc[nt], al, bh);
            }
        }

        // ---- tanh -> tf32 bits -> Ss[m][p] ----
#pragma unroll
        for (int nt = 0; nt < 2; nt++) {
            int mrow = mr + g;
            int pcol = wq * 16 + nt * 8 + 2 * q;
            float t0 = __uint_as_float(f2tf(tanh_fast(sacc[nt][0] * inv_scale)));
            float t1 = __uint_as_float(f2tf(tanh_fast(sacc[nt][1] * inv_scale)));
            float t2 = __uint_as_float(f2tf(tanh_fast(sacc[nt][2] * inv_scale)));
            float t3 = __uint_as_float(f2tf(tanh_fast(sacc[nt][3] * inv_scale)));
            *(float2*)&Ss[mrow * 68 + pcol] = make_float2(t0, t1);
            *(float2*)&Ss[(mrow + 8) * 68 + pcol] = make_float2(t2, t3);
        }
        __syncthreads();

        // ---- GEMM2: warp m16 x f32, attn(tf32) x (v_hi + v_lo) ----
#pragma unroll
        for (int pc = 0; pc < 8; pc++) {
            int pk = pc * 8;
            unsigned af[4];
            af[0] = __float_as_uint(Ss[(mr + g) * 68 + pk + q]);
            af[1] = __float_as_uint(Ss[(mr + g + 8) * 68 + pk + q]);
            af[2] = __float_as_uint(Ss[(mr + g) * 68 + pk + q + 4]);
            af[3] = __float_as_uint(Ss[(mr + g + 8) * 68 + pk + q + 4]);
#pragma unroll
            for (int nt = 0; nt < 4; nt++) {
                int fc = wq * 32 + nt * 8 + g;
                unsigned bh[2], bl[2];
                bh[0] = __float_as_uint(vsh[(pk + q) * 136 + fc]);
                bh[1] = __float_as_uint(vsh[(pk + q + 4) * 136 + fc]);
                bl[0] = __float_as_uint(vsl[(pk + q) * 136 + fc]);
                bl[1] = __float_as_uint(vsl[(pk + q + 4) * 136 + fc]);
                mma_tf32(hacc[nt], af, bh);
                mma_tf32(hacc[nt], af, bl);
            }
        }
    }

    // write h into hcat [b][n][h][f]
#pragma unroll
    for (int nt = 0; nt < 4; nt++) {
        int mrow = m0 + mr + g;
        int fc = wq * 32 + nt * 8 + 2 * q;
        float* hp0 = hcat + (((long)b * Nn + mrow) * Hc + h) * Ec + fc;
        float* hp1 = hcat + (((long)b * Nn + mrow + 8) * Hc + h) * Ec + fc;
        *(float2*)hp0 = make_float2(hacc[nt][0], hacc[nt][1]);
        *(float2*)hp1 = make_float2(hacc[nt][2], hacc[nt][3]);
    }
}

// ---------------- launch ----------------
extern "C" void kernel_launch(void* const* d_in, const int* in_sizes, int n_in,
                              void* d_out, int out_size) {
    const float* x      = (const float*)d_in[0];
    const float* emb1_W = (const float*)d_in[1];
    const float* emb1_b = (const float*)d_in[2];
    const float* wq_W   = (const float*)d_in[3];
    const float* wq_b   = (const float*)d_in[4];
    const float* wv_W   = (const float*)d_in[7];
    const float* wv_b   = (const float*)d_in[8];
    const float* emb2_W = (const float*)d_in[9];
    const float* emb2_b = (const float*)d_in[10];
    float* out = (float*)d_out;

    float *gg, *gemb, *gq, *gv, *gu, *gr, *gh;
    float *grhi, *grlo, *gvhi, *gvlo, *gxhi, *gxlo;
    cudaGetSymbolAddress((void**)&gg, g_g);
    cudaGetSymbolAddress((void**)&gemb, g_emb);
    cudaGetSymbolAddress((void**)&gq, g_q);
    cudaGetSymbolAddress((void**)&gv, g_v);
    cudaGetSymbolAddress((void**)&gu, g_u);
    cudaGetSymbolAddress((void**)&gr, g_r);
    cudaGetSymbolAddress((void**)&gh, g_h);
    cudaGetSymbolAddress((void**)&grhi, g_rhi);
    cudaGetSymbolAddress((void**)&grlo, g_rlo);
    cudaGetSymbolAddress((void**)&gvhi, g_vhi);
    cudaGetSymbolAddress((void**)&gvlo, g_vlo);
    cudaGetSymbolAddress((void**)&gxhi, g_xhi);
    cudaGetSymbolAddress((void**)&gxlo, g_xlo);

    static int smem_set = 0;
    if (!smem_set) {
        cudaFuncSetAttribute(attn_mma2_kernel, cudaFuncAttributeMaxDynamicSharedMemorySize,
                             AT2_FLOATS * sizeof(float));
        smem_set = 1;
    }

    // zero split-K accumulators
    zero_kernel<<<(Bc * Ec * DFc + 255) / 256, 256>>>(gg, Bc * Ec * DFc);
    zero_kernel<<<(Bc * Hc * DFc * Ec + 255) / 256, 256>>>(gu, Bc * Hc * DFc * Ec);

    // x hi/lo split
    split_kernel<<<(Bc * Nn * DFc / 4 + 255) / 256, 256>>>(x, gxhi, gxlo, Bc * Nn * DFc / 4);

    // stage 1: g[b,e,d] = sum_m W1[e,m] x[b,m,d]   (split-K 8, atomic)
    tf32_gemm<<<dim3(1, Bc, 8), 256>>>(emb1_W, 0, Bc, Nn, 1,
                                       x, (long)Nn * DFc, Bc, 1, DFc,
                                       nullptr, 0,
                                       gg, (long)Ec * DFc, nullptr, nullptr, Nn, 8, 0);

    // stage 2: emb = x g^T + b1
    tf32_gemm<<<dim3(16, Bc, 1), 256>>>(x, (long)Nn * DFc, 1, DFc, 1,
                                        gg, (long)Ec * DFc, Bc, DFc, 1,
                                        emb1_b, 0,
                                        gemb, (long)Nn * Ec, nullptr, nullptr, DFc, 1, 0);

    // stage 3: q, v projections (v also emits hi/lo)
    tf32_gemm<<<dim3(16, Bc * Hc, 1), 256>>>(gemb, (long)Nn * Ec, Hc, Ec, 1,
                                             wq_W, (long)Ec * Ec, Hc, Ec, 1,
                                             wq_b, Ec,
                                             gq, (long)Nn * Ec, nullptr, nullptr, Ec, 1, 0);
    tf32_gemm<<<dim3(16, Bc * Hc, 1), 256>>>(gemb, (long)Nn * Ec, Hc, Ec, 1,
                                             wv_W, (long)Ec * Ec, Hc, Ec, 1,
                                             wv_b, Ec,
                                             gv, (long)Nn * Ec, gvhi, gvlo, Ec, 1, 0);

    // stage 4: u = x^T v   (split-K 8, atomic)
    tf32_gemm<<<dim3(1, Bc * Hc, 8), 256>>>(x, (long)Nn * DFc, Hc, 1, DFc,
                                            gv, (long)Nn * Ec, Bc * Hc, 1, Ec,
                                            nullptr, 0,
                                            gu, (long)DFc * Ec, nullptr, nullptr, Nn, 8, 0);

    // stage 5: r = q u^T  (emits hi/lo for attention)
    tf32_gemm<<<dim3(16, Bc * Hc, 1), 256>>>(gq, (long)Nn * Ec, 1, Ec, 1,
                                             gu, (long)DFc * Ec, Bc * Hc, Ec, 1,
                                             nullptr, 0,
                                             gr, (long)Nn * DFc, grhi, grlo, Ec, 1, 0);

    // stage 6: fused attention (pre-split operands)
    attn_mma2_kernel<<<dim3(Nn / 64, Bc * Hc), 512, AT2_FLOATS * sizeof(float)>>>(
        grhi, grlo, gxhi, gxlo, gvhi, gvlo, gh);

    // stage 7: out = relu(hcat @ emb2_W^T + emb2_b)
    tf32_gemm<<<dim3(16, Bc, 1), 256>>>(gh, (long)Nn * Hc * Ec, 1, Hc * Ec, 1,
                                        emb2_W, 0, 1, Hc * Ec, 1,
                                        emb2_b, 0,
                                        out, (long)Nn * Ec, nullptr, nullptr, Hc * Ec, 1, 1);
}

// round 6
// speedup vs baseline: 1.3160x; 1.3160x over previous
#include <cuda_runtime.h>
#include <math.h>

#define Bc 8
#define Nn 2048
#define DFc 128
#define Ec 128
#define Hc 4

// ---------------- scratch (static device arrays; no allocation) ----------------
__device__ float g_g[Bc * Ec * DFc];                     // [b][e][d]
__device__ float g_emb[Bc * Nn * Ec];                    // [b][n][e]
__device__ float g_q[(size_t)Bc * Hc * Nn * Ec];         // [b][h][n][f]
__device__ float g_v[(size_t)Bc * Hc * Nn * Ec];         // [b][h][n][f]
__device__ float g_u[Bc * Hc * DFc * Ec];                // [b][h][d][f]
__device__ float g_r[(size_t)Bc * Hc * Nn * DFc];        // [b][h][n][d]
__device__ float g_h[(size_t)Bc * Nn * Hc * Ec];         // hcat layout [b][n][h][f]

// ---------------- zero init ----------------
__global__ void zero_kernel(float* p, int n) {
    int i = blockIdx.x * blockDim.x + threadIdx.x;
    if (i < n) p[i] = 0.0f;
}

// ---------------- tf32 helpers ----------------
__device__ __forceinline__ unsigned f2tf(float f) {
    unsigned u;
    asm("cvt.rna.tf32.f32 %0, %1;" : "=r"(u) : "f"(f));
    return u;
}

__device__ __forceinline__ void mma_tf32(float c[4], const unsigned a[4], const unsigned b[2]) {
    asm volatile(
        "mma.sync.aligned.m16n8k8.row.col.f32.tf32.tf32.f32 "
        "{%0,%1,%2,%3}, {%4,%5,%6,%7}, {%8,%9}, {%0,%1,%2,%3};"
        : "+f"(c[0]), "+f"(c[1]), "+f"(c[2]), "+f"(c[3])
        : "r"(a[0]), "r"(a[1]), "r"(a[2]), "r"(a[3]), "r"(b[0]), "r"(b[1]));
}

__device__ __forceinline__ float tanh_fast(float x) {
    float y;
    asm("tanh.approx.f32 %0, %1;" : "=f"(y) : "f"(x));
    return y;
}

// ================= unified 3xTF32 tensor GEMM (R3 version) =================
// C[M,N=128] = act( sum_k A[m,k] B[n,k] + bias[n] )
// grid = (M/128, nbatch, ksplit). ksplit>1 -> atomicAdd epilogue (no bias/act).
__global__ __launch_bounds__(256, 1) void tf32_gemm(
    const float* __restrict__ A, long a_sb, int a_div, int a_sm, int a_sk,
    const float* __restrict__ Bm, long b_sb, int b_mod, int b_sn, int b_sk,
    const float* __restrict__ bias, int bias_sb,
    float* __restrict__ C, long c_sb,
    int K, int ksplit, int act)
{
    __shared__ float As[128 * 36];
    __shared__ float Bs[128 * 36];

    int by = blockIdx.y;
    int m0 = blockIdx.x * 128;
    const float* Ab = A + (long)(by / a_div) * a_sb + (long)m0 * a_sm;
    const float* Bb = Bm + (long)(by % b_mod) * b_sb;
    float* Cb = C + (long)by * c_sb + (long)m0 * 128;

    int Kper = K / ksplit;
    int k0base = blockIdx.z * Kper;

    int t = threadIdx.x;
    int warp = t >> 5;
    int lane = t & 31;
    int g = lane >> 2;
    int q = lane & 3;
    int wm = warp >> 1;
    int wn = warp & 1;

    float acc[2][8][4];
#pragma unroll
    for (int mt = 0; mt < 2; mt++)
#pragma unroll
        for (int nt = 0; nt < 8; nt++)
#pragma unroll
            for (int c = 0; c < 4; c++) acc[mt][nt][c] = 0.0f;

    for (int kc0 = 0; kc0 < Kper; kc0 += 32) {
        int k0 = k0base + kc0;
        __syncthreads();
        if (a_sk == 1) {
            int row = t >> 1;
            int c4 = (t & 1) * 16;
            const float* src = Ab + (long)row * a_sm + k0 + c4;
            float4 v0 = *(const float4*)(src);
            float4 v1 = *(const float4*)(src + 4);
            float4 v2 = *(const float4*)(src + 8);
            float4 v3 = *(const float4*)(src + 12);
            float* dst = &As[row * 36 + c4];
            *(float4*)(dst) = v0; *(float4*)(dst + 4) = v1;
            *(float4*)(dst + 8) = v2; *(float4*)(dst + 12) = v3;
        } else {
            int row = t & 127;
            int kb = (t >> 7) * 16;
#pragma unroll
            for (int e = 0; e < 16; e++)
                As[row * 36 + kb + e] = Ab[(long)row * a_sm + (long)(k0 + kb + e) * a_sk];
        }
        if (b_sk == 1) {
            int row = t >> 1;
            int c4 = (t & 1) * 16;
            const float* src = Bb + (long)row * b_sn + k0 + c4;
            float4 v0 = *(const float4*)(src);
            float4 v1 = *(const float4*)(src + 4);
            float4 v2 = *(const float4*)(src + 8);
            float4 v3 = *(const float4*)(src + 12);
            float* dst = &Bs[row * 36 + c4];
            *(float4*)(dst) = v0; *(float4*)(dst + 4) = v1;
            *(float4*)(dst + 8) = v2; *(float4*)(dst + 12) = v3;
        } else {
            int row = t & 127;
            int kb = (t >> 7) * 16;
#pragma unroll
            for (int e = 0; e < 16; e++)
                Bs[row * 36 + kb + e] = Bb[(long)row * b_sn + (long)(k0 + kb + e) * b_sk];
        }
        __syncthreads();

#pragma unroll
        for (int kc = 0; kc < 4; kc++) {
            int k8 = kc * 8;
            unsigned ah[2][4], al[2][4];
#pragma unroll
            for (int mt = 0; mt < 2; mt++) {
                int mr = wm * 32 + mt * 16;
                float e0 = As[(mr + g) * 36 + k8 + q];
                float e1 = As[(mr + g + 8) * 36 + k8 + q];
                float e2 = As[(mr + g) * 36 + k8 + q + 4];
                float e3 = As[(mr + g + 8) * 36 + k8 + q + 4];
                ah[mt][0] = f2tf(e0); al[mt][0] = f2tf(e0 - __uint_as_float(ah[mt][0]));
                ah[mt][1] = f2tf(e1); al[mt][1] = f2tf(e1 - __uint_as_float(ah[mt][1]));
                ah[mt][2] = f2tf(e2); al[mt][2] = f2tf(e2 - __uint_as_float(ah[mt][2]));
                ah[mt][3] = f2tf(e3); al[mt][3] = f2tf(e3 - __uint_as_float(ah[mt][3]));
            }
            unsigned bh[8][2], bl[8][2];
#pragma unroll
            for (int nt = 0; nt < 8; nt++) {
                int nr = wn * 64 + nt * 8 + g;
                float e0 = Bs[nr * 36 + k8 + q];
                float e1 = Bs[nr * 36 + k8 + q + 4];
                bh[nt][0] = f2tf(e0); bl[nt][0] = f2tf(e0 - __uint_as_float(bh[nt][0]));
                bh[nt][1] = f2tf(e1); bl[nt][1] = f2tf(e1 - __uint_as_float(bh[nt][1]));
            }
#pragma unroll
            for (int mt = 0; mt < 2; mt++)
#pragma unroll
                for (int nt = 0; nt < 8; nt++) {
                    mma_tf32(acc[mt][nt], ah[mt], bh[nt]);
                    mma_tf32(acc[mt][nt], ah[mt], bl[nt]);
                    mma_tf32(acc[mt][nt], al[mt], bh[nt]);
                }
        }
    }

    if (ksplit > 1) {
#pragma unroll
        for (int mt = 0; mt < 2; mt++)
#pragma unroll
            for (int nt = 0; nt < 8; nt++) {
                int mr = wm * 32 + mt * 16 + g;
                int nc = wn * 64 + nt * 8 + 2 * q;
                atomicAdd(&Cb[(long)mr * 128 + nc], acc[mt][nt][0]);
                atomicAdd(&Cb[(long)mr * 128 + nc + 1], acc[mt][nt][1]);
                atomicAdd(&Cb[(long)(mr + 8) * 128 + nc], acc[mt][nt][2]);
                atomicAdd(&Cb[(long)(mr + 8) * 128 + nc + 1], acc[mt][nt][3]);
            }
    } else {
        const float* bp = bias ? (bias + (long)(by % b_mod) * bias_sb) : nullptr;
#pragma unroll
        for (int mt = 0; mt < 2; mt++)
#pragma unroll
            for (int nt = 0; nt < 8; nt++) {
                int mr = wm * 32 + mt * 16 + g;
                int nc = wn * 64 + nt * 8 + 2 * q;
                float b0 = bp ? bp[nc] : 0.0f;
                float b1 = bp ? bp[nc + 1] : 0.0f;
                float o00 = acc[mt][nt][0] + b0, o01 = acc[mt][nt][1] + b1;
                float o10 = acc[mt][nt][2] + b0, o11 = acc[mt][nt][3] + b1;
                if (act == 1) {
                    o00 = fmaxf(o00, 0.0f); o01 = fmaxf(o01, 0.0f);
                    o10 = fmaxf(o10, 0.0f); o11 = fmaxf(o11, 0.0f);
                }
                *(float2*)&Cb[(long)mr * 128 + nc] = make_float2(o00, o01);
                *(float2*)&Cb[(long)(mr + 8) * 128 + nc] = make_float2(o10, o11);
            }
    }
}

// ================= tensor-core fused attention v3 =================
// h = tanh( (r x^T)/sqrt(E) ) v   per (b,h)
// Block: 128 m-rows, p-tiles of 64, 256 threads (8 warps).
// r pre-split hi/lo in smem ONCE (reused over 32 p-tiles); x/v split in-loop;
// attn stored as tf32 bits. xs stride 132 (conflict-free), vs stride 136.
// smem floats:
//   rsh [128][132] @ 0          (16896)
//   rsl [128][132] @ 16896      (16896)
//   vs  [64][136]  @ 33792      (8704)
//   xs  [64][132] == Ss [128][68] @ 42496 (8704)
#define A3_RSH 0
#define A3_RSL 16896
#define A3_VS  33792
#define A3_XS  42496
#define A3_FLOATS (42496 + 8704)

__global__ __launch_bounds__(256) void attn_mma3_kernel(
    const float* __restrict__ r, const float* __restrict__ x,
    const float* __restrict__ v, float* __restrict__ hcat)
{
    extern __shared__ float sm[];
    float* rsh = sm + A3_RSH;   // [m][k] stride 132 (tf32 hi bits)
    float* rsl = sm + A3_RSL;   // [m][k] stride 132 (tf32 lo bits)
    float* vs  = sm + A3_VS;    // [p][f] stride 136 (raw fp32)
    float* xs  = sm + A3_XS;    // [p][k] stride 132 (raw fp32)
    float* Ss  = sm + A3_XS;    // [m][p] stride 68  (tf32 bits of attn; aliases xs)

    const float inv_scale = 0.08838834764831845f;  // 1/sqrt(128)

    int by = blockIdx.y;
    int b = by >> 2;
    int h = by & 3;
    int m0 = blockIdx.x * 128;

    const float* rb = r + (long)by * Nn * DFc;
    const float* xb = x + (long)b * Nn * DFc;
    const float* vb = v + (long)by * Nn * Ec;

    int t = threadIdx.x;
    int warp = t >> 5;
    int lane = t & 31;
    int g = lane >> 2;
    int q = lane & 3;

    int wm = warp >> 1;     // 0..3 -> m offset wm*32
    int wp = warp & 1;      // 0..1 -> p offset wp*32 (S-gemm)
    int wf = warp & 1;      // 0..1 -> f offset wf*64 (GEMM2)

    // load + split r tile [128 m][128 k] -> rsh/rsl (one-time)
    {
        int row = t >> 1;
        int cb = (t & 1) * 64;
#pragma unroll
        for (int j = 0; j < 16; j++) {
            float4 rv = *(const float4*)(rb + (long)(m0 + row) * DFc + cb + j * 4);
            float4 hv, lv;
            hv.x = __uint_as_float(f2tf(rv.x)); lv.x = __uint_as_float(f2tf(rv.x - hv.x));
            hv.y = __uint_as_float(f2tf(rv.y)); lv.y = __uint_as_float(f2tf(rv.y - hv.y));
            hv.z = __uint_as_float(f2tf(rv.z)); lv.z = __uint_as_float(f2tf(rv.z - hv.z));
            hv.w = __uint_as_float(f2tf(rv.w)); lv.w = __uint_as_float(f2tf(rv.w - hv.w));
            *(float4*)&rsh[row * 132 + cb + j * 4] = hv;
            *(float4*)&rsl[row * 132 + cb + j * 4] = lv;
        }
    }

    float hacc[2][8][4];
#pragma unroll
    for (int mt = 0; mt < 2; mt++)
#pragma unroll
        for (int nt = 0; nt < 8; nt++)
#pragma unroll
            for (int c = 0; c < 4; c++) hacc[mt][nt][c] = 0.0f;

    for (int pt = 0; pt < Nn / 64; pt++) {
        int p0 = pt * 64;
        __syncthreads();   // prev GEMM2 (Ss/vs reads) done; also covers r-split on iter 0
        // load x tile [64 p][128 k] and v tile [64 p][128 f]
        {
            int row = t >> 2;
            int cb = (t & 3) * 32;
#pragma unroll
            for (int j = 0; j < 8; j++) {
                float4 xv = *(const float4*)(xb + (long)(p0 + row) * DFc + cb + j * 4);
                *(float4*)&xs[row * 132 + cb + j * 4] = xv;
                float4 vv = *(const float4*)(vb + (long)(p0 + row) * Ec + cb + j * 4);
                *(float4*)&vs[row * 136 + cb + j * 4] = vv;
            }
        }
        __syncthreads();

        // ---- S-gemm: 3xTF32, warp region m32 x p32 ----
        float sacc[2][4][4];
#pragma unroll
        for (int mt = 0; mt < 2; mt++)
#pragma unroll
            for (int nt = 0; nt < 4; nt++)
#pragma unroll
                for (int c = 0; c < 4; c++) sacc[mt][nt][c] = 0.0f;

#pragma unroll 4
        for (int kc = 0; kc < 16; kc++) {
            int k0 = kc * 8;
            unsigned a_hi[2][4], a_lo[2][4];
#pragma unroll
            for (int mt = 0; mt < 2; mt++) {
                int mr = wm * 32 + mt * 16;
                a_hi[mt][0] = __float_as_uint(rsh[(mr + g) * 132 + k0 + q]);
                a_hi[mt][1] = __float_as_uint(rsh[(mr + g + 8) * 132 + k0 + q]);
                a_hi[mt][2] = __float_as_uint(rsh[(mr + g) * 132 + k0 + q + 4]);
                a_hi[mt][3] = __float_as_uint(rsh[(mr + g + 8) * 132 + k0 + q + 4]);
                a_lo[mt][0] = __float_as_uint(rsl[(mr + g) * 132 + k0 + q]);
                a_lo[mt][1] = __float_as_uint(rsl[(mr + g + 8) * 132 + k0 + q]);
                a_lo[mt][2] = __float_as_uint(rsl[(mr + g) * 132 + k0 + q + 4]);
                a_lo[mt][3] = __float_as_uint(rsl[(mr + g + 8) * 132 + k0 + q + 4]);
            }
            unsigned b_hi[4][2], b_lo[4][2];
#pragma unroll
            for (int nt = 0; nt < 4; nt++) {
                int pr = wp * 32 + nt * 8 + g;
                float e0 = xs[pr * 132 + k0 + q];
                float e1 = xs[pr * 132 + k0 + q + 4];
                b_hi[nt][0] = f2tf(e0); b_lo[nt][0] = f2tf(e0 - __uint_as_float(b_hi[nt][0]));
                b_hi[nt][1] = f2tf(e1); b_lo[nt][1] = f2tf(e1 - __uint_as_float(b_hi[nt][1]));
            }
#pragma unroll
            for (int mt = 0; mt < 2; mt++)
#pragma unroll
                for (int nt = 0; nt < 4; nt++) {
                    mma_tf32(sacc[mt][nt], a_hi[mt], b_hi[nt]);
                    mma_tf32(sacc[mt][nt], a_hi[mt], b_lo[nt]);
                    mma_tf32(sacc[mt][nt], a_lo[mt], b_hi[nt]);
                }
        }
        __syncthreads();   // xs reads done before tanh overwrites (Ss aliases xs)

        // ---- tanh epilogue -> Ss[m][p] (tf32 bits) ----
#pragma unroll
        for (int mt = 0; mt < 2; mt++)
#pragma unroll
            for (int nt = 0; nt < 4; nt++) {
                int mrow = wm * 32 + mt * 16 + g;
                int pcol = wp * 32 + nt * 8 + 2 * q;
                float t0 = __uint_as_float(f2tf(tanh_fast(sacc[mt][nt][0] * inv_scale)));
                float t1 = __uint_as_float(f2tf(tanh_fast(sacc[mt][nt][1] * inv_scale)));
                float t2 = __uint_as_float(f2tf(tanh_fast(sacc[mt][nt][2] * inv_scale)));
                float t3 = __uint_as_float(f2tf(tanh_fast(sacc[mt][nt][3] * inv_scale)));
                *(float2*)&Ss[mrow * 68 + pcol] = make_float2(t0, t1);
                *(float2*)&Ss[(mrow + 8) * 68 + pcol] = make_float2(t2, t3);
            }
        __syncthreads();

        // ---- GEMM2: hacc += attn(tf32) * (v_hi + v_lo), warp region m32 x f64 ----
#pragma unroll 2
        for (int pc = 0; pc < 8; pc++) {
            int pk = pc * 8;
            unsigned a_f[2][4];
#pragma unroll
            for (int mt = 0; mt < 2; mt++) {
                int mr = wm * 32 + mt * 16;
                a_f[mt][0] = __float_as_uint(Ss[(mr + g) * 68 + pk + q]);
                a_f[mt][1] = __float_as_uint(Ss[(mr + g + 8) * 68 + pk + q]);
                a_f[mt][2] = __float_as_uint(Ss[(mr + g) * 68 + pk + q + 4]);
                a_f[mt][3] = __float_as_uint(Ss[(mr + g + 8) * 68 + pk + q + 4]);
            }
#pragma unroll
            for (int nt = 0; nt < 8; nt++) {
                int fc = wf * 64 + nt * 8 + g;
                float e0 = vs[(pk + q) * 136 + fc];
                float e1 = vs[(pk + q + 4) * 136 + fc];
                unsigned bh[2], bl[2];
                bh[0] = f2tf(e0); bl[0] = f2tf(e0 - __uint_as_float(bh[0]));
                bh[1] = f2tf(e1); bl[1] = f2tf(e1 - __uint_as_float(bh[1]));
#pragma unroll
                for (int mt = 0; mt < 2; mt++) {
                    mma_tf32(hacc[mt][nt], a_f[mt], bh);
                    mma_tf32(hacc[mt][nt], a_f[mt], bl);
                }
            }
        }
    }

    // write h into hcat [b][n][h][f]
#pragma unroll
    for (int mt = 0; mt < 2; mt++)
#pragma unroll
        for (int nt = 0; nt < 8; nt++) {
            int mrow = m0 + wm * 32 + mt * 16 + g;
            int fc = wf * 64 + nt * 8 + 2 * q;
            float* hp0 = hcat + (((long)b * Nn + mrow) * Hc + h) * Ec + fc;
            float* hp1 = hcat + (((long)b * Nn + mrow + 8) * Hc + h) * Ec + fc;
            *(float2*)hp0 = make_float2(hacc[mt][nt][0], hacc[mt][nt][1]);
            *(float2*)hp1 = make_float2(hacc[mt][nt][2], hacc[mt][nt][3]);
        }
}

// ---------------- launch ----------------
extern "C" void kernel_launch(void* const* d_in, const int* in_sizes, int n_in,
                              void* d_out, int out_size) {
    const float* x      = (const float*)d_in[0];
    const float* emb1_W = (const float*)d_in[1];
    const float* emb1_b = (const float*)d_in[2];
    const float* wq_W   = (const float*)d_in[3];
    const float* wq_b   = (const float*)d_in[4];
    const float* wv_W   = (const float*)d_in[7];
    const float* wv_b   = (const float*)d_in[8];
    const float* emb2_W = (const float*)d_in[9];
    const float* emb2_b = (const float*)d_in[10];
    float* out = (float*)d_out;

    float *gg, *gemb, *gq, *gv, *gu, *gr, *gh;
    cudaGetSymbolAddress((void**)&gg, g_g);
    cudaGetSymbolAddress((void**)&gemb, g_emb);
    cudaGetSymbolAddress((void**)&gq, g_q);
    cudaGetSymbolAddress((void**)&gv, g_v);
    cudaGetSymbolAddress((void**)&gu, g_u);
    cudaGetSymbolAddress((void**)&gr, g_r);
    cudaGetSymbolAddress((void**)&gh, g_h);

    static int smem_set = 0;
    if (!smem_set) {
        cudaFuncSetAttribute(attn_mma3_kernel, cudaFuncAttributeMaxDynamicSharedMemorySize,
                             A3_FLOATS * sizeof(float));
        smem_set = 1;
    }

    // zero split-K accumulators
    zero_kernel<<<(Bc * Ec * DFc + 255) / 256, 256>>>(gg, Bc * Ec * DFc);
    zero_kernel<<<(Bc * Hc * DFc * Ec + 255) / 256, 256>>>(gu, Bc * Hc * DFc * Ec);

    // stage 1: g[b,e,d] = sum_m W1[e,m] x[b,m,d]   (split-K 8, atomic)
    tf32_gemm<<<dim3(1, Bc, 8), 256>>>(emb1_W, 0, Bc, Nn, 1,
                                       x, (long)Nn * DFc, Bc, 1, DFc,
                                       nullptr, 0,
                                       gg, (long)Ec * DFc, Nn, 8, 0);

    // stage 2: emb[b,n,e] = sum_d x[b,n,d] g[b,e,d] + emb1_b[e]
    tf32_gemm<<<dim3(16, Bc, 1), 256>>>(x, (long)Nn * DFc, 1, DFc, 1,
                                        gg, (long)Ec * DFc, Bc, DFc, 1,
                                        emb1_b, 0,
                                        gemb, (long)Nn * Ec, DFc, 1, 0);

    // stage 3: q, v projections per (b,h)
    tf32_gemm<<<dim3(16, Bc * Hc, 1), 256>>>(gemb, (long)Nn * Ec, Hc, Ec, 1,
                                             wq_W, (long)Ec * Ec, Hc, Ec, 1,
                                             wq_b, Ec,
                                             gq, (long)Nn * Ec, Ec, 1, 0);
    tf32_gemm<<<dim3(16, Bc * Hc, 1), 256>>>(gemb, (long)Nn * Ec, Hc, Ec, 1,
                                             wv_W, (long)Ec * Ec, Hc, Ec, 1,
                                             wv_b, Ec,
                                             gv, (long)Nn * Ec, Ec, 1, 0);

    // stage 4: u[b,h,d,f] = sum_n x[b,n,d] v[b,h,n,f]   (split-K 8, atomic)
    tf32_gemm<<<dim3(1, Bc * Hc, 8), 256>>>(x, (long)Nn * DFc, Hc, 1, DFc,
                                            gv, (long)Nn * Ec, Bc * Hc, 1, Ec,
                                            nullptr, 0,
                                            gu, (long)DFc * Ec, Nn, 8, 0);

    // stage 5: r[b,h,n,d] = sum_f q[b,h,n,f] u[b,h,d,f]
    tf32_gemm<<<dim3(16, Bc * Hc, 1), 256>>>(gq, (long)Nn * Ec, 1, Ec, 1,
                                             gu, (long)DFc * Ec, Bc * Hc, Ec, 1,
                                             nullptr, 0,
                                             gr, (long)Nn * DFc, Ec, 1, 0);

    // stage 6: fused attention (tensor cores, pre-split r)
    attn_mma3_kernel<<<dim3(Nn / 128, Bc * Hc), 256, A3_FLOATS * sizeof(float)>>>(
        gr, x, gv, gh);

    // stage 7: out = relu(hcat @ emb2_W^T + emb2_b)
    tf32_gemm<<<dim3(16, Bc, 1), 256>>>(gh, (long)Nn * Hc * Ec, 1, Hc * Ec, 1,
                                        emb2_W, 0, 1, Hc * Ec, 1,
                                        emb2_b, 0,
                                        out, (long)Nn * Ec, Hc * Ec, 1, 1);
}

// round 7
// speedup vs baseline: 1.4085x; 1.0703x over previous
#include <cuda_runtime.h>
#include <math.h>

#define Bc 8
#define Nn 2048
#define DFc 128
#define Ec 128
#define Hc 4

// ---------------- scratch (static device arrays; no allocation) ----------------
__device__ float g_g[Bc * Ec * DFc];                     // [b][e][d]
__device__ float g_emb[Bc * Nn * Ec];                    // [b][n][e]
__device__ float g_q[(size_t)Bc * Hc * Nn * Ec];         // [b][h][n][f]
__device__ float g_v[(size_t)Bc * Hc * Nn * Ec];         // [b][h][n][f]
__device__ float g_u[Bc * Hc * DFc * Ec];                // [b][h][d][f]
__device__ float g_r[(size_t)Bc * Hc * Nn * DFc];        // [b][h][n][d]
__device__ float g_h[(size_t)Bc * Nn * Hc * Ec];         // hcat layout [b][n][h][f]

// ---------------- zero init ----------------
__global__ void zero_kernel(float* p, int n) {
    int i = blockIdx.x * blockDim.x + threadIdx.x;
    if (i < n) p[i] = 0.0f;
}

// ---------------- tf32 helpers ----------------
__device__ __forceinline__ unsigned f2tf(float f) {
    unsigned u;
    asm("cvt.rna.tf32.f32 %0, %1;" : "=r"(u) : "f"(f));
    return u;
}

__device__ __forceinline__ void mma_tf32(float c[4], const unsigned a[4], const unsigned b[2]) {
    asm volatile(
        "mma.sync.aligned.m16n8k8.row.col.f32.tf32.tf32.f32 "
        "{%0,%1,%2,%3}, {%4,%5,%6,%7}, {%8,%9}, {%0,%1,%2,%3};"
        : "+f"(c[0]), "+f"(c[1]), "+f"(c[2]), "+f"(c[3])
        : "r"(a[0]), "r"(a[1]), "r"(a[2]), "r"(a[3]), "r"(b[0]), "r"(b[1]));
}

__device__ __forceinline__ float tanh_fast(float x) {
    float y;
    asm("tanh.approx.f32 %0, %1;" : "=f"(y) : "f"(x));
    return y;
}

// ================= unified 3xTF32 tensor GEMM (R3 version, unchanged) =================
__global__ __launch_bounds__(256, 1) void tf32_gemm(
    const float* __restrict__ A, long a_sb, int a_div, int a_sm, int a_sk,
    const float* __restrict__ Bm, long b_sb, int b_mod, int b_sn, int b_sk,
    const float* __restrict__ bias, int bias_sb,
    float* __restrict__ C, long c_sb,
    int K, int ksplit, int act)
{
    __shared__ float As[128 * 36];
    __shared__ float Bs[128 * 36];

    int by = blockIdx.y;
    int m0 = blockIdx.x * 128;
    const float* Ab = A + (long)(by / a_div) * a_sb + (long)m0 * a_sm;
    const float* Bb = Bm + (long)(by % b_mod) * b_sb;
    float* Cb = C + (long)by * c_sb + (long)m0 * 128;

    int Kper = K / ksplit;
    int k0base = blockIdx.z * Kper;

    int t = threadIdx.x;
    int warp = t >> 5;
    int lane = t & 31;
    int g = lane >> 2;
    int q = lane & 3;
    int wm = warp >> 1;
    int wn = warp & 1;

    float acc[2][8][4];
#pragma unroll
    for (int mt = 0; mt < 2; mt++)
#pragma unroll
        for (int nt = 0; nt < 8; nt++)
#pragma unroll
            for (int c = 0; c < 4; c++) acc[mt][nt][c] = 0.0f;

    for (int kc0 = 0; kc0 < Kper; kc0 += 32) {
        int k0 = k0base + kc0;
        __syncthreads();
        if (a_sk == 1) {
            int row = t >> 1;
            int c4 = (t & 1) * 16;
            const float* src = Ab + (long)row * a_sm + k0 + c4;
            float4 v0 = *(const float4*)(src);
            float4 v1 = *(const float4*)(src + 4);
            float4 v2 = *(const float4*)(src + 8);
            float4 v3 = *(const float4*)(src + 12);
            float* dst = &As[row * 36 + c4];
            *(float4*)(dst) = v0; *(float4*)(dst + 4) = v1;
            *(float4*)(dst + 8) = v2; *(float4*)(dst + 12) = v3;
        } else {
            int row = t & 127;
            int kb = (t >> 7) * 16;
#pragma unroll
            for (int e = 0; e < 16; e++)
                As[row * 36 + kb + e] = Ab[(long)row * a_sm + (long)(k0 + kb + e) * a_sk];
        }
        if (b_sk == 1) {
            int row = t >> 1;
            int c4 = (t & 1) * 16;
            const float* src = Bb + (long)row * b_sn + k0 + c4;
            float4 v0 = *(const float4*)(src);
            float4 v1 = *(const float4*)(src + 4);
            float4 v2 = *(const float4*)(src + 8);
            float4 v3 = *(const float4*)(src + 12);
            float* dst = &Bs[row * 36 + c4];
            *(float4*)(dst) = v0; *(float4*)(dst + 4) = v1;
            *(float4*)(dst + 8) = v2; *(float4*)(dst + 12) = v3;
        } else {
            int row = t & 127;
            int kb = (t >> 7) * 16;
#pragma unroll
            for (int e = 0; e < 16; e++)
                Bs[row * 36 + kb + e] = Bb[(long)row * b_sn + (long)(k0 + kb + e) * b_sk];
        }
        __syncthreads();

#pragma unroll
        for (int kc = 0; kc < 4; kc++) {
            int k8 = kc * 8;
            unsigned ah[2][4], al[2][4];
#pragma unroll
            for (int mt = 0; mt < 2; mt++) {
                int mr = wm * 32 + mt * 16;
                float e0 = As[(mr + g) * 36 + k8 + q];
                float e1 = As[(mr + g + 8) * 36 + k8 + q];
                float e2 = As[(mr + g) * 36 + k8 + q + 4];
                float e3 = As[(mr + g + 8) * 36 + k8 + q + 4];
                ah[mt][0] = f2tf(e0); al[mt][0] = f2tf(e0 - __uint_as_float(ah[mt][0]));
                ah[mt][1] = f2tf(e1); al[mt][1] = f2tf(e1 - __uint_as_float(ah[mt][1]));
                ah[mt][2] = f2tf(e2); al[mt][2] = f2tf(e2 - __uint_as_float(ah[mt][2]));
                ah[mt][3] = f2tf(e3); al[mt][3] = f2tf(e3 - __uint_as_float(ah[mt][3]));
            }
            unsigned bh[8][2], bl[8][2];
#pragma unroll
            for (int nt = 0; nt < 8; nt++) {
                int nr = wn * 64 + nt * 8 + g;
                float e0 = Bs[nr * 36 + k8 + q];
                float e1 = Bs[nr * 36 + k8 + q + 4];
                bh[nt][0] = f2tf(e0); bl[nt][0] = f2tf(e0 - __uint_as_float(bh[nt][0]));
                bh[nt][1] = f2tf(e1); bl[nt][1] = f2tf(e1 - __uint_as_float(bh[nt][1]));
            }
#pragma unroll
            for (int mt = 0; mt < 2; mt++)
#pragma unroll
                for (int nt = 0; nt < 8; nt++) {
                    mma_tf32(acc[mt][nt], ah[mt], bh[nt]);
                    mma_tf32(acc[mt][nt], ah[mt], bl[nt]);
                    mma_tf32(acc[mt][nt], al[mt], bh[nt]);
                }
        }
    }

    if (ksplit > 1) {
#pragma unroll
        for (int mt = 0; mt < 2; mt++)
#pragma unroll
            for (int nt = 0; nt < 8; nt++) {
                int mr = wm * 32 + mt * 16 + g;
                int nc = wn * 64 + nt * 8 + 2 * q;
                atomicAdd(&Cb[(long)mr * 128 + nc], acc[mt][nt][0]);
                atomicAdd(&Cb[(long)mr * 128 + nc + 1], acc[mt][nt][1]);
                atomicAdd(&Cb[(long)(mr + 8) * 128 + nc], acc[mt][nt][2]);
                atomicAdd(&Cb[(long)(mr + 8) * 128 + nc + 1], acc[mt][nt][3]);
            }
    } else {
        const float* bp = bias ? (bias + (long)(by % b_mod) * bias_sb) : nullptr;
#pragma unroll
        for (int mt = 0; mt < 2; mt++)
#pragma unroll
            for (int nt = 0; nt < 8; nt++) {
                int mr = wm * 32 + mt * 16 + g;
                int nc = wn * 64 + nt * 8 + 2 * q;
                float b0 = bp ? bp[nc] : 0.0f;
                float b1 = bp ? bp[nc + 1] : 0.0f;
                float o00 = acc[mt][nt][0] + b0, o01 = acc[mt][nt][1] + b1;
                float o10 = acc[mt][nt][2] + b0, o11 = acc[mt][nt][3] + b1;
                if (act == 1) {
                    o00 = fmaxf(o00, 0.0f); o01 = fmaxf(o01, 0.0f);
                    o10 = fmaxf(o10, 0.0f); o11 = fmaxf(o11, 0.0f);
                }
                *(float2*)&Cb[(long)mr * 128 + nc] = make_float2(o00, o01);
                *(float2*)&Cb[(long)(mr + 8) * 128 + nc] = make_float2(o10, o11);
            }
    }
}

// ================= tensor-core fused attention v4: 512 threads =================
// h = tanh( (r x^T)/sqrt(E) ) v   per (b,h)
// Block: 128 m-rows, p-tiles of 64, 512 threads (16 warps, 4/SMSP).
// S-gemm warp tile m32 x p16; GEMM2 warp tile m32 x f32. Same totals as R3,
// double the latency hiding. Ss has its own region (3 syncs per p-tile).
// smem floats:
//   rs [128][132] @ 0       (16896)
//   vs [64][136]  @ 16896   (8704)
//   xs [64][132]  @ 25600   (8448)
//   Ss [128][68]  @ 34048   (8704)
#define A4_RS 0
#define A4_VS 16896
#define A4_XS 25600
#define A4_SS 34048
#define A4_FLOATS (34048 + 8704)

__global__ __launch_bounds__(512, 1) void attn_mma4_kernel(
    const float* __restrict__ r, const float* __restrict__ x,
    const float* __restrict__ v, float* __restrict__ hcat)
{
    extern __shared__ float sm[];
    float* rs = sm + A4_RS;   // [m][k] stride 132 (raw fp32)
    float* vs = sm + A4_VS;   // [p][f] stride 136 (raw fp32)
    float* xs = sm + A4_XS;   // [p][k] stride 132 (raw fp32)
    float* Ss = sm + A4_SS;   // [m][p] stride 68  (tf32 bits of attn)

    const float inv_scale = 0.08838834764831845f;  // 1/sqrt(128)

    int by = blockIdx.y;
    int b = by >> 2;
    int h = by & 3;
    int m0 = blockIdx.x * 128;

    const float* rb = r + (long)by * Nn * DFc;
    const float* xb = x + (long)b * Nn * DFc;
    const float* vb = v + (long)by * Nn * Ec;

    int t = threadIdx.x;
    int warp = t >> 5;
    int lane = t & 31;
    int g = lane >> 2;
    int q = lane & 3;

    int wm = warp >> 2;     // 0..3 -> m offset wm*32
    int wq = warp & 3;      // 0..3 -> p offset wq*16 (S) / f offset wq*32 (GEMM2)
    int mrb = wm * 32;

    // load r tile [128 m][128 k]
    {
        int row = t >> 2;
        int cb = (t & 3) * 32;
#pragma unroll
        for (int j = 0; j < 8; j++) {
            float4 rv = *(const float4*)(rb + (long)(m0 + row) * DFc + cb + j * 4);
            *(float4*)&rs[row * 132 + cb + j * 4] = rv;
        }
    }

    float hacc[2][4][4];
#pragma unroll
    for (int mt = 0; mt < 2; mt++)
#pragma unroll
        for (int nt = 0; nt < 4; nt++)
#pragma unroll
            for (int c = 0; c < 4; c++) hacc[mt][nt][c] = 0.0f;

    for (int pt = 0; pt < Nn / 64; pt++) {
        int p0 = pt * 64;
        __syncthreads();   // prev GEMM2 done (vs/Ss free); also covers r load on iter 0
        // load x tile [64 p][128 k] and v tile [64 p][128 f]
        {
            int row = t >> 3;
            int cb = (t & 7) * 16;
#pragma unroll
            for (int j = 0; j < 4; j++) {
                float4 xv = *(const float4*)(xb + (long)(p0 + row) * DFc + cb + j * 4);
                *(float4*)&xs[row * 132 + cb + j * 4] = xv;
                float4 vv = *(const float4*)(vb + (long)(p0 + row) * Ec + cb + j * 4);
                *(float4*)&vs[row * 136 + cb + j * 4] = vv;
            }
        }
        __syncthreads();

        // ---- S-gemm: 3xTF32, warp region m32 x p16 ----
        float sacc[2][2][4];
#pragma unroll
        for (int mt = 0; mt < 2; mt++)
#pragma unroll
            for (int nt = 0; nt < 2; nt++)
#pragma unroll
                for (int c = 0; c < 4; c++) sacc[mt][nt][c] = 0.0f;

#pragma unroll 4
        for (int kc = 0; kc < 16; kc++) {
            int k0 = kc * 8;
            unsigned a_hi[2][4], a_lo[2][4];
#pragma unroll
            for (int mt = 0; mt < 2; mt++) {
                int mr = mrb + mt * 16;
                float e0 = rs[(mr + g) * 132 + k0 + q];
                float e1 = rs[(mr + g + 8) * 132 + k0 + q];
                float e2 = rs[(mr + g) * 132 + k0 + q + 4];
                float e3 = rs[(mr + g + 8) * 132 + k0 + q + 4];
                a_hi[mt][0] = f2tf(e0); a_lo[mt][0] = f2tf(e0 - __uint_as_float(a_hi[mt][0]));
                a_hi[mt][1] = f2tf(e1); a_lo[mt][1] = f2tf(e1 - __uint_as_float(a_hi[mt][1]));
                a_hi[mt][2] = f2tf(e2); a_lo[mt][2] = f2tf(e2 - __uint_as_float(a_hi[mt][2]));
                a_hi[mt][3] = f2tf(e3); a_lo[mt][3] = f2tf(e3 - __uint_as_float(a_hi[mt][3]));
            }
            unsigned b_hi[2][2], b_lo[2][2];
#pragma unroll
            for (int nt = 0; nt < 2; nt++) {
                int pr = wq * 16 + nt * 8 + g;
                float e0 = xs[pr * 132 + k0 + q];
                float e1 = xs[pr * 132 + k0 + q + 4];
                b_hi[nt][0] = f2tf(e0); b_lo[nt][0] = f2tf(e0 - __uint_as_float(b_hi[nt][0]));
                b_hi[nt][1] = f2tf(e1); b_lo[nt][1] = f2tf(e1 - __uint_as_float(b_hi[nt][1]));
            }
#pragma unroll
            for (int mt = 0; mt < 2; mt++)
#pragma unroll
                for (int nt = 0; nt < 2; nt++) {
                    mma_tf32(sacc[mt][nt], a_hi[mt], b_hi[nt]);
                    mma_tf32(sacc[mt][nt], a_hi[mt], b_lo[nt]);
                    mma_tf32(sacc[mt][nt], a_lo[mt], b_hi[nt]);
                }
        }

        // ---- tanh epilogue -> Ss[m][p] (tf32 bits); no sync needed before (own region) ----
#pragma unroll
        for (int mt = 0; mt < 2; mt++)
#pragma unroll
            for (int nt = 0; nt < 2; nt++) {
                int mrow = mrb + mt * 16 + g;
                int pcol = wq * 16 + nt * 8 + 2 * q;
                float t0 = __uint_as_float(f2tf(tanh_fast(sacc[mt][nt][0] * inv_scale)));
                float t1 = __uint_as_float(f2tf(tanh_fast(sacc[mt][nt][1] * inv_scale)));
                float t2 = __uint_as_float(f2tf(tanh_fast(sacc[mt][nt][2] * inv_scale)));
                float t3 = __uint_as_float(f2tf(tanh_fast(sacc[mt][nt][3] * inv_scale)));
                *(float2*)&Ss[mrow * 68 + pcol] = make_float2(t0, t1);
                *(float2*)&Ss[(mrow + 8) * 68 + pcol] = make_float2(t2, t3);
            }
        __syncthreads();   // Ss complete

        // ---- GEMM2: hacc += attn(tf32) * (v_hi + v_lo), warp region m32 x f32 ----
#pragma unroll 2
        for (int pc = 0; pc < 8; pc++) {
            int pk = pc * 8;
            unsigned a_f[2][4];
#pragma unroll
            for (int mt = 0; mt < 2; mt++) {
                int mr = mrb + mt * 16;
                a_f[mt][0] = __float_as_uint(Ss[(mr + g) * 68 + pk + q]);
                a_f[mt][1] = __float_as_uint(Ss[(mr + g + 8) * 68 + pk + q]);
                a_f[mt][2] = __float_as_uint(Ss[(mr + g) * 68 + pk + q + 4]);
                a_f[mt][3] = __float_as_uint(Ss[(mr + g + 8) * 68 + pk + q + 4]);
            }
#pragma unroll
            for (int nt = 0; nt < 4; nt++) {
                int fc = wq * 32 + nt * 8 + g;
                float e0 = vs[(pk + q) * 136 + fc];
                float e1 = vs[(pk + q + 4) * 136 + fc];
                unsigned bh[2], bl[2];
                bh[0] = f2tf(e0); bl[0] = f2tf(e0 - __uint_as_float(bh[0]));
                bh[1] = f2tf(e1); bl[1] = f2tf(e1 - __uint_as_float(bh[1]));
#pragma unroll
                for (int mt = 0; mt < 2; mt++) {
                    mma_tf32(hacc[mt][nt], a_f[mt], bh);
                    mma_tf32(hacc[mt][nt], a_f[mt], bl);
                }
            }
        }
    }

    // write h into hcat [b][n][h][f]
#pragma unroll
    for (int mt = 0; mt < 2; mt++)
#pragma unroll
        for (int nt = 0; nt < 4; nt++) {
            int mrow = m0 + mrb + mt * 16 + g;
            int fc = wq * 32 + nt * 8 + 2 * q;
            float* hp0 = hcat + (((long)b * Nn + mrow) * Hc + h) * Ec + fc;
            float* hp1 = hcat + (((long)b * Nn + mrow + 8) * Hc + h) * Ec + fc;
            *(float2*)hp0 = make_float2(hacc[mt][nt][0], hacc[mt][nt][1]);
            *(float2*)hp1 = make_float2(hacc[mt][nt][2], hacc[mt][nt][3]);
        }
}

// ---------------- launch ----------------
extern "C" void kernel_launch(void* const* d_in, const int* in_sizes, int n_in,
                              void* d_out, int out_size) {
    const float* x      = (const float*)d_in[0];
    const float* emb1_W = (const float*)d_in[1];
    const float* emb1_b = (const float*)d_in[2];
    const float* wq_W   = (const float*)d_in[3];
    const float* wq_b   = (const float*)d_in[4];
    const float* wv_W   = (const float*)d_in[7];
    const float* wv_b   = (const float*)d_in[8];
    const float* emb2_W = (const float*)d_in[9];
    const float* emb2_b = (const float*)d_in[10];
    float* out = (float*)d_out;

    float *gg, *gemb, *gq, *gv, *gu, *gr, *gh;
    cudaGetSymbolAddress((void**)&gg, g_g);
    cudaGetSymbolAddress((void**)&gemb, g_emb);
    cudaGetSymbolAddress((void**)&gq, g_q);
    cudaGetSymbolAddress((void**)&gv, g_v);
    cudaGetSymbolAddress((void**)&gu, g_u);
    cudaGetSymbolAddress((void**)&gr, g_r);
    cudaGetSymbolAddress((void**)&gh, g_h);

    static int smem_set = 0;
    if (!smem_set) {
        cudaFuncSetAttribute(attn_mma4_kernel, cudaFuncAttributeMaxDynamicSharedMemorySize,
                             A4_FLOATS * sizeof(float));
        smem_set = 1;
    }

    // zero split-K accumulators
    zero_kernel<<<(Bc * Ec * DFc + 255) / 256, 256>>>(gg, Bc * Ec * DFc);
    zero_kernel<<<(Bc * Hc * DFc * Ec + 255) / 256, 256>>>(gu, Bc * Hc * DFc * Ec);

    // stage 1: g[b,e,d] = sum_m W1[e,m] x[b,m,d]   (split-K 8, atomic)
    tf32_gemm<<<dim3(1, Bc, 8), 256>>>(emb1_W, 0, Bc, Nn, 1,
                                       x, (long)Nn * DFc, Bc, 1, DFc,
                                       nullptr, 0,
                                       gg, (long)Ec * DFc, Nn, 8, 0);

    // stage 2: emb[b,n,e] = sum_d x[b,n,d] g[b,e,d] + emb1_b[e]
    tf32_gemm<<<dim3(16, Bc, 1), 256>>>(x, (long)Nn * DFc, 1, DFc, 1,
                                        gg, (long)Ec * DFc, Bc, DFc, 1,
                                        emb1_b, 0,
                                        gemb, (long)Nn * Ec, DFc, 1, 0);

    // stage 3: q, v projections per (b,h)
    tf32_gemm<<<dim3(16, Bc * Hc, 1), 256>>>(gemb, (long)Nn * Ec, Hc, Ec, 1,
                                             wq_W, (long)Ec * Ec, Hc, Ec, 1,
                                             wq_b, Ec,
                                             gq, (long)Nn * Ec, Ec, 1, 0);
    tf32_gemm<<<dim3(16, Bc * Hc, 1), 256>>>(gemb, (long)Nn * Ec, Hc, Ec, 1,
                                             wv_W, (long)Ec * Ec, Hc, Ec, 1,
                                             wv_b, Ec,
                                             gv, (long)Nn * Ec, Ec, 1, 0);

    // stage 4: u[b,h,d,f] = sum_n x[b,n,d] v[b,h,n,f]   (split-K 8, atomic)
    tf32_gemm<<<dim3(1, Bc * Hc, 8), 256>>>(x, (long)Nn * DFc, Hc, 1, DFc,
                                            gv, (long)Nn * Ec, Bc * Hc, 1, Ec,
                                            nullptr, 0,
                                            gu, (long)DFc * Ec, Nn, 8, 0);

    // stage 5: r[b,h,n,d] = sum_f q[b,h,n,f] u[b,h,d,f]
    tf32_gemm<<<dim3(16, Bc * Hc, 1), 256>>>(gq, (long)Nn * Ec, 1, Ec, 1,
                                             gu, (long)DFc * Ec, Bc * Hc, Ec, 1,
                                             nullptr, 0,
                                             gr, (long)Nn * DFc, Ec, 1, 0);

    // stage 6: fused attention (tensor cores, 512 threads)
    attn_mma4_kernel<<<dim3(Nn / 128, Bc * Hc), 512, A4_FLOATS * sizeof(float)>>>(
        gr, x, gv, gh);

    // stage 7: out = relu(hcat @ emb2_W^T + emb2_b)
    tf32_gemm<<<dim3(16, Bc, 1), 256>>>(gh, (long)Nn * Hc * Ec, 1, Hc * Ec, 1,
                                        emb2_W, 0, 1, Hc * Ec, 1,
                                        emb2_b, 0,
                                        out, (long)Nn * Ec, Hc * Ec, 1, 1);
}

// round 10
// speedup vs baseline: 1.6737x; 1.1883x over previous
#include <cuda_runtime.h>
#include <cuda_fp16.h>
#include <math.h>

#define Bc 8
#define Nn 2048
#define DFc 128
#define Ec 128
#define Hc 4

// ---------------- scratch (static device arrays; no allocation) ----------------
__device__ float g_g[Bc * Ec * DFc];                     // [b][e][d]
__device__ float g_emb[Bc * Nn * Ec];                    // [b][n][e]
__device__ float g_q[(size_t)Bc * Hc * Nn * Ec];         // [b][h][n][f]
__device__ float g_v[(size_t)Bc * Hc * Nn * Ec];         // [b][h][n][f]
__device__ float g_u[Bc * Hc * DFc * Ec];                // [b][h][d][f]
__device__ float g_r[(size_t)Bc * Hc * Nn * DFc];        // [b][h][n][d]
__device__ float g_h[(size_t)Bc * Nn * Hc * Ec];         // hcat layout [b][n][h][f]

// ---------------- zero init ----------------
__global__ void zero_kernel(float* p, int n) {
    int i = blockIdx.x * blockDim.x + threadIdx.x;
    if (i < n) p[i] = 0.0f;
}

// ---------------- tf32 helpers ----------------
__device__ __forceinline__ unsigned f2tf(float f) {
    unsigned u;
    asm("cvt.rna.tf32.f32 %0, %1;" : "=r"(u) : "f"(f));
    return u;
}

__device__ __forceinline__ void mma_tf32(float c[4], const unsigned a[4], const unsigned b[2]) {
    asm volatile(
        "mma.sync.aligned.m16n8k8.row.col.f32.tf32.tf32.f32 "
        "{%0,%1,%2,%3}, {%4,%5,%6,%7}, {%8,%9}, {%0,%1,%2,%3};"
        : "+f"(c[0]), "+f"(c[1]), "+f"(c[2]), "+f"(c[3])
        : "r"(a[0]), "r"(a[1]), "r"(a[2]), "r"(a[3]), "r"(b[0]), "r"(b[1]));
}

__device__ __forceinline__ float tanh_fast(float x) {
    float y;
    asm("tanh.approx.f32 %0, %1;" : "=f"(y) : "f"(x));
    return y;
}

// ---------------- fp16 helpers ----------------
__device__ __forceinline__ void mma_f16(float c[4], const unsigned a[4], const unsigned b[2]) {
    asm volatile(
        "mma.sync.aligned.m16n8k16.row.col.f32.f16.f16.f32 "
        "{%0,%1,%2,%3}, {%4,%5,%6,%7}, {%8,%9}, {%0,%1,%2,%3};"
        : "+f"(c[0]), "+f"(c[1]), "+f"(c[2]), "+f"(c[3])
        : "r"(a[0]), "r"(a[1]), "r"(a[2]), "r"(a[3]), "r"(b[0]), "r"(b[1]));
}

__device__ __forceinline__ unsigned pack2(float e0, float e1) {
    __half2 h = __floats2half2_rn(e0, e1);
    return *reinterpret_cast<unsigned*>(&h);
}

__device__ __forceinline__ void split2(float e0, float e1, unsigned& hw, unsigned& lw) {
    __half2 h = __floats2half2_rn(e0, e1);
    float2 hf = __half22float2(h);
    __half2 l = __floats2half2_rn(e0 - hf.x, e1 - hf.y);
    hw = *reinterpret_cast<unsigned*>(&h);
    lw = *reinterpret_cast<unsigned*>(&l);
}

// ================= unified 3xTF32 tensor GEMM (unchanged) =================
__global__ __launch_bounds__(256, 1) void tf32_gemm(
    const float* __restrict__ A, long a_sb, int a_div, int a_sm, int a_sk,
    const float* __restrict__ Bm, long b_sb, int b_mod, int b_sn, int b_sk,
    const float* __restrict__ bias, int bias_sb,
    float* __restrict__ C, long c_sb,
    int K, int ksplit, int act)
{
    __shared__ float As[128 * 36];
    __shared__ float Bs[128 * 36];

    int by = blockIdx.y;
    int m0 = blockIdx.x * 128;
    const float* Ab = A + (long)(by / a_div) * a_sb + (long)m0 * a_sm;
    const float* Bb = Bm + (long)(by % b_mod) * b_sb;
    float* Cb = C + (long)by * c_sb + (long)m0 * 128;

    int Kper = K / ksplit;
    int k0base = blockIdx.z * Kper;

    int t = threadIdx.x;
    int warp = t >> 5;
    int lane = t & 31;
    int g = lane >> 2;
    int q = lane & 3;
    int wm = warp >> 1;
    int wn = warp & 1;

    float acc[2][8][4];
#pragma unroll
    for (int mt = 0; mt < 2; mt++)
#pragma unroll
        for (int nt = 0; nt < 8; nt++)
#pragma unroll
            for (int c = 0; c < 4; c++) acc[mt][nt][c] = 0.0f;

    for (int kc0 = 0; kc0 < Kper; kc0 += 32) {
        int k0 = k0base + kc0;
        __syncthreads();
        if (a_sk == 1) {
            int row = t >> 1;
            int c4 = (t & 1) * 16;
            const float* src = Ab + (long)row * a_sm + k0 + c4;
            float4 v0 = *(const float4*)(src);
            float4 v1 = *(const float4*)(src + 4);
            float4 v2 = *(const float4*)(src + 8);
            float4 v3 = *(const float4*)(src + 12);
            float* dst = &As[row * 36 + c4];
            *(float4*)(dst) = v0; *(float4*)(dst + 4) = v1;
            *(float4*)(dst + 8) = v2; *(float4*)(dst + 12) = v3;
        } else {
            int row = t & 127;
            int kb = (t >> 7) * 16;
#pragma unroll
            for (int e = 0; e < 16; e++)
                As[row * 36 + kb + e] = Ab[(long)row * a_sm + (long)(k0 + kb + e) * a_sk];
        }
        if (b_sk == 1) {
            int row = t >> 1;
            int c4 = (t & 1) * 16;
            const float* src = Bb + (long)row * b_sn + k0 + c4;
            float4 v0 = *(const float4*)(src);
            float4 v1 = *(const float4*)(src + 4);
            float4 v2 = *(const float4*)(src + 8);
            float4 v3 = *(const float4*)(src + 12);
            float* dst = &Bs[row * 36 + c4];
            *(float4*)(dst) = v0; *(float4*)(dst + 4) = v1;
            *(float4*)(dst + 8) = v2; *(float4*)(dst + 12) = v3;
        } else {
            int row = t & 127;
            int kb = (t >> 7) * 16;
#pragma unroll
            for (int e = 0; e < 16; e++)
                Bs[row * 36 + kb + e] = Bb[(long)row * b_sn + (long)(k0 + kb + e) * b_sk];
        }
        __syncthreads();

#pragma unroll
        for (int kc = 0; kc < 4; kc++) {
            int k8 = kc * 8;
            unsigned ah[2][4], al[2][4];
#pragma unroll
            for (int mt = 0; mt < 2; mt++) {
                int mr = wm * 32 + mt * 16;
                float e0 = As[(mr + g) * 36 + k8 + q];
                float e1 = As[(mr + g + 8) * 36 + k8 + q];
                float e2 = As[(mr + g) * 36 + k8 + q + 4];
                float e3 = As[(mr + g + 8) * 36 + k8 + q + 4];
                ah[mt][0] = f2tf(e0); al[mt][0] = f2tf(e0 - __uint_as_float(ah[mt][0]));
                ah[mt][1] = f2tf(e1); al[mt][1] = f2tf(e1 - __uint_as_float(ah[mt][1]));
                ah[mt][2] = f2tf(e2); al[mt][2] = f2tf(e2 - __uint_as_float(ah[mt][2]));
                ah[mt][3] = f2tf(e3); al[mt][3] = f2tf(e3 - __uint_as_float(ah[mt][3]));
            }
            unsigned bh[8][2], bl[8][2];
#pragma unroll
            for (int nt = 0; nt < 8; nt++) {
                int nr = wn * 64 + nt * 8 + g;
                float e0 = Bs[nr * 36 + k8 + q];
                float e1 = Bs[nr * 36 + k8 + q + 4];
                bh[nt][0] = f2tf(e0); bl[nt][0] = f2tf(e0 - __uint_as_float(bh[nt][0]));
                bh[nt][1] = f2tf(e1); bl[nt][1] = f2tf(e1 - __uint_as_float(bh[nt][1]));
            }
#pragma unroll
            for (int mt = 0; mt < 2; mt++)
#pragma unroll
                for (int nt = 0; nt < 8; nt++) {
                    mma_tf32(acc[mt][nt], ah[mt], bh[nt]);
                    mma_tf32(acc[mt][nt], ah[mt], bl[nt]);
                    mma_tf32(acc[mt][nt], al[mt], bh[nt]);
                }
        }
    }

    if (ksplit > 1) {
#pragma unroll
        for (int mt = 0; mt < 2; mt++)
#pragma unroll
            for (int nt = 0; nt < 8; nt++) {
                int mr = wm * 32 + mt * 16 + g;
                int nc = wn * 64 + nt * 8 + 2 * q;
                atomicAdd(&Cb[(long)mr * 128 + nc], acc[mt][nt][0]);
                atomicAdd(&Cb[(long)mr * 128 + nc + 1], acc[mt][nt][1]);
                atomicAdd(&Cb[(long)(mr + 8) * 128 + nc], acc[mt][nt][2]);
                atomicAdd(&Cb[(long)(mr + 8) * 128 + nc + 1], acc[mt][nt][3]);
            }
    } else {
        const float* bp = bias ? (bias + (long)(by % b_mod) * bias_sb) : nullptr;
#pragma unroll
        for (int mt = 0; mt < 2; mt++)
#pragma unroll
            for (int nt = 0; nt < 8; nt++) {
                int mr = wm * 32 + mt * 16 + g;
                int nc = wn * 64 + nt * 8 + 2 * q;
                float b0 = bp ? bp[nc] : 0.0f;
                float b1 = bp ? bp[nc + 1] : 0.0f;
                float o00 = acc[mt][nt][0] + b0, o01 = acc[mt][nt][1] + b1;
                float o10 = acc[mt][nt][2] + b0, o11 = acc[mt][nt][3] + b1;
                if (act == 1) {
                    o00 = fmaxf(o00, 0.0f); o01 = fmaxf(o01, 0.0f);
                    o10 = fmaxf(o10, 0.0f); o11 = fmaxf(o11, 0.0f);
                }
                *(float2*)&Cb[(long)mr * 128 + nc] = make_float2(o00, o01);
                *(float2*)&Cb[(long)(mr + 8) * 128 + nc] = make_float2(o10, o11);
            }
    }
}

// ================= fused attention v5: tf32 S-gemm + f16 GEMM2 =================
// h = tanh( (r x^T)/sqrt(E) ) v   per (b,h)
// Block: 128 m-rows, p-tiles of 64, 512 threads (16 warps).
// S-gemm: 3xTF32 (identical to R7 winner). attn packed to fp16 half2 (pairs
// along p) at the tanh epilogue. GEMM2: m16n8k16 f16, attn x (v_hi + v_lo),
// v pre-split to fp16 hi/lo once per p-tile (no range issues: |attn|<=1, |v|~15).
// smem words (1 word = 1 float or 1 half2):
//   rs  [128][132] float @ 0        (16896)
//   xs  [64][132]  float @ 16896    (8448)
//   SSH [128][36]  half2 @ 25344    (4608)   attn pairs along p (32 used)
//   VHS [32][136]  half2 @ 29952    (4352)   v hi, pairs along p
//   VLS [32][136]  half2 @ 34304    (4352)   v lo
#define A6_RS  0
#define A6_XS  16896
#define A6_SSH 25344
#define A6_VHS 29952
#define A6_VLS 34304
#define A6_WORDS (34304 + 4352)

__global__ __launch_bounds__(512, 1) void attn_mix_kernel(
    const float* __restrict__ r, const float* __restrict__ x,
    const float* __restrict__ v, float* __restrict__ hcat)
{
    extern __shared__ unsigned smw[];
    float* rs = (float*)(smw + A6_RS);    // [m][k] stride 132
    float* xs = (float*)(smw + A6_XS);    // [p][k] stride 132
    unsigned* SSH = smw + A6_SSH;         // [m][p-pair] stride 36
    unsigned* VHS = smw + A6_VHS;         // [p-pair][f] stride 136
    unsigned* VLS = smw + A6_VLS;

    const float inv_scale = 0.08838834764831845f;  // 1/sqrt(128)

    int by = blockIdx.y;
    int b = by >> 2;
    int h = by & 3;
    int m0 = blockIdx.x * 128;

    const float* rb = r + (long)by * Nn * DFc;
    const float* xb = x + (long)b * Nn * DFc;
    const float* vb = v + (long)by * Nn * Ec;

    int t = threadIdx.x;
    int warp = t >> 5;
    int lane = t & 31;
    int g = lane >> 2;
    int q = lane & 3;

    int wm = warp >> 2;     // 0..3 -> m offset wm*32
    int wq = warp & 3;      // 0..3 -> p offset wq*16 (S) / f offset wq*32 (GEMM2)
    int mrb = wm * 32;

    // load r tile [128 m][128 k]
    {
        int row = t >> 2;
        int cb = (t & 3) * 32;
#pragma unroll
        for (int j = 0; j < 8; j++) {
            float4 rv = *(const float4*)(rb + (long)(m0 + row) * DFc + cb + j * 4);
            *(float4*)&rs[row * 132 + cb + j * 4] = rv;
        }
    }

    float hacc[2][4][4];
#pragma unroll
    for (int mt = 0; mt < 2; mt++)
#pragma unroll
        for (int nt = 0; nt < 4; nt++)
#pragma unroll
            for (int c = 0; c < 4; c++) hacc[mt][nt][c] = 0.0f;

    for (int pt = 0; pt < Nn / 64; pt++) {
        int p0 = pt * 64;
        __syncthreads();   // prev GEMM2 done (VHS/VLS/SSH free), xs free; covers r load iter 0

        // ---- load x tile [64 p][128 k] (raw fp32) ----
        {
            int row = t >> 3;
            int cb = (t & 7) * 16;
#pragma unroll
            for (int j = 0; j < 4; j++) {
                float4 xv = *(const float4*)(xb + (long)(p0 + row) * DFc + cb + j * 4);
                *(float4*)&xs[row * 132 + cb + j * 4] = xv;
            }
        }
        // ---- load + split v tile [64 p][128 f] -> fp16 pairs along p ----
        {
            int p2 = t >> 4;             // 0..31 (p-pair index)
            int fc = (t & 15) * 8;       // f base
            const float* v0p = vb + (long)(p0 + 2 * p2) * Ec + fc;
            const float* v1p = v0p + Ec;
            float4 a0 = *(const float4*)(v0p);
            float4 a1 = *(const float4*)(v0p + 4);
            float4 c0 = *(const float4*)(v1p);
            float4 c1 = *(const float4*)(v1p + 4);
            unsigned hw[8], lw[8];
            split2(a0.x, c0.x, hw[0], lw[0]);
            split2(a0.y, c0.y, hw[1], lw[1]);
            split2(a0.z, c0.z, hw[2], lw[2]);
            split2(a0.w, c0.w, hw[3], lw[3]);
            split2(a1.x, c1.x, hw[4], lw[4]);
            split2(a1.y, c1.y, hw[5], lw[5]);
            split2(a1.z, c1.z, hw[6], lw[6]);
            split2(a1.w, c1.w, hw[7], lw[7]);
            int wbase = p2 * 136 + fc;
            *(uint4*)&VHS[wbase]     = make_uint4(hw[0], hw[1], hw[2], hw[3]);
            *(uint4*)&VHS[wbase + 4] = make_uint4(hw[4], hw[5], hw[6], hw[7]);
            *(uint4*)&VLS[wbase]     = make_uint4(lw[0], lw[1], lw[2], lw[3]);
            *(uint4*)&VLS[wbase + 4] = make_uint4(lw[4], lw[5], lw[6], lw[7]);
        }
        __syncthreads();

        // ---- S-gemm: 3xTF32, warp region m32 x p16 (identical to R7) ----
        float sacc[2][2][4];
#pragma unroll
        for (int mt = 0; mt < 2; mt++)
#pragma unroll
            for (int nt = 0; nt < 2; nt++)
#pragma unroll
                for (int c = 0; c < 4; c++) sacc[mt][nt][c] = 0.0f;

#pragma unroll 4
        for (int kc = 0; kc < 16; kc++) {
            int k0 = kc * 8;
            unsigned a_hi[2][4], a_lo[2][4];
#pragma unroll
            for (int mt = 0; mt < 2; mt++) {
                int mr = mrb + mt * 16;
                float e0 = rs[(mr + g) * 132 + k0 + q];
                float e1 = rs[(mr + g + 8) * 132 + k0 + q];
                float e2 = rs[(mr + g) * 132 + k0 + q + 4];
                float e3 = rs[(mr + g + 8) * 132 + k0 + q + 4];
                a_hi[mt][0] = f2tf(e0); a_lo[mt][0] = f2tf(e0 - __uint_as_float(a_hi[mt][0]));
                a_hi[mt][1] = f2tf(e1); a_lo[mt][1] = f2tf(e1 - __uint_as_float(a_hi[mt][1]));
                a_hi[mt][2] = f2tf(e2); a_lo[mt][2] = f2tf(e2 - __uint_as_float(a_hi[mt][2]));
                a_hi[mt][3] = f2tf(e3); a_lo[mt][3] = f2tf(e3 - __uint_as_float(a_hi[mt][3]));
            }
            unsigned b_hi[2][2], b_lo[2][2];
#pragma unroll
            for (int nt = 0; nt < 2; nt++) {
                int pr = wq * 16 + nt * 8 + g;
                float e0 = xs[pr * 132 + k0 + q];
                float e1 = xs[pr * 132 + k0 + q + 4];
                b_hi[nt][0] = f2tf(e0); b_lo[nt][0] = f2tf(e0 - __uint_as_float(b_hi[nt][0]));
                b_hi[nt][1] = f2tf(e1); b_lo[nt][1] = f2tf(e1 - __uint_as_float(b_hi[nt][1]));
            }
#pragma unroll
            for (int mt = 0; mt < 2; mt++)
#pragma unroll
                for (int nt = 0; nt < 2; nt++) {
                    mma_tf32(sacc[mt][nt], a_hi[mt], b_hi[nt]);
                    mma_tf32(sacc[mt][nt], a_hi[mt], b_lo[nt]);
                    mma_tf32(sacc[mt][nt], a_lo[mt], b_hi[nt]);
                }
        }

        // ---- tanh epilogue -> SSH (attn as fp16 half2, pairs along p) ----
        // S frag: c0=(g, col 2q), c1=(g, 2q+1), c2=(g+8, 2q), c3=(g+8, 2q+1)
        // p col = wq*16 + nt*8 + 2q -> pair word index = wq*8 + nt*4 + q
#pragma unroll
        for (int mt = 0; mt < 2; mt++)
#pragma unroll
            for (int nt = 0; nt < 2; nt++) {
                int row0 = mrb + mt * 16 + g;
                int wcol = wq * 8 + nt * 4 + q;
                float t0 = tanh_fast(sacc[mt][nt][0] * inv_scale);
                float t1 = tanh_fast(sacc[mt][nt][1] * inv_scale);
                float t2 = tanh_fast(sacc[mt][nt][2] * inv_scale);
                float t3 = tanh_fast(sacc[mt][nt][3] * inv_scale);
                SSH[row0 * 36 + wcol] = pack2(t0, t1);
                SSH[(row0 + 8) * 36 + wcol] = pack2(t2, t3);
            }
        __syncthreads();   // SSH ready

        // ---- GEMM2: m16n8k16 f16, warp m32 x f32, attn x (v_hi + v_lo) ----
#pragma unroll
        for (int pc = 0; pc < 4; pc++) {
            int pw = pc * 8;   // p-pair base (k16 chunk = 8 pairs)
            unsigned af[2][4];
#pragma unroll
            for (int mt = 0; mt < 2; mt++) {
                int s0 = (mrb + mt * 16 + g) * 36 + pw + q;
                int s1 = s0 + 8 * 36;
                af[mt][0] = SSH[s0];      // (row g,   k=2q,2q+1)
                af[mt][1] = SSH[s1];      // (row g+8, k=2q,2q+1)
                af[mt][2] = SSH[s0 + 4];  // (row g,   k=2q+8,2q+9)
                af[mt][3] = SSH[s1 + 4];  // (row g+8, k=2q+8,2q+9)
            }
#pragma unroll
            for (int nt = 0; nt < 4; nt++) {
                int fc = wq * 32 + nt * 8 + g;
                unsigned bh2[2], bl2[2];
                bh2[0] = VHS[(pw + q) * 136 + fc];       // (k=2q,2q+1,   col g)
                bh2[1] = VHS[(pw + q + 4) * 136 + fc];   // (k=2q+8,2q+9, col g)
                bl2[0] = VLS[(pw + q) * 136 + fc];
                bl2[1] = VLS[(pw + q + 4) * 136 + fc];
#pragma unroll
                for (int mt = 0; mt < 2; mt++) {
                    mma_f16(hacc[mt][nt], af[mt], bh2);
                    mma_f16(hacc[mt][nt], af[mt], bl2);
                }
            }
        }
    }

    // ---- write h into hcat [b][n][h][f] ----
#pragma unroll
    for (int mt = 0; mt < 2; mt++)
#pragma unroll
        for (int nt = 0; nt < 4; nt++) {
            int mrow = m0 + mrb + mt * 16 + g;
            int fc = wq * 32 + nt * 8 + 2 * q;
            float* hp0 = hcat + (((long)b * Nn + mrow) * Hc + h) * Ec + fc;
            float* hp1 = hcat + (((long)b * Nn + mrow + 8) * Hc + h) * Ec + fc;
            *(float2*)hp0 = make_float2(hacc[mt][nt][0], hacc[mt][nt][1]);
            *(float2*)hp1 = make_float2(hacc[mt][nt][2], hacc[mt][nt][3]);
        }
}

// ---------------- launch ----------------
extern "C" void kernel_launch(void* const* d_in, const int* in_sizes, int n_in,
                              void* d_out, int out_size) {
    const float* x      = (const float*)d_in[0];
    const float* emb1_W = (const float*)d_in[1];
    const float* emb1_b = (const float*)d_in[2];
    const float* wq_W   = (const float*)d_in[3];
    const float* wq_b   = (const float*)d_in[4];
    const float* wv_W   = (const float*)d_in[7];
    const float* wv_b   = (const float*)d_in[8];
    const float* emb2_W = (const float*)d_in[9];
    const float* emb2_b = (const float*)d_in[10];
    float* out = (float*)d_out;

    float *gg, *gemb, *gq, *gv, *gu, *gr, *gh;
    cudaGetSymbolAddress((void**)&gg, g_g);
    cudaGetSymbolAddress((void**)&gemb, g_emb);
    cudaGetSymbolAddress((void**)&gq, g_q);
    cudaGetSymbolAddress((void**)&gv, g_v);
    cudaGetSymbolAddress((void**)&gu, g_u);
    cudaGetSymbolAddress((void**)&gr, g_r);
    cudaGetSymbolAddress((void**)&gh, g_h);

    static int smem_set = 0;
    if (!smem_set) {
        cudaFuncSetAttribute(attn_mix_kernel, cudaFuncAttributeMaxDynamicSharedMemorySize,
                             A6_WORDS * sizeof(unsigned));
        smem_set = 1;
    }

    // zero split-K accumulators
    zero_kernel<<<(Bc * Ec * DFc + 255) / 256, 256>>>(gg, Bc * Ec * DFc);
    zero_kernel<<<(Bc * Hc * DFc * Ec + 255) / 256, 256>>>(gu, Bc * Hc * DFc * Ec);

    // stage 1: g[b,e,d] = sum_m W1[e,m] x[b,m,d]   (split-K 8, atomic)
    tf32_gemm<<<dim3(1, Bc, 8), 256>>>(emb1_W, 0, Bc, Nn, 1,
                                       x, (long)Nn * DFc, Bc, 1, DFc,
                                       nullptr, 0,
                                       gg, (long)Ec * DFc, Nn, 8, 0);

    // stage 2: emb[b,n,e] = sum_d x[b,n,d] g[b,e,d] + emb1_b[e]
    tf32_gemm<<<dim3(16, Bc, 1), 256>>>(x, (long)Nn * DFc, 1, DFc, 1,
                                        gg, (long)Ec * DFc, Bc, DFc, 1,
                                        emb1_b, 0,
                                        gemb, (long)Nn * Ec, DFc, 1, 0);

    // stage 3: q, v projections per (b,h)
    tf32_gemm<<<dim3(16, Bc * Hc, 1), 256>>>(gemb, (long)Nn * Ec, Hc, Ec, 1,
                                             wq_W, (long)Ec * Ec, Hc, Ec, 1,
                                             wq_b, Ec,
                                             gq, (long)Nn * Ec, Ec, 1, 0);
    tf32_gemm<<<dim3(16, Bc * Hc, 1), 256>>>(gemb, (long)Nn * Ec, Hc, Ec, 1,
                                             wv_W, (long)Ec * Ec, Hc, Ec, 1,
                                             wv_b, Ec,
                                             gv, (long)Nn * Ec, Ec, 1, 0);

    // stage 4: u[b,h,d,f] = sum_n x[b,n,d] v[b,h,n,f]   (split-K 8, atomic)
    tf32_gemm<<<dim3(1, Bc * Hc, 8), 256>>>(x, (long)Nn * DFc, Hc, 1, DFc,
                                            gv, (long)Nn * Ec, Bc * Hc, 1, Ec,
                                            nullptr, 0,
                                            gu, (long)DFc * Ec, Nn, 8, 0);

    // stage 5: r[b,h,n,d] = sum_f q[b,h,n,f] u[b,h,d,f]
    tf32_gemm<<<dim3(16, Bc * Hc, 1), 256>>>(gq, (long)Nn * Ec, 1, Ec, 1,
                                             gu, (long)DFc * Ec, Bc * Hc, Ec, 1,
                                             nullptr, 0,
                                             gr, (long)Nn * DFc, Ec, 1, 0);

    // stage 6: fused attention (tf32 S-gemm + f16 GEMM2)
    attn_mix_kernel<<<dim3(Nn / 128, Bc * Hc), 512, A6_WORDS * sizeof(unsigned)>>>(
        gr, x, gv, gh);

    // stage 7: out = relu(hcat @ emb2_W^T + emb2_b)
    tf32_gemm<<<dim3(16, Bc, 1), 256>>>(gh, (long)Nn * Hc * Ec, 1, Hc * Ec, 1,
                                        emb2_W, 0, 1, Hc * Ec, 1,
                                        emb2_b, 0,
                                        out, (long)Nn * Ec, Hc * Ec, 1, 1);
}

// round 11
// speedup vs baseline: 2.4829x; 1.4834x over previous
#include <cuda_runtime.h>
#include <cuda_fp16.h>
#include <math.h>

#define Bc 8
#define Nn 2048
#define DFc 128
#define Ec 128
#define Hc 4

// ---------------- scratch (static device arrays; no allocation) ----------------
__device__ float g_g[Bc * Ec * DFc];                     // [b][e][d]
__device__ float g_emb[Bc * Nn * Ec];                    // [b][n][e]
__device__ float g_q[(size_t)Bc * Hc * Nn * Ec];         // [b][h][n][f]
__device__ float g_v[(size_t)Bc * Hc * Nn * Ec];         // [b][h][n][f]
__device__ float g_u[Bc * Hc * DFc * Ec];                // [b][h][d][f]
__device__ float g_r[(size_t)Bc * Hc * Nn * DFc];        // [b][h][n][d]
__device__ float g_h[(size_t)Bc * Nn * Hc * Ec];         // hcat layout [b][n][h][f]

// ---------------- zero init ----------------
__global__ void zero_kernel(float* p, int n) {
    int i = blockIdx.x * blockDim.x + threadIdx.x;
    if (i < n) p[i] = 0.0f;
}

// ---------------- tf32 helpers ----------------
__device__ __forceinline__ unsigned f2tf(float f) {
    unsigned u;
    asm("cvt.rna.tf32.f32 %0, %1;" : "=r"(u) : "f"(f));
    return u;
}

__device__ __forceinline__ void mma_tf32(float c[4], const unsigned a[4], const unsigned b[2]) {
    asm volatile(
        "mma.sync.aligned.m16n8k8.row.col.f32.tf32.tf32.f32 "
        "{%0,%1,%2,%3}, {%4,%5,%6,%7}, {%8,%9}, {%0,%1,%2,%3};"
        : "+f"(c[0]), "+f"(c[1]), "+f"(c[2]), "+f"(c[3])
        : "r"(a[0]), "r"(a[1]), "r"(a[2]), "r"(a[3]), "r"(b[0]), "r"(b[1]));
}

__device__ __forceinline__ float tanh_fast(float x) {
    float y;
    asm("tanh.approx.f32 %0, %1;" : "=f"(y) : "f"(x));
    return y;
}

// ---------------- fp16 helpers ----------------
__device__ __forceinline__ void mma_f16(float c[4], const unsigned a[4], const unsigned b[2]) {
    asm volatile(
        "mma.sync.aligned.m16n8k16.row.col.f32.f16.f16.f32 "
        "{%0,%1,%2,%3}, {%4,%5,%6,%7}, {%8,%9}, {%0,%1,%2,%3};"
        : "+f"(c[0]), "+f"(c[1]), "+f"(c[2]), "+f"(c[3])
        : "r"(a[0]), "r"(a[1]), "r"(a[2]), "r"(a[3]), "r"(b[0]), "r"(b[1]));
}

__device__ __forceinline__ unsigned pack2(float e0, float e1) {
    __half2 h = __floats2half2_rn(e0, e1);
    return *reinterpret_cast<unsigned*>(&h);
}

__device__ __forceinline__ void split2(float e0, float e1, unsigned& hw, unsigned& lw) {
    __half2 h = __floats2half2_rn(e0, e1);
    float2 hf = __half22float2(h);
    __half2 l = __floats2half2_rn(e0 - hf.x, e1 - hf.y);
    hw = *reinterpret_cast<unsigned*>(&h);
    lw = *reinterpret_cast<unsigned*>(&l);
}

// ================= unified 3xTF32 tensor GEMM (unchanged) =================
__global__ __launch_bounds__(256, 1) void tf32_gemm(
    const float* __restrict__ A, long a_sb, int a_div, int a_sm, int a_sk,
    const float* __restrict__ Bm, long b_sb, int b_mod, int b_sn, int b_sk,
    const float* __restrict__ bias, int bias_sb,
    float* __restrict__ C, long c_sb,
    int K, int ksplit, int act)
{
    __shared__ float As[128 * 36];
    __shared__ float Bs[128 * 36];

    int by = blockIdx.y;
    int m0 = blockIdx.x * 128;
    const float* Ab = A + (long)(by / a_div) * a_sb + (long)m0 * a_sm;
    const float* Bb = Bm + (long)(by % b_mod) * b_sb;
    float* Cb = C + (long)by * c_sb + (long)m0 * 128;

    int Kper = K / ksplit;
    int k0base = blockIdx.z * Kper;

    int t = threadIdx.x;
    int warp = t >> 5;
    int lane = t & 31;
    int g = lane >> 2;
    int q = lane & 3;
    int wm = warp >> 1;
    int wn = warp & 1;

    float acc[2][8][4];
#pragma unroll
    for (int mt = 0; mt < 2; mt++)
#pragma unroll
        for (int nt = 0; nt < 8; nt++)
#pragma unroll
            for (int c = 0; c < 4; c++) acc[mt][nt][c] = 0.0f;

    for (int kc0 = 0; kc0 < Kper; kc0 += 32) {
        int k0 = k0base + kc0;
        __syncthreads();
        if (a_sk == 1) {
            int row = t >> 1;
            int c4 = (t & 1) * 16;
            const float* src = Ab + (long)row * a_sm + k0 + c4;
            float4 v0 = *(const float4*)(src);
            float4 v1 = *(const float4*)(src + 4);
            float4 v2 = *(const float4*)(src + 8);
            float4 v3 = *(const float4*)(src + 12);
            float* dst = &As[row * 36 + c4];
            *(float4*)(dst) = v0; *(float4*)(dst + 4) = v1;
            *(float4*)(dst + 8) = v2; *(float4*)(dst + 12) = v3;
        } else {
            int row = t & 127;
            int kb = (t >> 7) * 16;
#pragma unroll
            for (int e = 0; e < 16; e++)
                As[row * 36 + kb + e] = Ab[(long)row * a_sm + (long)(k0 + kb + e) * a_sk];
        }
        if (b_sk == 1) {
            int row = t >> 1;
            int c4 = (t & 1) * 16;
            const float* src = Bb + (long)row * b_sn + k0 + c4;
            float4 v0 = *(const float4*)(src);
            float4 v1 = *(const float4*)(src + 4);
            float4 v2 = *(const float4*)(src + 8);
            float4 v3 = *(const float4*)(src + 12);
            float* dst = &Bs[row * 36 + c4];
            *(float4*)(dst) = v0; *(float4*)(dst + 4) = v1;
            *(float4*)(dst + 8) = v2; *(float4*)(dst + 12) = v3;
        } else {
            int row = t & 127;
            int kb = (t >> 7) * 16;
#pragma unroll
            for (int e = 0; e < 16; e++)
                Bs[row * 36 + kb + e] = Bb[(long)row * b_sn + (long)(k0 + kb + e) * b_sk];
        }
        __syncthreads();

#pragma unroll
        for (int kc = 0; kc < 4; kc++) {
            int k8 = kc * 8;
            unsigned ah[2][4], al[2][4];
#pragma unroll
            for (int mt = 0; mt < 2; mt++) {
                int mr = wm * 32 + mt * 16;
                float e0 = As[(mr + g) * 36 + k8 + q];
                float e1 = As[(mr + g + 8) * 36 + k8 + q];
                float e2 = As[(mr + g) * 36 + k8 + q + 4];
                float e3 = As[(mr + g + 8) * 36 + k8 + q + 4];
                ah[mt][0] = f2tf(e0); al[mt][0] = f2tf(e0 - __uint_as_float(ah[mt][0]));
                ah[mt][1] = f2tf(e1); al[mt][1] = f2tf(e1 - __uint_as_float(ah[mt][1]));
                ah[mt][2] = f2tf(e2); al[mt][2] = f2tf(e2 - __uint_as_float(ah[mt][2]));
                ah[mt][3] = f2tf(e3); al[mt][3] = f2tf(e3 - __uint_as_float(ah[mt][3]));
            }
            unsigned bh[8][2], bl[8][2];
#pragma unroll
            for (int nt = 0; nt < 8; nt++) {
                int nr = wn * 64 + nt * 8 + g;
                float e0 = Bs[nr * 36 + k8 + q];
                float e1 = Bs[nr * 36 + k8 + q + 4];
                bh[nt][0] = f2tf(e0); bl[nt][0] = f2tf(e0 - __uint_as_float(bh[nt][0]));
                bh[nt][1] = f2tf(e1); bl[nt][1] = f2tf(e1 - __uint_as_float(bh[nt][1]));
            }
#pragma unroll
            for (int mt = 0; mt < 2; mt++)
#pragma unroll
                for (int nt = 0; nt < 8; nt++) {
                    mma_tf32(acc[mt][nt], ah[mt], bh[nt]);
                    mma_tf32(acc[mt][nt], ah[mt], bl[nt]);
                    mma_tf32(acc[mt][nt], al[mt], bh[nt]);
                }
        }
    }

    if (ksplit > 1) {
#pragma unroll
        for (int mt = 0; mt < 2; mt++)
#pragma unroll
            for (int nt = 0; nt < 8; nt++) {
                int mr = wm * 32 + mt * 16 + g;
                int nc = wn * 64 + nt * 8 + 2 * q;
                atomicAdd(&Cb[(long)mr * 128 + nc], acc[mt][nt][0]);
                atomicAdd(&Cb[(long)mr * 128 + nc + 1], acc[mt][nt][1]);
                atomicAdd(&Cb[(long)(mr + 8) * 128 + nc], acc[mt][nt][2]);
                atomicAdd(&Cb[(long)(mr + 8) * 128 + nc + 1], acc[mt][nt][3]);
            }
    } else {
        const float* bp = bias ? (bias + (long)(by % b_mod) * bias_sb) : nullptr;
#pragma unroll
        for (int mt = 0; mt < 2; mt++)
#pragma unroll
            for (int nt = 0; nt < 8; nt++) {
                int mr = wm * 32 + mt * 16 + g;
                int nc = wn * 64 + nt * 8 + 2 * q;
                float b0 = bp ? bp[nc] : 0.0f;
                float b1 = bp ? bp[nc + 1] : 0.0f;
                float o00 = acc[mt][nt][0] + b0, o01 = acc[mt][nt][1] + b1;
                float o10 = acc[mt][nt][2] + b0, o11 = acc[mt][nt][3] + b1;
                if (act == 1) {
                    o00 = fmaxf(o00, 0.0f); o01 = fmaxf(o01, 0.0f);
                    o10 = fmaxf(o10, 0.0f); o11 = fmaxf(o11, 0.0f);
                }
                *(float2*)&Cb[(long)mr * 128 + nc] = make_float2(o00, o01);
                *(float2*)&Cb[(long)(mr + 8) * 128 + nc] = make_float2(o10, o11);
            }
    }
}

// ================= full fp16-split fused attention =================
// h = tanh( (r x^T)/sqrt(E) ) v   per (b,h)
// Block: 128 m-rows, p-tiles of 64, 512 threads (16 warps).
// r scaled by 2^-6 at load; all operands fp16 hi/lo (half2 pairs along k).
// S-gemm: 3-term m16n8k16 (hh, hl, lh) -> ~22-bit precision (same as 3xTF32).
// GEMM2: attn(fp16) x (v_hi + v_lo)  -- R9-validated path, unchanged.
// smem words (1 word = half2). Row strides: 128 k -> 68 words; 64 p-pairs -> 36.
//   RHS [128][68] @ 0        RLS @ 8704
//   XHS [64][68]  @ 17408    XLS @ 21760
//   SSH [128][36] @ 26112
//   VHS [32][136] @ 30720    VLS @ 35072
#define A7_RHS 0
#define A7_RLS 8704
#define A7_XHS 17408
#define A7_XLS 21760
#define A7_SSH 26112
#define A7_VHS 30720
#define A7_VLS 35072
#define A7_WORDS (35072 + 4352)

__global__ __launch_bounds__(512, 1) void attn_f16v2_kernel(
    const float* __restrict__ r, const float* __restrict__ x,
    const float* __restrict__ v, float* __restrict__ hcat)
{
    extern __shared__ unsigned smw[];
    unsigned* RHS = smw + A7_RHS;   // [m][kw] stride 68
    unsigned* RLS = smw + A7_RLS;
    unsigned* XHS = smw + A7_XHS;   // [p][kw] stride 68
    unsigned* XLS = smw + A7_XLS;
    unsigned* SSH = smw + A7_SSH;   // [m][p-pair] stride 36
    unsigned* VHS = smw + A7_VHS;   // [p-pair][f] stride 136
    unsigned* VLS = smw + A7_VLS;

    const float rscale = 0.015625f;               // 2^-6
    const float inv_scale = 5.656854249492380f;   // 64 / sqrt(128)

    int by = blockIdx.y;
    int b = by >> 2;
    int h = by & 3;
    int m0 = blockIdx.x * 128;

    const float* rb = r + (long)by * Nn * DFc;
    const float* xb = x + (long)b * Nn * DFc;
    const float* vb = v + (long)by * Nn * Ec;

    int t = threadIdx.x;
    int warp = t >> 5;
    int lane = t & 31;
    int g = lane >> 2;
    int q = lane & 3;

    int wm = warp >> 2;     // 0..3 -> m offset wm*32
    int wq = warp & 3;      // 0..3 -> p offset wq*16 (S) / f offset wq*32 (GEMM2)
    int mrb = wm * 32;

    // ---- load + split r tile [128 m][128 k] (scaled), 64 words/row, stride 68 ----
    {
        int row = t >> 2;            // 0..127
        int cw = (t & 3) * 16;       // word base 0/16/32/48
#pragma unroll
        for (int j = 0; j < 8; j++) {
            float4 rv = *(const float4*)(rb + (long)(m0 + row) * DFc + cw * 2 + j * 4);
            unsigned h0, l0, h1, l1;
            split2(rv.x * rscale, rv.y * rscale, h0, l0);
            split2(rv.z * rscale, rv.w * rscale, h1, l1);
            int wi = row * 68 + cw + j * 2;
            RHS[wi] = h0; RHS[wi + 1] = h1;
            RLS[wi] = l0; RLS[wi + 1] = l1;
        }
    }

    float hacc[2][4][4];
#pragma unroll
    for (int mt = 0; mt < 2; mt++)
#pragma unroll
        for (int nt = 0; nt < 4; nt++)
#pragma unroll
            for (int c = 0; c < 4; c++) hacc[mt][nt][c] = 0.0f;

    for (int pt = 0; pt < Nn / 64; pt++) {
        int p0 = pt * 64;
        __syncthreads();   // prev iter's reads done; also covers r split on iter 0

        // ---- load + split x tile [64 p][128 k]: 64 words/row, stride 68 ----
        {
            int row = t >> 3;            // 0..63
            int cw = (t & 7) * 8;        // word base 0..56
#pragma unroll
            for (int j = 0; j < 4; j++) {
                float4 xv = *(const float4*)(xb + (long)(p0 + row) * DFc + cw * 2 + j * 4);
                unsigned h0, l0, h1, l1;
                split2(xv.x, xv.y, h0, l0);
                split2(xv.z, xv.w, h1, l1);
                int wi = row * 68 + cw + j * 2;
                XHS[wi] = h0; XHS[wi + 1] = h1;
                XLS[wi] = l0; XLS[wi + 1] = l1;
            }
        }
        // ---- load + split v tile [64 p][128 f] -> fp16 pairs along p (R9 path) ----
        {
            int p2 = t >> 4;             // 0..31 (p-pair index)
            int fc = (t & 15) * 8;       // f base
            const float* v0p = vb + (long)(p0 + 2 * p2) * Ec + fc;
            const float* v1p = v0p + Ec;
            float4 a0 = *(const float4*)(v0p);
            float4 a1 = *(const float4*)(v0p + 4);
            float4 c0 = *(const float4*)(v1p);
            float4 c1 = *(const float4*)(v1p + 4);
            unsigned hw[8], lw[8];
            split2(a0.x, c0.x, hw[0], lw[0]);
            split2(a0.y, c0.y, hw[1], lw[1]);
            split2(a0.z, c0.z, hw[2], lw[2]);
            split2(a0.w, c0.w, hw[3], lw[3]);
            split2(a1.x, c1.x, hw[4], lw[4]);
            split2(a1.y, c1.y, hw[5], lw[5]);
            split2(a1.z, c1.z, hw[6], lw[6]);
            split2(a1.w, c1.w, hw[7], lw[7]);
            int wbase = p2 * 136 + fc;
            *(uint4*)&VHS[wbase]     = make_uint4(hw[0], hw[1], hw[2], hw[3]);
            *(uint4*)&VHS[wbase + 4] = make_uint4(hw[4], hw[5], hw[6], hw[7]);
            *(uint4*)&VLS[wbase]     = make_uint4(lw[0], lw[1], lw[2], lw[3]);
            *(uint4*)&VLS[wbase + 4] = make_uint4(lw[4], lw[5], lw[6], lw[7]);
        }
        __syncthreads();

        // ---- S-gemm: 3-term fp16 m16n8k16, warp m32 x p16 ----
        float sacc[2][2][4];
#pragma unroll
        for (int mt = 0; mt < 2; mt++)
#pragma unroll
            for (int nt = 0; nt < 2; nt++)
#pragma unroll
                for (int c = 0; c < 4; c++) sacc[mt][nt][c] = 0.0f;

#pragma unroll
        for (int kc = 0; kc < 8; kc++) {
            int kw = kc * 8;
            unsigned ah[2][4], al[2][4];
#pragma unroll
            for (int mt = 0; mt < 2; mt++) {
                int r0 = (mrb + mt * 16 + g) * 68 + kw + q;
                int r1 = r0 + 8 * 68;
                ah[mt][0] = RHS[r0];     ah[mt][1] = RHS[r1];
                ah[mt][2] = RHS[r0 + 4]; ah[mt][3] = RHS[r1 + 4];
                al[mt][0] = RLS[r0];     al[mt][1] = RLS[r1];
                al[mt][2] = RLS[r0 + 4]; al[mt][3] = RLS[r1 + 4];
            }
            unsigned bh[2][2], bl[2][2];
#pragma unroll
            for (int nt = 0; nt < 2; nt++) {
                int pb = (wq * 16 + nt * 8 + g) * 68 + kw + q;
                bh[nt][0] = XHS[pb]; bh[nt][1] = XHS[pb + 4];
                bl[nt][0] = XLS[pb]; bl[nt][1] = XLS[pb + 4];
            }
#pragma unroll
            for (int mt = 0; mt < 2; mt++)
#pragma unroll
                for (int nt = 0; nt < 2; nt++) {
                    mma_f16(sacc[mt][nt], ah[mt], bh[nt]);
                    mma_f16(sacc[mt][nt], ah[mt], bl[nt]);
                    mma_f16(sacc[mt][nt], al[mt], bh[nt]);
                }
        }

        // ---- tanh epilogue -> SSH (attn as fp16 half2, pairs along p) ----
#pragma unroll
        for (int mt = 0; mt < 2; mt++)
#pragma unroll
            for (int nt = 0; nt < 2; nt++) {
                int row0 = mrb + mt * 16 + g;
                int wcol = wq * 8 + nt * 4 + q;
                float t0 = tanh_fast(sacc[mt][nt][0] * inv_scale);
                float t1 = tanh_fast(sacc[mt][nt][1] * inv_scale);
                float t2 = tanh_fast(sacc[mt][nt][2] * inv_scale);
                float t3 = tanh_fast(sacc[mt][nt][3] * inv_scale);
                SSH[row0 * 36 + wcol] = pack2(t0, t1);
                SSH[(row0 + 8) * 36 + wcol] = pack2(t2, t3);
            }
        __syncthreads();   // SSH ready

        // ---- GEMM2: m16n8k16 f16, warp m32 x f32 (R9-validated) ----
#pragma unroll
        for (int pc = 0; pc < 4; pc++) {
            int pw = pc * 8;
            unsigned af[2][4];
#pragma unroll
            for (int mt = 0; mt < 2; mt++) {
                int s0 = (mrb + mt * 16 + g) * 36 + pw + q;
                int s1 = s0 + 8 * 36;
                af[mt][0] = SSH[s0];
                af[mt][1] = SSH[s1];
                af[mt][2] = SSH[s0 + 4];
                af[mt][3] = SSH[s1 + 4];
            }
#pragma unroll
            for (int nt = 0; nt < 4; nt++) {
                int fc = wq * 32 + nt * 8 + g;
                unsigned bh2[2], bl2[2];
                bh2[0] = VHS[(pw + q) * 136 + fc];
                bh2[1] = VHS[(pw + q + 4) * 136 + fc];
                bl2[0] = VLS[(pw + q) * 136 + fc];
                bl2[1] = VLS[(pw + q + 4) * 136 + fc];
#pragma unroll
                for (int mt = 0; mt < 2; mt++) {
                    mma_f16(hacc[mt][nt], af[mt], bh2);
                    mma_f16(hacc[mt][nt], af[mt], bl2);
                }
            }
        }
    }

    // ---- write h into hcat [b][n][h][f] ----
#pragma unroll
    for (int mt = 0; mt < 2; mt++)
#pragma unroll
        for (int nt = 0; nt < 4; nt++) {
            int mrow = m0 + mrb + mt * 16 + g;
            int fc = wq * 32 + nt * 8 + 2 * q;
            float* hp0 = hcat + (((long)b * Nn + mrow) * Hc + h) * Ec + fc;
            float* hp1 = hcat + (((long)b * Nn + mrow + 8) * Hc + h) * Ec + fc;
            *(float2*)hp0 = make_float2(hacc[mt][nt][0], hacc[mt][nt][1]);
            *(float2*)hp1 = make_float2(hacc[mt][nt][2], hacc[mt][nt][3]);
        }
}

// ---------------- launch ----------------
extern "C" void kernel_launch(void* const* d_in, const int* in_sizes, int n_in,
                              void* d_out, int out_size) {
    const float* x      = (const float*)d_in[0];
    const float* emb1_W = (const float*)d_in[1];
    const float* emb1_b = (const float*)d_in[2];
    const float* wq_W   = (const float*)d_in[3];
    const float* wq_b   = (const float*)d_in[4];
    const float* wv_W   = (const float*)d_in[7];
    const float* wv_b   = (const float*)d_in[8];
    const float* emb2_W = (const float*)d_in[9];
    const float* emb2_b = (const float*)d_in[10];
    float* out = (float*)d_out;

    float *gg, *gemb, *gq, *gv, *gu, *gr, *gh;
    cudaGetSymbolAddress((void**)&gg, g_g);
    cudaGetSymbolAddress((void**)&gemb, g_emb);
    cudaGetSymbolAddress((void**)&gq, g_q);
    cudaGetSymbolAddress((void**)&gv, g_v);
    cudaGetSymbolAddress((void**)&gu, g_u);
    cudaGetSymbolAddress((void**)&gr, g_r);
    cudaGetSymbolAddress((void**)&gh, g_h);

    static int smem_set = 0;
    if (!smem_set) {
        cudaFuncSetAttribute(attn_f16v2_kernel, cudaFuncAttributeMaxDynamicSharedMemorySize,
                             A7_WORDS * sizeof(unsigned));
        smem_set = 1;
    }

    // zero split-K accumulators
    zero_kernel<<<(Bc * Ec * DFc + 255) / 256, 256>>>(gg, Bc * Ec * DFc);
    zero_kernel<<<(Bc * Hc * DFc * Ec + 255) / 256, 256>>>(gu, Bc * Hc * DFc * Ec);

    // stage 1: g[b,e,d] = sum_m W1[e,m] x[b,m,d]   (split-K 8, atomic)
    tf32_gemm<<<dim3(1, Bc, 8), 256>>>(emb1_W, 0, Bc, Nn, 1,
                                       x, (long)Nn * DFc, Bc, 1, DFc,
                                       nullptr, 0,
                                       gg, (long)Ec * DFc, Nn, 8, 0);

    // stage 2: emb[b,n,e] = sum_d x[b,n,d] g[b,e,d] + emb1_b[e]
    tf32_gemm<<<dim3(16, Bc, 1), 256>>>(x, (long)Nn * DFc, 1, DFc, 1,
                                        gg, (long)Ec * DFc, Bc, DFc, 1,
                                        emb1_b, 0,
                                        gemb, (long)Nn * Ec, DFc, 1, 0);

    // stage 3: q, v projections per (b,h)
    tf32_gemm<<<dim3(16, Bc * Hc, 1), 256>>>(gemb, (long)Nn * Ec, Hc, Ec, 1,
                                             wq_W, (long)Ec * Ec, Hc, Ec, 1,
                                             wq_b, Ec,
                                             gq, (long)Nn * Ec, Ec, 1, 0);
    tf32_gemm<<<dim3(16, Bc * Hc, 1), 256>>>(gemb, (long)Nn * Ec, Hc, Ec, 1,
                                             wv_W, (long)Ec * Ec, Hc, Ec, 1,
                                             wv_b, Ec,
                                             gv, (long)Nn * Ec, Ec, 1, 0);

    // stage 4: u[b,h,d,f] = sum_n x[b,n,d] v[b,h,n,f]   (split-K 8, atomic)
    tf32_gemm<<<dim3(1, Bc * Hc, 8), 256>>>(x, (long)Nn * DFc, Hc, 1, DFc,
                                            gv, (long)Nn * Ec, Bc * Hc, 1, Ec,
                                            nullptr, 0,
                                            gu, (long)DFc * Ec, Nn, 8, 0);

    // stage 5: r[b,h,n,d] = sum_f q[b,h,n,f] u[b,h,d,f]
    tf32_gemm<<<dim3(16, Bc * Hc, 1), 256>>>(gq, (long)Nn * Ec, 1, Ec, 1,
                                             gu, (long)DFc * Ec, Bc * Hc, Ec, 1,
                                             nullptr, 0,
                                             gr, (long)Nn * DFc, Ec, 1, 0);

    // stage 6: fused attention (full fp16 split tensor cores)
    attn_f16v2_kernel<<<dim3(Nn / 128, Bc * Hc), 512, A7_WORDS * sizeof(unsigned)>>>(
        gr, x, gv, gh);

    // stage 7: out = relu(hcat @ emb2_W^T + emb2_b)
    tf32_gemm<<<dim3(16, Bc, 1), 256>>>(gh, (long)Nn * Hc * Ec, 1, Hc * Ec, 1,
                                        emb2_W, 0, 1, Hc * Ec, 1,
                                        emb2_b, 0,
                                        out, (long)Nn * Ec, Hc * Ec, 1, 1);
}

// round 12
// speedup vs baseline: 2.4830x; 1.0001x over previous
#include <cuda_runtime.h>
#include <cuda_fp16.h>
#include <math.h>

#define Bc 8
#define Nn 2048
#define DFc 128
#define Ec 128
#define Hc 4

// ---------------- scratch (static device arrays; no allocation) ----------------
__device__ float g_g[Bc * Ec * DFc];                     // [b][e][d]
__device__ float g_emb[Bc * Nn * Ec];                    // [b][n][e]
__device__ float g_q[(size_t)Bc * Hc * Nn * Ec];         // [b][h][n][f]
__device__ float g_v[(size_t)Bc * Hc * Nn * Ec];         // [b][h][n][f]
__device__ float g_u[Bc * Hc * DFc * Ec];                // [b][h][d][f]
__device__ float g_r[(size_t)Bc * Hc * Nn * DFc];        // [b][h][n][d]
__device__ float g_h[(size_t)Bc * Nn * Hc * Ec];         // hcat layout [b][n][h][f]

// ---------------- zero init ----------------
__global__ void zero_kernel(float* p, int n) {
    int i = blockIdx.x * blockDim.x + threadIdx.x;
    if (i < n) p[i] = 0.0f;
}

// ---------------- tf32 helpers ----------------
__device__ __forceinline__ unsigned f2tf(float f) {
    unsigned u;
    asm("cvt.rna.tf32.f32 %0, %1;" : "=r"(u) : "f"(f));
    return u;
}

__device__ __forceinline__ void mma_tf32(float c[4], const unsigned a[4], const unsigned b[2]) {
    asm volatile(
        "mma.sync.aligned.m16n8k8.row.col.f32.tf32.tf32.f32 "
        "{%0,%1,%2,%3}, {%4,%5,%6,%7}, {%8,%9}, {%0,%1,%2,%3};"
        : "+f"(c[0]), "+f"(c[1]), "+f"(c[2]), "+f"(c[3])
        : "r"(a[0]), "r"(a[1]), "r"(a[2]), "r"(a[3]), "r"(b[0]), "r"(b[1]));
}

__device__ __forceinline__ float tanh_fast(float x) {
    float y;
    asm("tanh.approx.f32 %0, %1;" : "=f"(y) : "f"(x));
    return y;
}

// ---------------- fp16 helpers ----------------
__device__ __forceinline__ void mma_f16(float c[4], const unsigned a[4], const unsigned b[2]) {
    asm volatile(
        "mma.sync.aligned.m16n8k16.row.col.f32.f16.f16.f32 "
        "{%0,%1,%2,%3}, {%4,%5,%6,%7}, {%8,%9}, {%0,%1,%2,%3};"
        : "+f"(c[0]), "+f"(c[1]), "+f"(c[2]), "+f"(c[3])
        : "r"(a[0]), "r"(a[1]), "r"(a[2]), "r"(a[3]), "r"(b[0]), "r"(b[1]));
}

__device__ __forceinline__ unsigned pack2(float e0, float e1) {
    __half2 h = __floats2half2_rn(e0, e1);
    return *reinterpret_cast<unsigned*>(&h);
}

__device__ __forceinline__ void split2(float e0, float e1, unsigned& hw, unsigned& lw) {
    __half2 h = __floats2half2_rn(e0, e1);
    float2 hf = __half22float2(h);
    __half2 l = __floats2half2_rn(e0 - hf.x, e1 - hf.y);
    hw = *reinterpret_cast<unsigned*>(&h);
    lw = *reinterpret_cast<unsigned*>(&l);
}

// ================= unified 3xTF32 tensor GEMM (unchanged) =================
__global__ __launch_bounds__(256, 1) void tf32_gemm(
    const float* __restrict__ A, long a_sb, int a_div, int a_sm, int a_sk,
    const float* __restrict__ Bm, long b_sb, int b_mod, int b_sn, int b_sk,
    const float* __restrict__ bias, int bias_sb,
    float* __restrict__ C, long c_sb,
    int K, int ksplit, int act)
{
    __shared__ float As[128 * 36];
    __shared__ float Bs[128 * 36];

    int by = blockIdx.y;
    int m0 = blockIdx.x * 128;
    const float* Ab = A + (long)(by / a_div) * a_sb + (long)m0 * a_sm;
    const float* Bb = Bm + (long)(by % b_mod) * b_sb;
    float* Cb = C + (long)by * c_sb + (long)m0 * 128;

    int Kper = K / ksplit;
    int k0base = blockIdx.z * Kper;

    int t = threadIdx.x;
    int warp = t >> 5;
    int lane = t & 31;
    int g = lane >> 2;
    int q = lane & 3;
    int wm = warp >> 1;
    int wn = warp & 1;

    float acc[2][8][4];
#pragma unroll
    for (int mt = 0; mt < 2; mt++)
#pragma unroll
        for (int nt = 0; nt < 8; nt++)
#pragma unroll
            for (int c = 0; c < 4; c++) acc[mt][nt][c] = 0.0f;

    for (int kc0 = 0; kc0 < Kper; kc0 += 32) {
        int k0 = k0base + kc0;
        __syncthreads();
        if (a_sk == 1) {
            int row = t >> 1;
            int c4 = (t & 1) * 16;
            const float* src = Ab + (long)row * a_sm + k0 + c4;
            float4 v0 = *(const float4*)(src);
            float4 v1 = *(const float4*)(src + 4);
            float4 v2 = *(const float4*)(src + 8);
            float4 v3 = *(const float4*)(src + 12);
            float* dst = &As[row * 36 + c4];
            *(float4*)(dst) = v0; *(float4*)(dst + 4) = v1;
            *(float4*)(dst + 8) = v2; *(float4*)(dst + 12) = v3;
        } else {
            int row = t & 127;
            int kb = (t >> 7) * 16;
#pragma unroll
            for (int e = 0; e < 16; e++)
                As[row * 36 + kb + e] = Ab[(long)row * a_sm + (long)(k0 + kb + e) * a_sk];
        }
        if (b_sk == 1) {
            int row = t >> 1;
            int c4 = (t & 1) * 16;
            const float* src = Bb + (long)row * b_sn + k0 + c4;
            float4 v0 = *(const float4*)(src);
            float4 v1 = *(const float4*)(src + 4);
            float4 v2 = *(const float4*)(src + 8);
            float4 v3 = *(const float4*)(src + 12);
            float* dst = &Bs[row * 36 + c4];
            *(float4*)(dst) = v0; *(float4*)(dst + 4) = v1;
            *(float4*)(dst + 8) = v2; *(float4*)(dst + 12) = v3;
        } else {
            int row = t & 127;
            int kb = (t >> 7) * 16;
#pragma unroll
            for (int e = 0; e < 16; e++)
                Bs[row * 36 + kb + e] = Bb[(long)row * b_sn + (long)(k0 + kb + e) * b_sk];
        }
        __syncthreads();

#pragma unroll
        for (int kc = 0; kc < 4; kc++) {
            int k8 = kc * 8;
            unsigned ah[2][4], al[2][4];
#pragma unroll
            for (int mt = 0; mt < 2; mt++) {
                int mr = wm * 32 + mt * 16;
                float e0 = As[(mr + g) * 36 + k8 + q];
                float e1 = As[(mr + g + 8) * 36 + k8 + q];
                float e2 = As[(mr + g) * 36 + k8 + q + 4];
                float e3 = As[(mr + g + 8) * 36 + k8 + q + 4];
                ah[mt][0] = f2tf(e0); al[mt][0] = f2tf(e0 - __uint_as_float(ah[mt][0]));
                ah[mt][1] = f2tf(e1); al[mt][1] = f2tf(e1 - __uint_as_float(ah[mt][1]));
                ah[mt][2] = f2tf(e2); al[mt][2] = f2tf(e2 - __uint_as_float(ah[mt][2]));
                ah[mt][3] = f2tf(e3); al[mt][3] = f2tf(e3 - __uint_as_float(ah[mt][3]));
            }
            unsigned bh[8][2], bl[8][2];
#pragma unroll
            for (int nt = 0; nt < 8; nt++) {
                int nr = wn * 64 + nt * 8 + g;
                float e0 = Bs[nr * 36 + k8 + q];
                float e1 = Bs[nr * 36 + k8 + q + 4];
                bh[nt][0] = f2tf(e0); bl[nt][0] = f2tf(e0 - __uint_as_float(bh[nt][0]));
                bh[nt][1] = f2tf(e1); bl[nt][1] = f2tf(e1 - __uint_as_float(bh[nt][1]));
            }
#pragma unroll
            for (int mt = 0; mt < 2; mt++)
#pragma unroll
                for (int nt = 0; nt < 8; nt++) {
                    mma_tf32(acc[mt][nt], ah[mt], bh[nt]);
                    mma_tf32(acc[mt][nt], ah[mt], bl[nt]);
                    mma_tf32(acc[mt][nt], al[mt], bh[nt]);
                }
        }
    }

    if (ksplit > 1) {
#pragma unroll
        for (int mt = 0; mt < 2; mt++)
#pragma unroll
            for (int nt = 0; nt < 8; nt++) {
                int mr = wm * 32 + mt * 16 + g;
                int nc = wn * 64 + nt * 8 + 2 * q;
                atomicAdd(&Cb[(long)mr * 128 + nc], acc[mt][nt][0]);
                atomicAdd(&Cb[(long)mr * 128 + nc + 1], acc[mt][nt][1]);
                atomicAdd(&Cb[(long)(mr + 8) * 128 + nc], acc[mt][nt][2]);
                atomicAdd(&Cb[(long)(mr + 8) * 128 + nc + 1], acc[mt][nt][3]);
            }
    } else {
        const float* bp = bias ? (bias + (long)(by % b_mod) * bias_sb) : nullptr;
#pragma unroll
        for (int mt = 0; mt < 2; mt++)
#pragma unroll
            for (int nt = 0; nt < 8; nt++) {
                int mr = wm * 32 + mt * 16 + g;
                int nc = wn * 64 + nt * 8 + 2 * q;
                float b0 = bp ? bp[nc] : 0.0f;
                float b1 = bp ? bp[nc + 1] : 0.0f;
                float o00 = acc[mt][nt][0] + b0, o01 = acc[mt][nt][1] + b1;
                float o10 = acc[mt][nt][2] + b0, o11 = acc[mt][nt][3] + b1;
                if (act == 1) {
                    o00 = fmaxf(o00, 0.0f); o01 = fmaxf(o01, 0.0f);
                    o10 = fmaxf(o10, 0.0f); o11 = fmaxf(o11, 0.0f);
                }
                *(float2*)&Cb[(long)mr * 128 + nc] = make_float2(o00, o01);
                *(float2*)&Cb[(long)(mr + 8) * 128 + nc] = make_float2(o10, o11);
            }
    }
}

// ================= full fp16-split fused attention =================
// h = tanh( (r x^T)/sqrt(E) ) v   per (b,h)
// Block: 128 m-rows, p-tiles of 64, 512 threads (16 warps).
// r scaled by 2^-6 at load; all operands fp16 hi/lo (half2 pairs along k).
// S-gemm: 3-term m16n8k16 (hh, hl, lh) -> ~22-bit precision (same as 3xTF32).
// GEMM2: attn(fp16) x (v_hi + v_lo)  -- R9-validated path, unchanged.
// smem words (1 word = half2). Row strides: 128 k -> 68 words; 64 p-pairs -> 36.
//   RHS [128][68] @ 0        RLS @ 8704
//   XHS [64][68]  @ 17408    XLS @ 21760
//   SSH [128][36] @ 26112
//   VHS [32][136] @ 30720    VLS @ 35072
#define A7_RHS 0
#define A7_RLS 8704
#define A7_XHS 17408
#define A7_XLS 21760
#define A7_SSH 26112
#define A7_VHS 30720
#define A7_VLS 35072
#define A7_WORDS (35072 + 4352)

__global__ __launch_bounds__(512, 1) void attn_f16v2_kernel(
    const float* __restrict__ r, const float* __restrict__ x,
    const float* __restrict__ v, float* __restrict__ hcat)
{
    extern __shared__ unsigned smw[];
    unsigned* RHS = smw + A7_RHS;   // [m][kw] stride 68
    unsigned* RLS = smw + A7_RLS;
    unsigned* XHS = smw + A7_XHS;   // [p][kw] stride 68
    unsigned* XLS = smw + A7_XLS;
    unsigned* SSH = smw + A7_SSH;   // [m][p-pair] stride 36
    unsigned* VHS = smw + A7_VHS;   // [p-pair][f] stride 136
    unsigned* VLS = smw + A7_VLS;

    const float rscale = 0.015625f;               // 2^-6
    const float inv_scale = 5.656854249492380f;   // 64 / sqrt(128)

    int by = blockIdx.y;
    int b = by >> 2;
    int h = by & 3;
    int m0 = blockIdx.x * 128;

    const float* rb = r + (long)by * Nn * DFc;
    const float* xb = x + (long)b * Nn * DFc;
    const float* vb = v + (long)by * Nn * Ec;

    int t = threadIdx.x;
    int warp = t >> 5;
    int lane = t & 31;
    int g = lane >> 2;
    int q = lane & 3;

    int wm = warp >> 2;     // 0..3 -> m offset wm*32
    int wq = warp & 3;      // 0..3 -> p offset wq*16 (S) / f offset wq*32 (GEMM2)
    int mrb = wm * 32;

    // ---- load + split r tile [128 m][128 k] (scaled), 64 words/row, stride 68 ----
    {
        int row = t >> 2;            // 0..127
        int cw = (t & 3) * 16;       // word base 0/16/32/48
#pragma unroll
        for (int j = 0; j < 8; j++) {
            float4 rv = *(const float4*)(rb + (long)(m0 + row) * DFc + cw * 2 + j * 4);
            unsigned h0, l0, h1, l1;
            split2(rv.x * rscale, rv.y * rscale, h0, l0);
            split2(rv.z * rscale, rv.w * rscale, h1, l1);
            int wi = row * 68 + cw + j * 2;
            RHS[wi] = h0; RHS[wi + 1] = h1;
            RLS[wi] = l0; RLS[wi + 1] = l1;
        }
    }

    float hacc[2][4][4];
#pragma unroll
    for (int mt = 0; mt < 2; mt++)
#pragma unroll
        for (int nt = 0; nt < 4; nt++)
#pragma unroll
            for (int c = 0; c < 4; c++) hacc[mt][nt][c] = 0.0f;

    for (int pt = 0; pt < Nn / 64; pt++) {
        int p0 = pt * 64;
        __syncthreads();   // prev iter's reads done; also covers r split on iter 0

        // ---- load + split x tile [64 p][128 k]: 64 words/row, stride 68 ----
        {
            int row = t >> 3;            // 0..63
            int cw = (t & 7) * 8;        // word base 0..56
#pragma unroll
            for (int j = 0; j < 4; j++) {
                float4 xv = *(const float4*)(xb + (long)(p0 + row) * DFc + cw * 2 + j * 4);
                unsigned h0, l0, h1, l1;
                split2(xv.x, xv.y, h0, l0);
                split2(xv.z, xv.w, h1, l1);
                int wi = row * 68 + cw + j * 2;
                XHS[wi] = h0; XHS[wi + 1] = h1;
                XLS[wi] = l0; XLS[wi + 1] = l1;
            }
        }
        // ---- load + split v tile [64 p][128 f] -> fp16 pairs along p (R9 path) ----
        {
            int p2 = t >> 4;             // 0..31 (p-pair index)
            int fc = (t & 15) * 8;       // f base
            const float* v0p = vb + (long)(p0 + 2 * p2) * Ec + fc;
            const float* v1p = v0p + Ec;
            float4 a0 = *(const float4*)(v0p);
            float4 a1 = *(const float4*)(v0p + 4);
            float4 c0 = *(const float4*)(v1p);
            float4 c1 = *(const float4*)(v1p + 4);
            unsigned hw[8], lw[8];
            split2(a0.x, c0.x, hw[0], lw[0]);
            split2(a0.y, c0.y, hw[1], lw[1]);
            split2(a0.z, c0.z, hw[2], lw[2]);
            split2(a0.w, c0.w, hw[3], lw[3]);
            split2(a1.x, c1.x, hw[4], lw[4]);
            split2(a1.y, c1.y, hw[5], lw[5]);
            split2(a1.z, c1.z, hw[6], lw[6]);
            split2(a1.w, c1.w, hw[7], lw[7]);
            int wbase = p2 * 136 + fc;
            *(uint4*)&VHS[wbase]     = make_uint4(hw[0], hw[1], hw[2], hw[3]);
            *(uint4*)&VHS[wbase + 4] = make_uint4(hw[4], hw[5], hw[6], hw[7]);
            *(uint4*)&VLS[wbase]     = make_uint4(lw[0], lw[1], lw[2], lw[3]);
            *(uint4*)&VLS[wbase + 4] = make_uint4(lw[4], lw[5], lw[6], lw[7]);
        }
        __syncthreads();

        // ---- S-gemm: 3-term fp16 m16n8k16, warp m32 x p16 ----
        float sacc[2][2][4];
#pragma unroll
        for (int mt = 0; mt < 2; mt++)
#pragma unroll
            for (int nt = 0; nt < 2; nt++)
#pragma unroll
                for (int c = 0; c < 4; c++) sacc[mt][nt][c] = 0.0f;

#pragma unroll
        for (int kc = 0; kc < 8; kc++) {
            int kw = kc * 8;
            unsigned ah[2][4], al[2][4];
#pragma unroll
            for (int mt = 0; mt < 2; mt++) {
                int r0 = (mrb + mt * 16 + g) * 68 + kw + q;
                int r1 = r0 + 8 * 68;
                ah[mt][0] = RHS[r0];     ah[mt][1] = RHS[r1];
                ah[mt][2] = RHS[r0 + 4]; ah[mt][3] = RHS[r1 + 4];
                al[mt][0] = RLS[r0];     al[mt][1] = RLS[r1];
                al[mt][2] = RLS[r0 + 4]; al[mt][3] = RLS[r1 + 4];
            }
            unsigned bh[2][2], bl[2][2];
#pragma unroll
            for (int nt = 0; nt < 2; nt++) {
                int pb = (wq * 16 + nt * 8 + g) * 68 + kw + q;
                bh[nt][0] = XHS[pb]; bh[nt][1] = XHS[pb + 4];
                bl[nt][0] = XLS[pb]; bl[nt][1] = XLS[pb + 4];
            }
#pragma unroll
            for (int mt = 0; mt < 2; mt++)
#pragma unroll
                for (int nt = 0; nt < 2; nt++) {
                    mma_f16(sacc[mt][nt], ah[mt], bh[nt]);
                    mma_f16(sacc[mt][nt], ah[mt], bl[nt]);
                    mma_f16(sacc[mt][nt], al[mt], bh[nt]);
                }
        }

        // ---- tanh epilogue -> SSH (attn as fp16 half2, pairs along p) ----
#pragma unroll
        for (int mt = 0; mt < 2; mt++)
#pragma unroll
            for (int nt = 0; nt < 2; nt++) {
                int row0 = mrb + mt * 16 + g;
                int wcol = wq * 8 + nt * 4 + q;
                float t0 = tanh_fast(sacc[mt][nt][0] * inv_scale);
                float t1 = tanh_fast(sacc[mt][nt][1] * inv_scale);
                float t2 = tanh_fast(sacc[mt][nt][2] * inv_scale);
                float t3 = tanh_fast(sacc[mt][nt][3] * inv_scale);
                SSH[row0 * 36 + wcol] = pack2(t0, t1);
                SSH[(row0 + 8) * 36 + wcol] = pack2(t2, t3);
            }
        __syncthreads();   // SSH ready

        // ---- GEMM2: m16n8k16 f16, warp m32 x f32 (R9-validated) ----
#pragma unroll
        for (int pc = 0; pc < 4; pc++) {
            int pw = pc * 8;
            unsigned af[2][4];
#pragma unroll
            for (int mt = 0; mt < 2; mt++) {
                int s0 = (mrb + mt * 16 + g) * 36 + pw + q;
                int s1 = s0 + 8 * 36;
                af[mt][0] = SSH[s0];
                af[mt][1] = SSH[s1];
                af[mt][2] = SSH[s0 + 4];
                af[mt][3] = SSH[s1 + 4];
            }
#pragma unroll
            for (int nt = 0; nt < 4; nt++) {
                int fc = wq * 32 + nt * 8 + g;
                unsigned bh2[2], bl2[2];
                bh2[0] = VHS[(pw + q) * 136 + fc];
                bh2[1] = VHS[(pw + q + 4) * 136 + fc];
                bl2[0] = VLS[(pw + q) * 136 + fc];
                bl2[1] = VLS[(pw + q + 4) * 136 + fc];
#pragma unroll
                for (int mt = 0; mt < 2; mt++) {
                    mma_f16(hacc[mt][nt], af[mt], bh2);
                    mma_f16(hacc[mt][nt], af[mt], bl2);
                }
            }
        }
    }

    // ---- write h into hcat [b][n][h][f] ----
#pragma unroll
    for (int mt = 0; mt < 2; mt++)
#pragma unroll
        for (int nt = 0; nt < 4; nt++) {
            int mrow = m0 + mrb + mt * 16 + g;
            int fc = wq * 32 + nt * 8 + 2 * q;
            float* hp0 = hcat + (((long)b * Nn + mrow) * Hc + h) * Ec + fc;
            float* hp1 = hcat + (((long)b * Nn + mrow + 8) * Hc + h) * Ec + fc;
            *(float2*)hp0 = make_float2(hacc[mt][nt][0], hacc[mt][nt][1]);
            *(float2*)hp1 = make_float2(hacc[mt][nt][2], hacc[mt][nt][3]);
        }
}

// ---------------- launch ----------------
extern "C" void kernel_launch(void* const* d_in, const int* in_sizes, int n_in,
                              void* d_out, int out_size) {
    const float* x      = (const float*)d_in[0];
    const float* emb1_W = (const float*)d_in[1];
    const float* emb1_b = (const float*)d_in[2];
    const float* wq_W   = (const float*)d_in[3];
    const float* wq_b   = (const float*)d_in[4];
    const float* wv_W   = (const float*)d_in[7];
    const float* wv_b   = (const float*)d_in[8];
    const float* emb2_W = (const float*)d_in[9];
    const float* emb2_b = (const float*)d_in[10];
    float* out = (float*)d_out;

    float *gg, *gemb, *gq, *gv, *gu, *gr, *gh;
    cudaGetSymbolAddress((void**)&gg, g_g);
    cudaGetSymbolAddress((void**)&gemb, g_emb);
    cudaGetSymbolAddress((void**)&gq, g_q);
    cudaGetSymbolAddress((void**)&gv, g_v);
    cudaGetSymbolAddress((void**)&gu, g_u);
    cudaGetSymbolAddress((void**)&gr, g_r);
    cudaGetSymbolAddress((void**)&gh, g_h);

    static int smem_set = 0;
    if (!smem_set) {
        cudaFuncSetAttribute(attn_f16v2_kernel, cudaFuncAttributeMaxDynamicSharedMemorySize,
                             A7_WORDS * sizeof(unsigned));
        smem_set = 1;
    }

    // zero split-K accumulators
    zero_kernel<<<(Bc * Ec * DFc + 255) / 256, 256>>>(gg, Bc * Ec * DFc);
    zero_kernel<<<(Bc * Hc * DFc * Ec + 255) / 256, 256>>>(gu, Bc * Hc * DFc * Ec);

    // stage 1: g[b,e,d] = sum_m W1[e,m] x[b,m,d]   (split-K 8, atomic)
    tf32_gemm<<<dim3(1, Bc, 8), 256>>>(emb1_W, 0, Bc, Nn, 1,
                                       x, (long)Nn * DFc, Bc, 1, DFc,
                                       nullptr, 0,
                                       gg, (long)Ec * DFc, Nn, 8, 0);

    // stage 2: emb[b,n,e] = sum_d x[b,n,d] g[b,e,d] + emb1_b[e]
    tf32_gemm<<<dim3(16, Bc, 1), 256>>>(x, (long)Nn * DFc, 1, DFc, 1,
                                        gg, (long)Ec * DFc, Bc, DFc, 1,
                                        emb1_b, 0,
                                        gemb, (long)Nn * Ec, DFc, 1, 0);

    // stage 3: q, v projections per (b,h)
    tf32_gemm<<<dim3(16, Bc * Hc, 1), 256>>>(gemb, (long)Nn * Ec, Hc, Ec, 1,
                                             wq_W, (long)Ec * Ec, Hc, Ec, 1,
                                             wq_b, Ec,
                                             gq, (long)Nn * Ec, Ec, 1, 0);
    tf32_gemm<<<dim3(16, Bc * Hc, 1), 256>>>(gemb, (long)Nn * Ec, Hc, Ec, 1,
                                             wv_W, (long)Ec * Ec, Hc, Ec, 1,
                                             wv_b, Ec,
                                             gv, (long)Nn * Ec, Ec, 1, 0);

    // stage 4: u[b,h,d,f] = sum_n x[b,n,d] v[b,h,n,f]   (split-K 8, atomic)
    tf32_gemm<<<dim3(1, Bc * Hc, 8), 256>>>(x, (long)Nn * DFc, Hc, 1, DFc,
                                            gv, (long)Nn * Ec, Bc * Hc, 1, Ec,
                                            nullptr, 0,
                                            gu, (long)DFc * Ec, Nn, 8, 0);

    // stage 5: r[b,h,n,d] = sum_f q[b,h,n,f] u[b,h,d,f]
    tf32_gemm<<<dim3(16, Bc * Hc, 1), 256>>>(gq, (long)Nn * Ec, 1, Ec, 1,
                                             gu, (long)DFc * Ec, Bc * Hc, Ec, 1,
                                             nullptr, 0,
                                             gr, (long)Nn * DFc, Ec, 1, 0);

    // stage 6: fused attention (full fp16 split tensor cores)
    attn_f16v2_kernel<<<dim3(Nn / 128, Bc * Hc), 512, A7_WORDS * sizeof(unsigned)>>>(
        gr, x, gv, gh);

    // stage 7: out = relu(hcat @ emb2_W^T + emb2_b)
    tf32_gemm<<<dim3(16, Bc, 1), 256>>>(gh, (long)Nn * Hc * Ec, 1, Hc * Ec, 1,
                                        emb2_W, 0, 1, Hc * Ec, 1,
                                        emb2_b, 0,
                                        out, (long)Nn * Ec, Hc * Ec, 1, 1);
}

// round 13
// speedup vs baseline: 2.9802x; 1.2002x over previous
#include <cuda_runtime.h>
#include <cuda_fp16.h>
#include <math.h>

#define Bc 8
#define Nn 2048
#define DFc 128
#define Ec 128
#define Hc 4

// ---------------- scratch (static device arrays; no allocation) ----------------
__device__ float g_g[Bc * Ec * DFc];                     // [b][e][d]
__device__ float g_emb[Bc * Nn * Ec];                    // [b][n][e]
__device__ float g_q[(size_t)Bc * Hc * Nn * Ec];         // [b][h][n][f]
__device__ float g_v[(size_t)Bc * Hc * Nn * Ec];         // [b][h][n][f]
__device__ float g_u[Bc * Hc * DFc * Ec];                // [b][h][d][f]
__device__ float g_r[(size_t)Bc * Hc * Nn * DFc];        // [b][h][n][d]
__device__ float g_h[(size_t)Bc * Nn * Hc * Ec];         // hcat layout [b][n][h][f]

// ---------------- zero init ----------------
__global__ void zero_kernel(float* p, int n) {
    int i = blockIdx.x * blockDim.x + threadIdx.x;
    if (i < n) p[i] = 0.0f;
}

__device__ __forceinline__ float tanh_fast(float x) {
    float y;
    asm("tanh.approx.f32 %0, %1;" : "=f"(y) : "f"(x));
    return y;
}

// ---------------- fp16 helpers ----------------
__device__ __forceinline__ void mma_f16(float c[4], const unsigned a[4], const unsigned b[2]) {
    asm volatile(
        "mma.sync.aligned.m16n8k16.row.col.f32.f16.f16.f32 "
        "{%0,%1,%2,%3}, {%4,%5,%6,%7}, {%8,%9}, {%0,%1,%2,%3};"
        : "+f"(c[0]), "+f"(c[1]), "+f"(c[2]), "+f"(c[3])
        : "r"(a[0]), "r"(a[1]), "r"(a[2]), "r"(a[3]), "r"(b[0]), "r"(b[1]));
}

__device__ __forceinline__ unsigned pack2(float e0, float e1) {
    __half2 h = __floats2half2_rn(e0, e1);
    return *reinterpret_cast<unsigned*>(&h);
}

__device__ __forceinline__ void split2(float e0, float e1, unsigned& hw, unsigned& lw) {
    __half2 h = __floats2half2_rn(e0, e1);
    float2 hf = __half22float2(h);
    __half2 l = __floats2half2_rn(e0 - hf.x, e1 - hf.y);
    hw = *reinterpret_cast<unsigned*>(&h);
    lw = *reinterpret_cast<unsigned*>(&l);
}

// ================= unified 3-term fp16 tensor GEMM =================
// C[M,N=128] = act( sum_k A[m,k] B[n,k] + bias[n] )
// A element: Ab[m*a_sm + k*a_sk], B element: Bb[n*b_sn + k*b_sk]
// grid = (M/128, nbatch, ksplit). ksplit>1 -> atomicAdd epilogue (no bias/act).
// CTA tile 128x128, K chunks of 32 (2 x k16). 8 warps of m32 x n64.
// Operands pre-split to fp16 hi/lo half2 pairs along k (R10-validated layout).
__global__ __launch_bounds__(256, 1) void f16_gemm(
    const float* __restrict__ A, long a_sb, int a_div, int a_sm, int a_sk,
    const float* __restrict__ Bm, long b_sb, int b_mod, int b_sn, int b_sk,
    const float* __restrict__ bias, int bias_sb,
    float* __restrict__ C, long c_sb,
    int K, int ksplit, int act)
{
    // word = half2 (2 k-values). 32-k tile = 16 words/row, stride 20 (conflict-free frags)
    __shared__ unsigned AH[128 * 20];
    __shared__ unsigned AL[128 * 20];
    __shared__ unsigned BH[128 * 20];
    __shared__ unsigned BL[128 * 20];

    int by = blockIdx.y;
    int m0 = blockIdx.x * 128;
    const float* Ab = A + (long)(by / a_div) * a_sb + (long)m0 * a_sm;
    const float* Bb = Bm + (long)(by % b_mod) * b_sb;
    float* Cb = C + (long)by * c_sb + (long)m0 * 128;

    int Kper = K / ksplit;
    int k0base = blockIdx.z * Kper;

    int t = threadIdx.x;
    int warp = t >> 5;
    int lane = t & 31;
    int g = lane >> 2;
    int q = lane & 3;
    int wm = warp >> 1;       // 0..3 -> m offset wm*32
    int wn = warp & 1;        // 0..1 -> n offset wn*64

    float acc[2][8][4];
#pragma unroll
    for (int mt = 0; mt < 2; mt++)
#pragma unroll
        for (int nt = 0; nt < 8; nt++)
#pragma unroll
            for (int c = 0; c < 4; c++) acc[mt][nt][c] = 0.0f;

    for (int kc0 = 0; kc0 < Kper; kc0 += 32) {
        int k0 = k0base + kc0;
        __syncthreads();
        // ---- load + split A tile [128 m][32 k] ----
        if (a_sk == 1) {
            int row = t >> 1;
            int cf = (t & 1) * 16;       // float base 0/16
            const float* src = Ab + (long)row * a_sm + k0 + cf;
            float4 v0 = *(const float4*)(src);
            float4 v1 = *(const float4*)(src + 4);
            float4 v2 = *(const float4*)(src + 8);
            float4 v3 = *(const float4*)(src + 12);
            int wi = row * 20 + cf / 2;
            unsigned hw, lw;
            split2(v0.x, v0.y, hw, lw); AH[wi + 0] = hw; AL[wi + 0] = lw;
            split2(v0.z, v0.w, hw, lw); AH[wi + 1] = hw; AL[wi + 1] = lw;
            split2(v1.x, v1.y, hw, lw); AH[wi + 2] = hw; AL[wi + 2] = lw;
            split2(v1.z, v1.w, hw, lw); AH[wi + 3] = hw; AL[wi + 3] = lw;
            split2(v2.x, v2.y, hw, lw); AH[wi + 4] = hw; AL[wi + 4] = lw;
            split2(v2.z, v2.w, hw, lw); AH[wi + 5] = hw; AL[wi + 5] = lw;
            split2(v3.x, v3.y, hw, lw); AH[wi + 6] = hw; AL[wi + 6] = lw;
            split2(v3.z, v3.w, hw, lw); AH[wi + 7] = hw; AL[wi + 7] = lw;
        } else {
            int row = t & 127;
            int kb = (t >> 7) * 16;      // float base 0/16
#pragma unroll
            for (int e = 0; e < 8; e++) {
                float e0 = Ab[(long)row * a_sm + (long)(k0 + kb + 2 * e) * a_sk];
                float e1 = Ab[(long)row * a_sm + (long)(k0 + kb + 2 * e + 1) * a_sk];
                unsigned hw, lw;
                split2(e0, e1, hw, lw);
                int wi = row * 20 + kb / 2 + e;
                AH[wi] = hw; AL[wi] = lw;
            }
        }
        // ---- load + split B tile [128 n][32 k] ----
        if (b_sk == 1) {
            int row = t >> 1;
            int cf = (t & 1) * 16;
            const float* src = Bb + (long)row * b_sn + k0 + cf;
            float4 v0 = *(const float4*)(src);
            float4 v1 = *(const float4*)(src + 4);
            float4 v2 = *(const float4*)(src + 8);
            float4 v3 = *(const float4*)(src + 12);
            int wi = row * 20 + cf / 2;
            unsigned hw, lw;
            split2(v0.x, v0.y, hw, lw); BH[wi + 0] = hw; BL[wi + 0] = lw;
            split2(v0.z, v0.w, hw, lw); BH[wi + 1] = hw; BL[wi + 1] = lw;
            split2(v1.x, v1.y, hw, lw); BH[wi + 2] = hw; BL[wi + 2] = lw;
            split2(v1.z, v1.w, hw, lw); BH[wi + 3] = hw; BL[wi + 3] = lw;
            split2(v2.x, v2.y, hw, lw); BH[wi + 4] = hw; BL[wi + 4] = lw;
            split2(v2.z, v2.w, hw, lw); BH[wi + 5] = hw; BL[wi + 5] = lw;
            split2(v3.x, v3.y, hw, lw); BH[wi + 6] = hw; BL[wi + 6] = lw;
            split2(v3.z, v3.w, hw, lw); BH[wi + 7] = hw; BL[wi + 7] = lw;
        } else {
            int row = t & 127;
            int kb = (t >> 7) * 16;
#pragma unroll
            for (int e = 0; e < 8; e++) {
                float e0 = Bb[(long)row * b_sn + (long)(k0 + kb + 2 * e) * b_sk];
                float e1 = Bb[(long)row * b_sn + (long)(k0 + kb + 2 * e + 1) * b_sk];
                unsigned hw, lw;
                split2(e0, e1, hw, lw);
                int wi = row * 20 + kb / 2 + e;
                BH[wi] = hw; BL[wi] = lw;
            }
        }
        __syncthreads();

        // ---- compute: 2 x k16 chunks, 3 terms (hh, hl, lh) ----
#pragma unroll
        for (int kc = 0; kc < 2; kc++) {
            int kw = kc * 8;
            unsigned ah[2][4], al[2][4];
#pragma unroll
            for (int mt = 0; mt < 2; mt++) {
                int r0 = (wm * 32 + mt * 16 + g) * 20 + kw + q;
                int r1 = r0 + 8 * 20;
                ah[mt][0] = AH[r0];     ah[mt][1] = AH[r1];
                ah[mt][2] = AH[r0 + 4]; ah[mt][3] = AH[r1 + 4];
                al[mt][0] = AL[r0];     al[mt][1] = AL[r1];
                al[mt][2] = AL[r0 + 4]; al[mt][3] = AL[r1 + 4];
            }
            unsigned bh[8][2], bl[8][2];
#pragma unroll
            for (int nt = 0; nt < 8; nt++) {
                int pb = (wn * 64 + nt * 8 + g) * 20 + kw + q;
                bh[nt][0] = BH[pb]; bh[nt][1] = BH[pb + 4];
                bl[nt][0] = BL[pb]; bl[nt][1] = BL[pb + 4];
            }
#pragma unroll
            for (int mt = 0; mt < 2; mt++)
#pragma unroll
                for (int nt = 0; nt < 8; nt++) {
                    mma_f16(acc[mt][nt], ah[mt], bh[nt]);
                    mma_f16(acc[mt][nt], ah[mt], bl[nt]);
                    mma_f16(acc[mt][nt], al[mt], bh[nt]);
                }
        }
    }

    // ---- epilogue ----
    if (ksplit > 1) {
#pragma unroll
        for (int mt = 0; mt < 2; mt++)
#pragma unroll
            for (int nt = 0; nt < 8; nt++) {
                int mr = wm * 32 + mt * 16 + g;
                int nc = wn * 64 + nt * 8 + 2 * q;
                atomicAdd(&Cb[(long)mr * 128 + nc], acc[mt][nt][0]);
                atomicAdd(&Cb[(long)mr * 128 + nc + 1], acc[mt][nt][1]);
                atomicAdd(&Cb[(long)(mr + 8) * 128 + nc], acc[mt][nt][2]);
                atomicAdd(&Cb[(long)(mr + 8) * 128 + nc + 1], acc[mt][nt][3]);
            }
    } else {
        const float* bp = bias ? (bias + (long)(by % b_mod) * bias_sb) : nullptr;
#pragma unroll
        for (int mt = 0; mt < 2; mt++)
#pragma unroll
            for (int nt = 0; nt < 8; nt++) {
                int mr = wm * 32 + mt * 16 + g;
                int nc = wn * 64 + nt * 8 + 2 * q;
                float b0 = bp ? bp[nc] : 0.0f;
                float b1 = bp ? bp[nc + 1] : 0.0f;
                float o00 = acc[mt][nt][0] + b0, o01 = acc[mt][nt][1] + b1;
                float o10 = acc[mt][nt][2] + b0, o11 = acc[mt][nt][3] + b1;
                if (act == 1) {
                    o00 = fmaxf(o00, 0.0f); o01 = fmaxf(o01, 0.0f);
                    o10 = fmaxf(o10, 0.0f); o11 = fmaxf(o11, 0.0f);
                }
                *(float2*)&Cb[(long)mr * 128 + nc] = make_float2(o00, o01);
                *(float2*)&Cb[(long)(mr + 8) * 128 + nc] = make_float2(o10, o11);
            }
    }
}

// ================= full fp16-split fused attention (R10 + v_hi-only GEMM2) ====
// h = tanh( (r x^T)/sqrt(E) ) v   per (b,h)
// Block: 128 m-rows, p-tiles of 64, 512 threads (16 warps).
// smem words. Row strides: 128 k -> 68 words; 64 p-pairs -> 36.
//   RHS [128][68] @ 0        RLS @ 8704
//   XHS [64][68]  @ 17408    XLS @ 21760
//   SSH [128][36] @ 26112
//   VHS [32][136] @ 30720
#define A7_RHS 0
#define A7_RLS 8704
#define A7_XHS 17408
#define A7_XLS 21760
#define A7_SSH 26112
#define A7_VHS 30720
#define A7_WORDS (30720 + 4352)

__global__ __launch_bounds__(512, 1) void attn_f16v3_kernel(
    const float* __restrict__ r, const float* __restrict__ x,
    const float* __restrict__ v, float* __restrict__ hcat)
{
    extern __shared__ unsigned smw[];
    unsigned* RHS = smw + A7_RHS;   // [m][kw] stride 68
    unsigned* RLS = smw + A7_RLS;
    unsigned* XHS = smw + A7_XHS;   // [p][kw] stride 68
    unsigned* XLS = smw + A7_XLS;
    unsigned* SSH = smw + A7_SSH;   // [m][p-pair] stride 36
    unsigned* VHS = smw + A7_VHS;   // [p-pair][f] stride 136

    const float rscale = 0.015625f;               // 2^-6
    const float inv_scale = 5.656854249492380f;   // 64 / sqrt(128)

    int by = blockIdx.y;
    int b = by >> 2;
    int h = by & 3;
    int m0 = blockIdx.x * 128;

    const float* rb = r + (long)by * Nn * DFc;
    const float* xb = x + (long)b * Nn * DFc;
    const float* vb = v + (long)by * Nn * Ec;

    int t = threadIdx.x;
    int warp = t >> 5;
    int lane = t & 31;
    int g = lane >> 2;
    int q = lane & 3;

    int wm = warp >> 2;
    int wq = warp & 3;
    int mrb = wm * 32;

    // ---- load + split r tile [128 m][128 k] (scaled), stride 68 ----
    {
        int row = t >> 2;
        int cw = (t & 3) * 16;
#pragma unroll
        for (int j = 0; j < 8; j++) {
            float4 rv = *(const float4*)(rb + (long)(m0 + row) * DFc + cw * 2 + j * 4);
            unsigned h0, l0, h1, l1;
            split2(rv.x * rscale, rv.y * rscale, h0, l0);
            split2(rv.z * rscale, rv.w * rscale, h1, l1);
            int wi = row * 68 + cw + j * 2;
            RHS[wi] = h0; RHS[wi + 1] = h1;
            RLS[wi] = l0; RLS[wi + 1] = l1;
        }
    }

    float hacc[2][4][4];
#pragma unroll
    for (int mt = 0; mt < 2; mt++)
#pragma unroll
        for (int nt = 0; nt < 4; nt++)
#pragma unroll
            for (int c = 0; c < 4; c++) hacc[mt][nt][c] = 0.0f;

    for (int pt = 0; pt < Nn / 64; pt++) {
        int p0 = pt * 64;
        __syncthreads();

        // ---- load + split x tile [64 p][128 k], stride 68 ----
        {
            int row = t >> 3;
            int cw = (t & 7) * 8;
#pragma unroll
            for (int j = 0; j < 4; j++) {
                float4 xv = *(const float4*)(xb + (long)(p0 + row) * DFc + cw * 2 + j * 4);
                unsigned h0, l0, h1, l1;
                split2(xv.x, xv.y, h0, l0);
                split2(xv.z, xv.w, h1, l1);
                int wi = row * 68 + cw + j * 2;
                XHS[wi] = h0; XHS[wi + 1] = h1;
                XLS[wi] = l0; XLS[wi + 1] = l1;
            }
        }
        // ---- load v tile [64 p][128 f] -> fp16 hi only, pairs along p ----
        {
            int p2 = t >> 4;
            int fc = (t & 15) * 8;
            const float* v0p = vb + (long)(p0 + 2 * p2) * Ec + fc;
            const float* v1p = v0p + Ec;
            float4 a0 = *(const float4*)(v0p);
            float4 a1 = *(const float4*)(v0p + 4);
            float4 c0 = *(const float4*)(v1p);
            float4 c1 = *(const float4*)(v1p + 4);
            int wbase = p2 * 136 + fc;
            *(uint4*)&VHS[wbase] = make_uint4(
                pack2(a0.x, c0.x), pack2(a0.y, c0.y), pack2(a0.z, c0.z), pack2(a0.w, c0.w));
            *(uint4*)&VHS[wbase + 4] = make_uint4(
                pack2(a1.x, c1.x), pack2(a1.y, c1.y), pack2(a1.z, c1.z), pack2(a1.w, c1.w));
        }
        __syncthreads();

        // ---- S-gemm: 3-term fp16 m16n8k16, warp m32 x p16 ----
        float sacc[2][2][4];
#pragma unroll
        for (int mt = 0; mt < 2; mt++)
#pragma unroll
            for (int nt = 0; nt < 2; nt++)
#pragma unroll
                for (int c = 0; c < 4; c++) sacc[mt][nt][c] = 0.0f;

#pragma unroll
        for (int kc = 0; kc < 8; kc++) {
            int kw = kc * 8;
            unsigned ah[2][4], al[2][4];
#pragma unroll
            for (int mt = 0; mt < 2; mt++) {
                int r0 = (mrb + mt * 16 + g) * 68 + kw + q;
                int r1 = r0 + 8 * 68;
                ah[mt][0] = RHS[r0];     ah[mt][1] = RHS[r1];
                ah[mt][2] = RHS[r0 + 4]; ah[mt][3] = RHS[r1 + 4];
                al[mt][0] = RLS[r0];     al[mt][1] = RLS[r1];
                al[mt][2] = RLS[r0 + 4]; al[mt][3] = RLS[r1 + 4];
            }
            unsigned bh[2][2], bl[2][2];
#pragma unroll
            for (int nt = 0; nt < 2; nt++) {
                int pb = (wq * 16 + nt * 8 + g) * 68 + kw + q;
                bh[nt][0] = XHS[pb]; bh[nt][1] = XHS[pb + 4];
                bl[nt][0] = XLS[pb]; bl[nt][1] = XLS[pb + 4];
            }
#pragma unroll
            for (int mt = 0; mt < 2; mt++)
#pragma unroll
                for (int nt = 0; nt < 2; nt++) {
                    mma_f16(sacc[mt][nt], ah[mt], bh[nt]);
                    mma_f16(sacc[mt][nt], ah[mt], bl[nt]);
                    mma_f16(sacc[mt][nt], al[mt], bh[nt]);
                }
        }

        // ---- tanh epilogue -> SSH (attn as fp16 half2, pairs along p) ----
#pragma unroll
        for (int mt = 0; mt < 2; mt++)
#pragma unroll
            for (int nt = 0; nt < 2; nt++) {
                int row0 = mrb + mt * 16 + g;
                int wcol = wq * 8 + nt * 4 + q;
                float t0 = tanh_fast(sacc[mt][nt][0] * inv_scale);
                float t1 = tanh_fast(sacc[mt][nt][1] * inv_scale);
                float t2 = tanh_fast(sacc[mt][nt][2] * inv_scale);
                float t3 = tanh_fast(sacc[mt][nt][3] * inv_scale);
                SSH[row0 * 36 + wcol] = pack2(t0, t1);
                SSH[(row0 + 8) * 36 + wcol] = pack2(t2, t3);
            }
        __syncthreads();

        // ---- GEMM2: m16n8k16 f16, warp m32 x f32, attn x v_hi ----
#pragma unroll
        for (int pc = 0; pc < 4; pc++) {
            int pw = pc * 8;
            unsigned af[2][4];
#pragma unroll
            for (int mt = 0; mt < 2; mt++) {
                int s0 = (mrb + mt * 16 + g) * 36 + pw + q;
                int s1 = s0 + 8 * 36;
                af[mt][0] = SSH[s0];
                af[mt][1] = SSH[s1];
                af[mt][2] = SSH[s0 + 4];
                af[mt][3] = SSH[s1 + 4];
            }
#pragma unroll
            for (int nt = 0; nt < 4; nt++) {
                int fc = wq * 32 + nt * 8 + g;
                unsigned bh2[2];
                bh2[0] = VHS[(pw + q) * 136 + fc];
                bh2[1] = VHS[(pw + q + 4) * 136 + fc];
#pragma unroll
                for (int mt = 0; mt < 2; mt++)
                    mma_f16(hacc[mt][nt], af[mt], bh2);
            }
        }
    }

    // ---- write h into hcat [b][n][h][f] ----
#pragma unroll
    for (int mt = 0; mt < 2; mt++)
#pragma unroll
        for (int nt = 0; nt < 4; nt++) {
            int mrow = m0 + mrb + mt * 16 + g;
            int fc = wq * 32 + nt * 8 + 2 * q;
            float* hp0 = hcat + (((long)b * Nn + mrow) * Hc + h) * Ec + fc;
            float* hp1 = hcat + (((long)b * Nn + mrow + 8) * Hc + h) * Ec + fc;
            *(float2*)hp0 = make_float2(hacc[mt][nt][0], hacc[mt][nt][1]);
            *(float2*)hp1 = make_float2(hacc[mt][nt][2], hacc[mt][nt][3]);
        }
}

// ---------------- launch ----------------
extern "C" void kernel_launch(void* const* d_in, const int* in_sizes, int n_in,
                              void* d_out, int out_size) {
    const float* x      = (const float*)d_in[0];
    const float* emb1_W = (const float*)d_in[1];
    const float* emb1_b = (const float*)d_in[2];
    const float* wq_W   = (const float*)d_in[3];
    const float* wq_b   = (const float*)d_in[4];
    const float* wv_W   = (const float*)d_in[7];
    const float* wv_b   = (const float*)d_in[8];
    const float* emb2_W = (const float*)d_in[9];
    const float* emb2_b = (const float*)d_in[10];
    float* out = (float*)d_out;

    float *gg, *gemb, *gq, *gv, *gu, *gr, *gh;
    cudaGetSymbolAddress((void**)&gg, g_g);
    cudaGetSymbolAddress((void**)&gemb, g_emb);
    cudaGetSymbolAddress((void**)&gq, g_q);
    cudaGetSymbolAddress((void**)&gv, g_v);
    cudaGetSymbolAddress((void**)&gu, g_u);
    cudaGetSymbolAddress((void**)&gr, g_r);
    cudaGetSymbolAddress((void**)&gh, g_h);

    static int smem_set = 0;
    if (!smem_set) {
        cudaFuncSetAttribute(attn_f16v3_kernel, cudaFuncAttributeMaxDynamicSharedMemorySize,
                             A7_WORDS * sizeof(unsigned));
        smem_set = 1;
    }

    // zero split-K accumulators
    zero_kernel<<<(Bc * Ec * DFc + 255) / 256, 256>>>(gg, Bc * Ec * DFc);
    zero_kernel<<<(Bc * Hc * DFc * Ec + 255) / 256, 256>>>(gu, Bc * Hc * DFc * Ec);

    // stage 1: g[b,e,d] = sum_m W1[e,m] x[b,m,d]   (split-K 8, atomic)
    f16_gemm<<<dim3(1, Bc, 8), 256>>>(emb1_W, 0, Bc, Nn, 1,
                                      x, (long)Nn * DFc, Bc, 1, DFc,
                                      nullptr, 0,
                                      gg, (long)Ec * DFc, Nn, 8, 0);

    // stage 2: emb[b,n,e] = sum_d x[b,n,d] g[b,e,d] + emb1_b[e]
    f16_gemm<<<dim3(16, Bc, 1), 256>>>(x, (long)Nn * DFc, 1, DFc, 1,
                                       gg, (long)Ec * DFc, Bc, DFc, 1,
                                       emb1_b, 0,
                                       gemb, (long)Nn * Ec, DFc, 1, 0);

    // stage 3: q, v projections per (b,h)
    f16_gemm<<<dim3(16, Bc * Hc, 1), 256>>>(gemb, (long)Nn * Ec, Hc, Ec, 1,
                                            wq_W, (long)Ec * Ec, Hc, Ec, 1,
                                            wq_b, Ec,
                                            gq, (long)Nn * Ec, Ec, 1, 0);
    f16_gemm<<<dim3(16, Bc * Hc, 1), 256>>>(gemb, (long)Nn * Ec, Hc, Ec, 1,
                                            wv_W, (long)Ec * Ec, Hc, Ec, 1,
                                            wv_b, Ec,
                                            gv, (long)Nn * Ec, Ec, 1, 0);

    // stage 4: u[b,h,d,f] = sum_n x[b,n,d] v[b,h,n,f]   (split-K 8, atomic)
    f16_gemm<<<dim3(1, Bc * Hc, 8), 256>>>(x, (long)Nn * DFc, Hc, 1, DFc,
                                           gv, (long)Nn * Ec, Bc * Hc, 1, Ec,
                                           nullptr, 0,
                                           gu, (long)DFc * Ec, Nn, 8, 0);

    // stage 5: r[b,h,n,d] = sum_f q[b,h,n,f] u[b,h,d,f]
    f16_gemm<<<dim3(16, Bc * Hc, 1), 256>>>(gq, (long)Nn * Ec, 1, Ec, 1,
                                            gu, (long)DFc * Ec, Bc * Hc, Ec, 1,
                                            nullptr, 0,
                                            gr, (long)Nn * DFc, Ec, 1, 0);

    // stage 6: fused attention (full fp16 split, v_hi-only GEMM2)
    attn_f16v3_kernel<<<dim3(Nn / 128, Bc * Hc), 512, A7_WORDS * sizeof(unsigned)>>>(
        gr, x, gv, gh);

    // stage 7: out = relu(hcat @ emb2_W^T + emb2_b)
    f16_gemm<<<dim3(16, Bc, 1), 256>>>(gh, (long)Nn * Hc * Ec, 1, Hc * Ec, 1,
                                       emb2_W, 0, 1, Hc * Ec, 1,
                                       emb2_b, 0,
                                       out, (long)Nn * Ec, Hc * Ec, 1, 1);
}

// round 14
// speedup vs baseline: 3.0147x; 1.0116x over previous
#include <cuda_runtime.h>
#include <cuda_fp16.h>
#include <math.h>

#define Bc 8
#define Nn 2048
#define DFc 128
#define Ec 128
#define Hc 4

// ---------------- scratch (static device arrays; no allocation) ----------------
__device__ float g_g[Bc * Ec * DFc];                     // [b][e][d]
__device__ float g_emb[Bc * Nn * Ec];                    // [b][n][e]
__device__ float g_q[(size_t)Bc * Hc * Nn * Ec];         // [b][h][n][f]
__device__ float g_v[(size_t)Bc * Hc * Nn * Ec];         // [b][h][n][f]
__device__ float g_u[Bc * Hc * DFc * Ec];                // [b][h][d][f]
__device__ float g_r[(size_t)Bc * Hc * Nn * DFc];        // [b][h][n][d]
__device__ float g_h[(size_t)Bc * Nn * Hc * Ec];         // hcat layout [b][n][h][f]

// ---------------- zero init ----------------
__global__ void zero_kernel(float* p, int n) {
    int i = blockIdx.x * blockDim.x + threadIdx.x;
    if (i < n) p[i] = 0.0f;
}

__device__ __forceinline__ float tanh_fast(float x) {
    float y;
    asm("tanh.approx.f32 %0, %1;" : "=f"(y) : "f"(x));
    return y;
}

// ---------------- fp16 helpers ----------------
__device__ __forceinline__ void mma_f16(float c[4], const unsigned a[4], const unsigned b[2]) {
    asm volatile(
        "mma.sync.aligned.m16n8k16.row.col.f32.f16.f16.f32 "
        "{%0,%1,%2,%3}, {%4,%5,%6,%7}, {%8,%9}, {%0,%1,%2,%3};"
        : "+f"(c[0]), "+f"(c[1]), "+f"(c[2]), "+f"(c[3])
        : "r"(a[0]), "r"(a[1]), "r"(a[2]), "r"(a[3]), "r"(b[0]), "r"(b[1]));
}

__device__ __forceinline__ unsigned pack2(float e0, float e1) {
    __half2 h = __floats2half2_rn(e0, e1);
    return *reinterpret_cast<unsigned*>(&h);
}

__device__ __forceinline__ void split2(float e0, float e1, unsigned& hw, unsigned& lw) {
    __half2 h = __floats2half2_rn(e0, e1);
    float2 hf = __half22float2(h);
    __half2 l = __floats2half2_rn(e0 - hf.x, e1 - hf.y);
    hw = *reinterpret_cast<unsigned*>(&h);
    lw = *reinterpret_cast<unsigned*>(&l);
}

// ================= unified 3-term fp16 tensor GEMM (unchanged from R13) =================
__global__ __launch_bounds__(256, 1) void f16_gemm(
    const float* __restrict__ A, long a_sb, int a_div, int a_sm, int a_sk,
    const float* __restrict__ Bm, long b_sb, int b_mod, int b_sn, int b_sk,
    const float* __restrict__ bias, int bias_sb,
    float* __restrict__ C, long c_sb,
    int K, int ksplit, int act)
{
    __shared__ unsigned AH[128 * 20];
    __shared__ unsigned AL[128 * 20];
    __shared__ unsigned BH[128 * 20];
    __shared__ unsigned BL[128 * 20];

    int by = blockIdx.y;
    int m0 = blockIdx.x * 128;
    const float* Ab = A + (long)(by / a_div) * a_sb + (long)m0 * a_sm;
    const float* Bb = Bm + (long)(by % b_mod) * b_sb;
    float* Cb = C + (long)by * c_sb + (long)m0 * 128;

    int Kper = K / ksplit;
    int k0base = blockIdx.z * Kper;

    int t = threadIdx.x;
    int warp = t >> 5;
    int lane = t & 31;
    int g = lane >> 2;
    int q = lane & 3;
    int wm = warp >> 1;
    int wn = warp & 1;

    float acc[2][8][4];
#pragma unroll
    for (int mt = 0; mt < 2; mt++)
#pragma unroll
        for (int nt = 0; nt < 8; nt++)
#pragma unroll
            for (int c = 0; c < 4; c++) acc[mt][nt][c] = 0.0f;

    for (int kc0 = 0; kc0 < Kper; kc0 += 32) {
        int k0 = k0base + kc0;
        __syncthreads();
        if (a_sk == 1) {
            int row = t >> 1;
            int cf = (t & 1) * 16;
            const float* src = Ab + (long)row * a_sm + k0 + cf;
            float4 v0 = *(const float4*)(src);
            float4 v1 = *(const float4*)(src + 4);
            float4 v2 = *(const float4*)(src + 8);
            float4 v3 = *(const float4*)(src + 12);
            int wi = row * 20 + cf / 2;
            unsigned hw, lw;
            split2(v0.x, v0.y, hw, lw); AH[wi + 0] = hw; AL[wi + 0] = lw;
            split2(v0.z, v0.w, hw, lw); AH[wi + 1] = hw; AL[wi + 1] = lw;
            split2(v1.x, v1.y, hw, lw); AH[wi + 2] = hw; AL[wi + 2] = lw;
            split2(v1.z, v1.w, hw, lw); AH[wi + 3] = hw; AL[wi + 3] = lw;
            split2(v2.x, v2.y, hw, lw); AH[wi + 4] = hw; AL[wi + 4] = lw;
            split2(v2.z, v2.w, hw, lw); AH[wi + 5] = hw; AL[wi + 5] = lw;
            split2(v3.x, v3.y, hw, lw); AH[wi + 6] = hw; AL[wi + 6] = lw;
            split2(v3.z, v3.w, hw, lw); AH[wi + 7] = hw; AL[wi + 7] = lw;
        } else {
            int row = t & 127;
            int kb = (t >> 7) * 16;
#pragma unroll
            for (int e = 0; e < 8; e++) {
                float e0 = Ab[(long)row * a_sm + (long)(k0 + kb + 2 * e) * a_sk];
                float e1 = Ab[(long)row * a_sm + (long)(k0 + kb + 2 * e + 1) * a_sk];
                unsigned hw, lw;
                split2(e0, e1, hw, lw);
                int wi = row * 20 + kb / 2 + e;
                AH[wi] = hw; AL[wi] = lw;
            }
        }
        if (b_sk == 1) {
            int row = t >> 1;
            int cf = (t & 1) * 16;
            const float* src = Bb + (long)row * b_sn + k0 + cf;
            float4 v0 = *(const float4*)(src);
            float4 v1 = *(const float4*)(src + 4);
            float4 v2 = *(const float4*)(src + 8);
            float4 v3 = *(const float4*)(src + 12);
            int wi = row * 20 + cf / 2;
            unsigned hw, lw;
            split2(v0.x, v0.y, hw, lw); BH[wi + 0] = hw; BL[wi + 0] = lw;
            split2(v0.z, v0.w, hw, lw); BH[wi + 1] = hw; BL[wi + 1] = lw;
            split2(v1.x, v1.y, hw, lw); BH[wi + 2] = hw; BL[wi + 2] = lw;
            split2(v1.z, v1.w, hw, lw); BH[wi + 3] = hw; BL[wi + 3] = lw;
            split2(v2.x, v2.y, hw, lw); BH[wi + 4] = hw; BL[wi + 4] = lw;
            split2(v2.z, v2.w, hw, lw); BH[wi + 5] = hw; BL[wi + 5] = lw;
            split2(v3.x, v3.y, hw, lw); BH[wi + 6] = hw; BL[wi + 6] = lw;
            split2(v3.z, v3.w, hw, lw); BH[wi + 7] = hw; BL[wi + 7] = lw;
        } else {
            int row = t & 127;
            int kb = (t >> 7) * 16;
#pragma unroll
            for (int e = 0; e < 8; e++) {
                float e0 = Bb[(long)row * b_sn + (long)(k0 + kb + 2 * e) * b_sk];
                float e1 = Bb[(long)row * b_sn + (long)(k0 + kb + 2 * e + 1) * b_sk];
                unsigned hw, lw;
                split2(e0, e1, hw, lw);
                int wi = row * 20 + kb / 2 + e;
                BH[wi] = hw; BL[wi] = lw;
            }
        }
        __syncthreads();

#pragma unroll
        for (int kc = 0; kc < 2; kc++) {
            int kw = kc * 8;
            unsigned ah[2][4], al[2][4];
#pragma unroll
            for (int mt = 0; mt < 2; mt++) {
                int r0 = (wm * 32 + mt * 16 + g) * 20 + kw + q;
                int r1 = r0 + 8 * 20;
                ah[mt][0] = AH[r0];     ah[mt][1] = AH[r1];
                ah[mt][2] = AH[r0 + 4]; ah[mt][3] = AH[r1 + 4];
                al[mt][0] = AL[r0];     al[mt][1] = AL[r1];
                al[mt][2] = AL[r0 + 4]; al[mt][3] = AL[r1 + 4];
            }
            unsigned bh[8][2], bl[8][2];
#pragma unroll
            for (int nt = 0; nt < 8; nt++) {
                int pb = (wn * 64 + nt * 8 + g) * 20 + kw + q;
                bh[nt][0] = BH[pb]; bh[nt][1] = BH[pb + 4];
                bl[nt][0] = BL[pb]; bl[nt][1] = BL[pb + 4];
            }
#pragma unroll
            for (int mt = 0; mt < 2; mt++)
#pragma unroll
                for (int nt = 0; nt < 8; nt++) {
                    mma_f16(acc[mt][nt], ah[mt], bh[nt]);
                    mma_f16(acc[mt][nt], ah[mt], bl[nt]);
                    mma_f16(acc[mt][nt], al[mt], bh[nt]);
                }
        }
    }

    if (ksplit > 1) {
#pragma unroll
        for (int mt = 0; mt < 2; mt++)
#pragma unroll
            for (int nt = 0; nt < 8; nt++) {
                int mr = wm * 32 + mt * 16 + g;
                int nc = wn * 64 + nt * 8 + 2 * q;
                atomicAdd(&Cb[(long)mr * 128 + nc], acc[mt][nt][0]);
                atomicAdd(&Cb[(long)mr * 128 + nc + 1], acc[mt][nt][1]);
                atomicAdd(&Cb[(long)(mr + 8) * 128 + nc], acc[mt][nt][2]);
                atomicAdd(&Cb[(long)(mr + 8) * 128 + nc + 1], acc[mt][nt][3]);
            }
    } else {
        const float* bp = bias ? (bias + (long)(by % b_mod) * bias_sb) : nullptr;
#pragma unroll
        for (int mt = 0; mt < 2; mt++)
#pragma unroll
            for (int nt = 0; nt < 8; nt++) {
                int mr = wm * 32 + mt * 16 + g;
                int nc = wn * 64 + nt * 8 + 2 * q;
                float b0 = bp ? bp[nc] : 0.0f;
                float b1 = bp ? bp[nc + 1] : 0.0f;
                float o00 = acc[mt][nt][0] + b0, o01 = acc[mt][nt][1] + b1;
                float o10 = acc[mt][nt][2] + b0, o11 = acc[mt][nt][3] + b1;
                if (act == 1) {
                    o00 = fmaxf(o00, 0.0f); o01 = fmaxf(o01, 0.0f);
                    o10 = fmaxf(o10, 0.0f); o11 = fmaxf(o11, 0.0f);
                }
                *(float2*)&Cb[(long)mr * 128 + nc] = make_float2(o00, o01);
                *(float2*)&Cb[(long)(mr + 8) * 128 + nc] = make_float2(o10, o11);
            }
    }
}

// ================= fp16 fused attention v4: double-buffered, 2 syncs/tile ====
// h = tanh( (r x^T)/sqrt(E) ) v   per (b,h)
// Block: 128 m-rows, p-tiles of 64, 512 threads (16 warps).
// Pipeline per tile: sync / S-gemm / tanh->SSH / sync / load(pt+1)->buf[nxt] / GEMM2(pt)
// so gmem loads overlap GEMM2 and one barrier is removed.
// smem words. Row strides: 128 k -> 68 words; 64 p-pairs -> 36; v 136.
//   RHS [128][68] @ 0        RLS @ 8704
//   X buffers (2): @ 17408 + buf*8704  (XH at +0 [64][68], XL at +4352)
//   V buffers (2): @ 34816 + buf*4352  (VH [32][136])
//   SSH [128][36] @ 43520
#define A8_RHS 0
#define A8_RLS 8704
#define A8_XB  17408
#define A8_VB  34816
#define A8_SSH 43520
#define A8_WORDS (43520 + 4608)

__global__ __launch_bounds__(512, 1) void attn_f16v4_kernel(
    const float* __restrict__ r, const float* __restrict__ x,
    const float* __restrict__ v, float* __restrict__ hcat)
{
    extern __shared__ unsigned smw[];
    unsigned* RHS = smw + A8_RHS;   // [m][kw] stride 68
    unsigned* RLS = smw + A8_RLS;
    unsigned* SSH = smw + A8_SSH;   // [m][p-pair] stride 36

    const float rscale = 0.015625f;               // 2^-6
    const float inv_scale = 5.656854249492380f;   // 64 / sqrt(128)

    int by = blockIdx.y;
    int b = by >> 2;
    int h = by & 3;
    int m0 = blockIdx.x * 128;

    const float* rb = r + (long)by * Nn * DFc;
    const float* xb = x + (long)b * Nn * DFc;
    const float* vb = v + (long)by * Nn * Ec;

    int t = threadIdx.x;
    int warp = t >> 5;
    int lane = t & 31;
    int g = lane >> 2;
    int q = lane & 3;

    int wm = warp >> 2;
    int wq = warp & 3;
    int mrb = wm * 32;

    // per-thread load coordinates (constant across tiles)
    int x_row = t >> 3;            // 0..63
    int x_cw  = (t & 7) * 8;       // word base 0..56
    int v_p2  = t >> 4;            // 0..31 (p-pair)
    int v_fc  = (t & 15) * 8;      // f base

    // ---- load + split r tile [128 m][128 k] (scaled), stride 68 ----
    {
        int row = t >> 2;
        int cw = (t & 3) * 16;
#pragma unroll
        for (int j = 0; j < 8; j++) {
            float4 rv = *(const float4*)(rb + (long)(m0 + row) * DFc + cw * 2 + j * 4);
            unsigned h0, l0, h1, l1;
            split2(rv.x * rscale, rv.y * rscale, h0, l0);
            split2(rv.z * rscale, rv.w * rscale, h1, l1);
            int wi = row * 68 + cw + j * 2;
            RHS[wi] = h0; RHS[wi + 1] = h1;
            RLS[wi] = l0; RLS[wi + 1] = l1;
        }
    }

    // ---- prologue: load tile 0 into buffer 0 ----
    {
        unsigned* XH = smw + A8_XB;
        unsigned* XL = XH + 4352;
        unsigned* VH = smw + A8_VB;
#pragma unroll
        for (int j = 0; j < 4; j++) {
            float4 xv = *(const float4*)(xb + (long)x_row * DFc + x_cw * 2 + j * 4);
            unsigned h0, l0, h1, l1;
            split2(xv.x, xv.y, h0, l0);
            split2(xv.z, xv.w, h1, l1);
            int wi = x_row * 68 + x_cw + j * 2;
            XH[wi] = h0; XH[wi + 1] = h1;
            XL[wi] = l0; XL[wi + 1] = l1;
        }
        const float* v0p = vb + (long)(2 * v_p2) * Ec + v_fc;
        const float* v1p = v0p + Ec;
        float4 a0 = *(const float4*)(v0p);
        float4 a1 = *(const float4*)(v0p + 4);
        float4 c0 = *(const float4*)(v1p);
        float4 c1 = *(const float4*)(v1p + 4);
        int wbase = v_p2 * 136 + v_fc;
        *(uint4*)&VH[wbase] = make_uint4(
            pack2(a0.x, c0.x), pack2(a0.y, c0.y), pack2(a0.z, c0.z), pack2(a0.w, c0.w));
        *(uint4*)&VH[wbase + 4] = make_uint4(
            pack2(a1.x, c1.x), pack2(a1.y, c1.y), pack2(a1.z, c1.z), pack2(a1.w, c1.w));
    }

    float hacc[2][4][4];
#pragma unroll
    for (int mt = 0; mt < 2; mt++)
#pragma unroll
        for (int nt = 0; nt < 4; nt++)
#pragma unroll
            for (int c = 0; c < 4; c++) hacc[mt][nt][c] = 0.0f;

    for (int pt = 0; pt < Nn / 64; pt++) {
        int cur = pt & 1;
        unsigned* XH = smw + A8_XB + cur * 8704;
        unsigned* XL = XH + 4352;
        unsigned* VH = smw + A8_VB + cur * 4352;

        __syncthreads();   // (a) buf[cur] ready; GEMM2(pt-1) done -> SSH free

        // ---- S-gemm: 3-term fp16 m16n8k16, warp m32 x p16 ----
        float sacc[2][2][4];
#pragma unroll
        for (int mt = 0; mt < 2; mt++)
#pragma unroll
            for (int nt = 0; nt < 2; nt++)
#pragma unroll
                for (int c = 0; c < 4; c++) sacc[mt][nt][c] = 0.0f;

#pragma unroll
        for (int kc = 0; kc < 8; kc++) {
            int kw = kc * 8;
            unsigned ah[2][4], al[2][4];
#pragma unroll
            for (int mt = 0; mt < 2; mt++) {
                int r0 = (mrb + mt * 16 + g) * 68 + kw + q;
                int r1 = r0 + 8 * 68;
                ah[mt][0] = RHS[r0];     ah[mt][1] = RHS[r1];
                ah[mt][2] = RHS[r0 + 4]; ah[mt][3] = RHS[r1 + 4];
                al[mt][0] = RLS[r0];     al[mt][1] = RLS[r1];
                al[mt][2] = RLS[r0 + 4]; al[mt][3] = RLS[r1 + 4];
            }
            unsigned bh[2][2], bl[2][2];
#pragma unroll
            for (int nt = 0; nt < 2; nt++) {
                int pb = (wq * 16 + nt * 8 + g) * 68 + kw + q;
                bh[nt][0] = XH[pb]; bh[nt][1] = XH[pb + 4];
                bl[nt][0] = XL[pb]; bl[nt][1] = XL[pb + 4];
            }
#pragma unroll
            for (int mt = 0; mt < 2; mt++)
#pragma unroll
                for (int nt = 0; nt < 2; nt++) {
                    mma_f16(sacc[mt][nt], ah[mt], bh[nt]);
                    mma_f16(sacc[mt][nt], ah[mt], bl[nt]);
                    mma_f16(sacc[mt][nt], al[mt], bh[nt]);
                }
        }

        // ---- tanh epilogue -> SSH ----
#pragma unroll
        for (int mt = 0; mt < 2; mt++)
#pragma unroll
            for (int nt = 0; nt < 2; nt++) {
                int row0 = mrb + mt * 16 + g;
                int wcol = wq * 8 + nt * 4 + q;
                float t0 = tanh_fast(sacc[mt][nt][0] * inv_scale);
                float t1 = tanh_fast(sacc[mt][nt][1] * inv_scale);
                float t2 = tanh_fast(sacc[mt][nt][2] * inv_scale);
                float t3 = tanh_fast(sacc[mt][nt][3] * inv_scale);
                SSH[row0 * 36 + wcol] = pack2(t0, t1);
                SSH[(row0 + 8) * 36 + wcol] = pack2(t2, t3);
            }
        __syncthreads();   // (b) SSH ready

        // ---- load tile pt+1 into buf[1-cur] (overlaps GEMM2 below) ----
        if (pt + 1 < Nn / 64) {
            int p0n = (pt + 1) * 64;
            unsigned* XHn = smw + A8_XB + (1 - cur) * 8704;
            unsigned* XLn = XHn + 4352;
            unsigned* VHn = smw + A8_VB + (1 - cur) * 4352;
#pragma unroll
            for (int j = 0; j < 4; j++) {
                float4 xv = *(const float4*)(xb + (long)(p0n + x_row) * DFc + x_cw * 2 + j * 4);
                unsigned h0, l0, h1, l1;
                split2(xv.x, xv.y, h0, l0);
                split2(xv.z, xv.w, h1, l1);
                int wi = x_row * 68 + x_cw + j * 2;
                XHn[wi] = h0; XHn[wi + 1] = h1;
                XLn[wi] = l0; XLn[wi + 1] = l1;
            }
            const float* v0p = vb + (long)(p0n + 2 * v_p2) * Ec + v_fc;
            const float* v1p = v0p + Ec;
            float4 a0 = *(const float4*)(v0p);
            float4 a1 = *(const float4*)(v0p + 4);
            float4 c0 = *(const float4*)(v1p);
            float4 c1 = *(const float4*)(v1p + 4);
            int wbase = v_p2 * 136 + v_fc;
            *(uint4*)&VHn[wbase] = make_uint4(
                pack2(a0.x, c0.x), pack2(a0.y, c0.y), pack2(a0.z, c0.z), pack2(a0.w, c0.w));
            *(uint4*)&VHn[wbase + 4] = make_uint4(
                pack2(a1.x, c1.x), pack2(a1.y, c1.y), pack2(a1.z, c1.z), pack2(a1.w, c1.w));
        }

        // ---- GEMM2: m16n8k16 f16, warp m32 x f32, attn x v_hi ----
#pragma unroll
        for (int pc = 0; pc < 4; pc++) {
            int pw = pc * 8;
            unsigned af[2][4];
#pragma unroll
            for (int mt = 0; mt < 2; mt++) {
                int s0 = (mrb + mt * 16 + g) * 36 + pw + q;
                int s1 = s0 + 8 * 36;
                af[mt][0] = SSH[s0];
                af[mt][1] = SSH[s1];
                af[mt][2] = SSH[s0 + 4];
                af[mt][3] = SSH[s1 + 4];
            }
#pragma unroll
            for (int nt = 0; nt < 4; nt++) {
                int fc = wq * 32 + nt * 8 + g;
                unsigned bh2[2];
                bh2[0] = VH[(pw + q) * 136 + fc];
                bh2[1] = VH[(pw + q + 4) * 136 + fc];
#pragma unroll
                for (int mt = 0; mt < 2; mt++)
                    mma_f16(hacc[mt][nt], af[mt], bh2);
            }
        }
    }

    // ---- write h into hcat [b][n][h][f] ----
#pragma unroll
    for (int mt = 0; mt < 2; mt++)
#pragma unroll
        for (int nt = 0; nt < 4; nt++) {
            int mrow = m0 + mrb + mt * 16 + g;
            int fc = wq * 32 + nt * 8 + 2 * q;
            float* hp0 = hcat + (((long)b * Nn + mrow) * Hc + h) * Ec + fc;
            float* hp1 = hcat + (((long)b * Nn + mrow + 8) * Hc + h) * Ec + fc;
            *(float2*)hp0 = make_float2(hacc[mt][nt][0], hacc[mt][nt][1]);
            *(float2*)hp1 = make_float2(hacc[mt][nt][2], hacc[mt][nt][3]);
        }
}

// ---------------- launch ----------------
extern "C" void kernel_launch(void* const* d_in, const int* in_sizes, int n_in,
                              void* d_out, int out_size) {
    const float* x      = (const float*)d_in[0];
    const float* emb1_W = (const float*)d_in[1];
    const float* emb1_b = (const float*)d_in[2];
    const float* wq_W   = (const float*)d_in[3];
    const float* wq_b   = (const float*)d_in[4];
    const float* wv_W   = (const float*)d_in[7];
    const float* wv_b   = (const float*)d_in[8];
    const float* emb2_W = (const float*)d_in[9];
    const float* emb2_b = (const float*)d_in[10];
    float* out = (float*)d_out;

    float *gg, *gemb, *gq, *gv, *gu, *gr, *gh;
    cudaGetSymbolAddress((void**)&gg, g_g);
    cudaGetSymbolAddress((void**)&gemb, g_emb);
    cudaGetSymbolAddress((void**)&gq, g_q);
    cudaGetSymbolAddress((void**)&gv, g_v);
    cudaGetSymbolAddress((void**)&gu, g_u);
    cudaGetSymbolAddress((void**)&gr, g_r);
    cudaGetSymbolAddress((void**)&gh, g_h);

    static int smem_set = 0;
    if (!smem_set) {
        cudaFuncSetAttribute(attn_f16v4_kernel, cudaFuncAttributeMaxDynamicSharedMemorySize,
                             A8_WORDS * sizeof(unsigned));
        smem_set = 1;
    }

    // zero split-K accumulators
    zero_kernel<<<(Bc * Ec * DFc + 255) / 256, 256>>>(gg, Bc * Ec * DFc);
    zero_kernel<<<(Bc * Hc * DFc * Ec + 255) / 256, 256>>>(gu, Bc * Hc * DFc * Ec);

    // stage 1: g[b,e,d] = sum_m W1[e,m] x[b,m,d]   (split-K 16, atomic)
    f16_gemm<<<dim3(1, Bc, 16), 256>>>(emb1_W, 0, Bc, Nn, 1,
                                       x, (long)Nn * DFc, Bc, 1, DFc,
                                       nullptr, 0,
                                       gg, (long)Ec * DFc, Nn, 16, 0);

    // stage 2: emb[b,n,e] = sum_d x[b,n,d] g[b,e,d] + emb1_b[e]
    f16_gemm<<<dim3(16, Bc, 1), 256>>>(x, (long)Nn * DFc, 1, DFc, 1,
                                       gg, (long)Ec * DFc, Bc, DFc, 1,
                                       emb1_b, 0,
                                       gemb, (long)Nn * Ec, DFc, 1, 0);

    // stage 3: q, v projections per (b,h)
    f16_gemm<<<dim3(16, Bc * Hc, 1), 256>>>(gemb, (long)Nn * Ec, Hc, Ec, 1,
                                            wq_W, (long)Ec * Ec, Hc, Ec, 1,
                                            wq_b, Ec,
                                            gq, (long)Nn * Ec, Ec, 1, 0);
    f16_gemm<<<dim3(16, Bc * Hc, 1), 256>>>(gemb, (long)Nn * Ec, Hc, Ec, 1,
                                            wv_W, (long)Ec * Ec, Hc, Ec, 1,
                                            wv_b, Ec,
                                            gv, (long)Nn * Ec, Ec, 1, 0);

    // stage 4: u[b,h,d,f] = sum_n x[b,n,d] v[b,h,n,f]   (split-K 16, atomic)
    f16_gemm<<<dim3(1, Bc * Hc, 16), 256>>>(x, (long)Nn * DFc, Hc, 1, DFc,
                                            gv, (long)Nn * Ec, Bc * Hc, 1, Ec,
                                            nullptr, 0,
                                            gu, (long)DFc * Ec, Nn, 16, 0);

    // stage 5: r[b,h,n,d] = sum_f q[b,h,n,f] u[b,h,d,f]
    f16_gemm<<<dim3(16, Bc * Hc, 1), 256>>>(gq, (long)Nn * Ec, 1, Ec, 1,
                                            gu, (long)DFc * Ec, Bc * Hc, Ec, 1,
                                            nullptr, 0,
                                            gr, (long)Nn * DFc, Ec, 1, 0);

    // stage 6: fused attention (double-buffered fp16)
    attn_f16v4_kernel<<<dim3(Nn / 128, Bc * Hc), 512, A8_WORDS * sizeof(unsigned)>>>(
        gr, x, gv, gh);

    // stage 7: out = relu(hcat @ emb2_W^T + emb2_b)
    f16_gemm<<<dim3(16, Bc, 1), 256>>>(gh, (long)Nn * Hc * Ec, 1, Hc * Ec, 1,
                                       emb2_W, 0, 1, Hc * Ec, 1,
                                       emb2_b, 0,
                                       out, (long)Nn * Ec, Hc * Ec, 1, 1);
}

// round 17
// speedup vs baseline: 3.0670x; 1.0173x over previous
#include <cuda_runtime.h>
#include <cuda_fp16.h>
#include <math.h>

#define Bc 8
#define Nn 2048
#define DFc 128
#define Ec 128
#define Hc 4

// ---------------- scratch (static device arrays; no allocation) ----------------
__device__ float g_g[Bc * Ec * DFc];                     // [b][e][d]
__device__ float g_emb[Bc * Nn * Ec];                    // [b][n][e]
__device__ float g_q[(size_t)Bc * Hc * Nn * Ec];         // [b][h][n][f]
__device__ float g_v[(size_t)Bc * Hc * Nn * Ec];         // [b][h][n][f]
__device__ float g_u[Bc * Hc * DFc * Ec];                // [b][h][d][f]
__device__ float g_r[(size_t)Bc * Hc * Nn * DFc];        // [b][h][n][d]
__device__ float g_h[(size_t)Bc * Nn * Hc * Ec];         // hcat layout [b][n][h][f]

// ---------------- zero init ----------------
__global__ void zero_kernel(float* p, int n) {
    int i = blockIdx.x * blockDim.x + threadIdx.x;
    if (i < n) p[i] = 0.0f;
}

__device__ __forceinline__ float tanh_fast(float x) {
    float y;
    asm("tanh.approx.f32 %0, %1;" : "=f"(y) : "f"(x));
    return y;
}

// ---------------- fp16 helpers ----------------
__device__ __forceinline__ void mma_f16(float c[4], const unsigned a[4], const unsigned b[2]) {
    asm volatile(
        "mma.sync.aligned.m16n8k16.row.col.f32.f16.f16.f32 "
        "{%0,%1,%2,%3}, {%4,%5,%6,%7}, {%8,%9}, {%0,%1,%2,%3};"
        : "+f"(c[0]), "+f"(c[1]), "+f"(c[2]), "+f"(c[3])
        : "r"(a[0]), "r"(a[1]), "r"(a[2]), "r"(a[3]), "r"(b[0]), "r"(b[1]));
}

__device__ __forceinline__ unsigned pack2(float e0, float e1) {
    __half2 h = __floats2half2_rn(e0, e1);
    return *reinterpret_cast<unsigned*>(&h);
}

__device__ __forceinline__ void split2(float e0, float e1, unsigned& hw, unsigned& lw) {
    __half2 h = __floats2half2_rn(e0, e1);
    float2 hf = __half22float2(h);
    __half2 l = __floats2half2_rn(e0 - hf.x, e1 - hf.y);
    hw = *reinterpret_cast<unsigned*>(&h);
    lw = *reinterpret_cast<unsigned*>(&l);
}

// ================= 3-term fp16 tensor GEMM v2: 512 threads, m32xn32 warp tiles ====
// C[M,N=128] = act( sum_k A[m,k] B[n,k] + bias[n] )
// grid = (M/128, nbatch, ksplit). ksplit>1 -> atomicAdd epilogue (no bias/act).
// CTA tile 128x128, K chunks of 32 (2 x k16). 16 warps of m32 x n32 (4/SMSP).
__global__ __launch_bounds__(512, 1) void f16_gemm(
    const float* __restrict__ A, long a_sb, int a_div, int a_sm, int a_sk,
    const float* __restrict__ Bm, long b_sb, int b_mod, int b_sn, int b_sk,
    const float* __restrict__ bias, int bias_sb,
    float* __restrict__ C, long c_sb,
    int K, int ksplit, int act)
{
    // word = half2 (2 k-values). 32-k tile = 16 words/row, stride 20
    __shared__ unsigned AH[128 * 20];
    __shared__ unsigned AL[128 * 20];
    __shared__ unsigned BH[128 * 20];
    __shared__ unsigned BL[128 * 20];

    int by = blockIdx.y;
    int m0 = blockIdx.x * 128;
    const float* Ab = A + (long)(by / a_div) * a_sb + (long)m0 * a_sm;
    const float* Bb = Bm + (long)(by % b_mod) * b_sb;
    float* Cb = C + (long)by * c_sb + (long)m0 * 128;

    int Kper = K / ksplit;
    int k0base = blockIdx.z * Kper;

    int t = threadIdx.x;
    int warp = t >> 5;
    int lane = t & 31;
    int g = lane >> 2;
    int q = lane & 3;
    int wm = warp >> 2;       // 0..3 -> m offset wm*32
    int wn = warp & 3;        // 0..3 -> n offset wn*32

    float acc[2][4][4];
#pragma unroll
    for (int mt = 0; mt < 2; mt++)
#pragma unroll
        for (int nt = 0; nt < 4; nt++)
#pragma unroll
            for (int c = 0; c < 4; c++) acc[mt][nt][c] = 0.0f;

    for (int kc0 = 0; kc0 < Kper; kc0 += 32) {
        int k0 = k0base + kc0;
        __syncthreads();
        // ---- load + split A tile [128 m][32 k] (512 threads, 4 words each) ----
        if (a_sk == 1) {
            int row = t >> 2;               // 0..127
            int cf = (t & 3) * 8;           // float base 0/8/16/24
            const float* src = Ab + (long)row * a_sm + k0 + cf;
            float4 v0 = *(const float4*)(src);
            float4 v1 = *(const float4*)(src + 4);
            int wi = row * 20 + cf / 2;
            unsigned hw, lw;
            split2(v0.x, v0.y, hw, lw); AH[wi + 0] = hw; AL[wi + 0] = lw;
            split2(v0.z, v0.w, hw, lw); AH[wi + 1] = hw; AL[wi + 1] = lw;
            split2(v1.x, v1.y, hw, lw); AH[wi + 2] = hw; AL[wi + 2] = lw;
            split2(v1.z, v1.w, hw, lw); AH[wi + 3] = hw; AL[wi + 3] = lw;
        } else {
            int row = t & 127;
            int kb = (t >> 7) * 8;          // float base 0/8/16/24
#pragma unroll
            for (int e = 0; e < 4; e++) {
                float e0 = Ab[(long)row * a_sm + (long)(k0 + kb + 2 * e) * a_sk];
                float e1 = Ab[(long)row * a_sm + (long)(k0 + kb + 2 * e + 1) * a_sk];
                unsigned hw, lw;
                split2(e0, e1, hw, lw);
                int wi = row * 20 + kb / 2 + e;
                AH[wi] = hw; AL[wi] = lw;
            }
        }
        // ---- load + split B tile [128 n][32 k] ----
        if (b_sk == 1) {
            int row = t >> 2;
            int cf = (t & 3) * 8;
            const float* src = Bb + (long)row * b_sn + k0 + cf;
            float4 v0 = *(const float4*)(src);
            float4 v1 = *(const float4*)(src + 4);
            int wi = row * 20 + cf / 2;
            unsigned hw, lw;
            split2(v0.x, v0.y, hw, lw); BH[wi + 0] = hw; BL[wi + 0] = lw;
            split2(v0.z, v0.w, hw, lw); BH[wi + 1] = hw; BL[wi + 1] = lw;
            split2(v1.x, v1.y, hw, lw); BH[wi + 2] = hw; BL[wi + 2] = lw;
            split2(v1.z, v1.w, hw, lw); BH[wi + 3] = hw; BL[wi + 3] = lw;
        } else {
            int row = t & 127;
            int kb = (t >> 7) * 8;
#pragma unroll
            for (int e = 0; e < 4; e++) {
                float e0 = Bb[(long)row * b_sn + (long)(k0 + kb + 2 * e) * b_sk];
                float e1 = Bb[(long)row * b_sn + (long)(k0 + kb + 2 * e + 1) * b_sk];
                unsigned hw, lw;
                split2(e0, e1, hw, lw);
                int wi = row * 20 + kb / 2 + e;
                BH[wi] = hw; BL[wi] = lw;
            }
        }
        __syncthreads();

        // ---- compute: 2 x k16 chunks, 3 terms (hh, hl, lh), warp m32 x n32 ----
#pragma unroll
        for (int kc = 0; kc < 2; kc++) {
            int kw = kc * 8;
            unsigned ah[2][4], al[2][4];
#pragma unroll
            for (int mt = 0; mt < 2; mt++) {
                int r0 = (wm * 32 + mt * 16 + g) * 20 + kw + q;
                int r1 = r0 + 8 * 20;
                ah[mt][0] = AH[r0];     ah[mt][1] = AH[r1];
                ah[mt][2] = AH[r0 + 4]; ah[mt][3] = AH[r1 + 4];
                al[mt][0] = AL[r0];     al[mt][1] = AL[r1];
                al[mt][2] = AL[r0 + 4]; al[mt][3] = AL[r1 + 4];
            }
            unsigned bh[4][2], bl[4][2];
#pragma unroll
            for (int nt = 0; nt < 4; nt++) {
                int pb = (wn * 32 + nt * 8 + g) * 20 + kw + q;
                bh[nt][0] = BH[pb]; bh[nt][1] = BH[pb + 4];
                bl[nt][0] = BL[pb]; bl[nt][1] = BL[pb + 4];
            }
#pragma unroll
            for (int mt = 0; mt < 2; mt++)
#pragma unroll
                for (int nt = 0; nt < 4; nt++) {
                    mma_f16(acc[mt][nt], ah[mt], bh[nt]);
                    mma_f16(acc[mt][nt], ah[mt], bl[nt]);
                    mma_f16(acc[mt][nt], al[mt], bh[nt]);
                }
        }
    }

    // ---- epilogue ----
    if (ksplit > 1) {
#pragma unroll
        for (int mt = 0; mt < 2; mt++)
#pragma unroll
            for (int nt = 0; nt < 4; nt++) {
                int mr = wm * 32 + mt * 16 + g;
                int nc = wn * 32 + nt * 8 + 2 * q;
                atomicAdd(&Cb[(long)mr * 128 + nc], acc[mt][nt][0]);
                atomicAdd(&Cb[(long)mr * 128 + nc + 1], acc[mt][nt][1]);
                atomicAdd(&Cb[(long)(mr + 8) * 128 + nc], acc[mt][nt][2]);
                atomicAdd(&Cb[(long)(mr + 8) * 128 + nc + 1], acc[mt][nt][3]);
            }
    } else {
        const float* bp = bias ? (bias + (long)(by % b_mod) * bias_sb) : nullptr;
#pragma unroll
        for (int mt = 0; mt < 2; mt++)
#pragma unroll
            for (int nt = 0; nt < 4; nt++) {
                int mr = wm * 32 + mt * 16 + g;
                int nc = wn * 32 + nt * 8 + 2 * q;
                float b0 = bp ? bp[nc] : 0.0f;
                float b1 = bp ? bp[nc + 1] : 0.0f;
                float o00 = acc[mt][nt][0] + b0, o01 = acc[mt][nt][1] + b1;
                float o10 = acc[mt][nt][2] + b0, o11 = acc[mt][nt][3] + b1;
                if (act == 1) {
                    o00 = fmaxf(o00, 0.0f); o01 = fmaxf(o01, 0.0f);
                    o10 = fmaxf(o10, 0.0f); o11 = fmaxf(o11, 0.0f);
                }
                *(float2*)&Cb[(long)mr * 128 + nc] = make_float2(o00, o01);
                *(float2*)&Cb[(long)(mr + 8) * 128 + nc] = make_float2(o10, o11);
            }
    }
}

// ================= fp16 fused attention v4 (unchanged from R14) ====
#define A8_RHS 0
#define A8_RLS 8704
#define A8_XB  17408
#define A8_VB  34816
#define A8_SSH 43520
#define A8_WORDS (43520 + 4608)

__global__ __launch_bounds__(512, 1) void attn_f16v4_kernel(
    const float* __restrict__ r, const float* __restrict__ x,
    const float* __restrict__ v, float* __restrict__ hcat)
{
    extern __shared__ unsigned smw[];
    unsigned* RHS = smw + A8_RHS;   // [m][kw] stride 68
    unsigned* RLS = smw + A8_RLS;
    unsigned* SSH = smw + A8_SSH;   // [m][p-pair] stride 36

    const float rscale = 0.015625f;               // 2^-6
    const float inv_scale = 5.656854249492380f;   // 64 / sqrt(128)

    int by = blockIdx.y;
    int b = by >> 2;
    int h = by & 3;
    int m0 = blockIdx.x * 128;

    const float* rb = r + (long)by * Nn * DFc;
    const float* xb = x + (long)b * Nn * DFc;
    const float* vb = v + (long)by * Nn * Ec;

    int t = threadIdx.x;
    int warp = t >> 5;
    int lane = t & 31;
    int g = lane >> 2;
    int q = lane & 3;

    int wm = warp >> 2;
    int wq = warp & 3;
    int mrb = wm * 32;

    int x_row = t >> 3;
    int x_cw  = (t & 7) * 8;
    int v_p2  = t >> 4;
    int v_fc  = (t & 15) * 8;

    // ---- load + split r tile [128 m][128 k] (scaled), stride 68 ----
    {
        int row = t >> 2;
        int cw = (t & 3) * 16;
#pragma unroll
        for (int j = 0; j < 8; j++) {
            float4 rv = *(const float4*)(rb + (long)(m0 + row) * DFc + cw * 2 + j * 4);
            unsigned h0, l0, h1, l1;
            split2(rv.x * rscale, rv.y * rscale, h0, l0);
            split2(rv.z * rscale, rv.w * rscale, h1, l1);
            int wi = row * 68 + cw + j * 2;
            RHS[wi] = h0; RHS[wi + 1] = h1;
            RLS[wi] = l0; RLS[wi + 1] = l1;
        }
    }

    // ---- prologue: load tile 0 into buffer 0 ----
    {
        unsigned* XH = smw + A8_XB;
        unsigned* XL = XH + 4352;
        unsigned* VH = smw + A8_VB;
#pragma unroll
        for (int j = 0; j < 4; j++) {
            float4 xv = *(const float4*)(xb + (long)x_row * DFc + x_cw * 2 + j * 4);
            unsigned h0, l0, h1, l1;
            split2(xv.x, xv.y, h0, l0);
            split2(xv.z, xv.w, h1, l1);
            int wi = x_row * 68 + x_cw + j * 2;
            XH[wi] = h0; XH[wi + 1] = h1;
            XL[wi] = l0; XL[wi + 1] = l1;
        }
        const float* v0p = vb + (long)(2 * v_p2) * Ec + v_fc;
        const float* v1p = v0p + Ec;
        float4 a0 = *(const float4*)(v0p);
        float4 a1 = *(const float4*)(v0p + 4);
        float4 c0 = *(const float4*)(v1p);
        float4 c1 = *(const float4*)(v1p + 4);
        int wbase = v_p2 * 136 + v_fc;
        *(uint4*)&VH[wbase] = make_uint4(
            pack2(a0.x, c0.x), pack2(a0.y, c0.y), pack2(a0.z, c0.z), pack2(a0.w, c0.w));
        *(uint4*)&VH[wbase + 4] = make_uint4(
            pack2(a1.x, c1.x), pack2(a1.y, c1.y), pack2(a1.z, c1.z), pack2(a1.w, c1.w));
    }

    float hacc[2][4][4];
#pragma unroll
    for (int mt = 0; mt < 2; mt++)
#pragma unroll
        for (int nt = 0; nt < 4; nt++)
#pragma unroll
            for (int c = 0; c < 4; c++) hacc[mt][nt][c] = 0.0f;

    for (int pt = 0; pt < Nn / 64; pt++) {
        int cur = pt & 1;
        unsigned* XH = smw + A8_XB + cur * 8704;
        unsigned* XL = XH + 4352;
        unsigned* VH = smw + A8_VB + cur * 4352;

        __syncthreads();

        // ---- S-gemm: 3-term fp16 m16n8k16, warp m32 x p16 ----
        float sacc[2][2][4];
#pragma unroll
        for (int mt = 0; mt < 2; mt++)
#pragma unroll
            for (int nt = 0; nt < 2; nt++)
#pragma unroll
                for (int c = 0; c < 4; c++) sacc[mt][nt][c] = 0.0f;

#pragma unroll
        for (int kc = 0; kc < 8; kc++) {
            int kw = kc * 8;
            unsigned ah[2][4], al[2][4];
#pragma unroll
            for (int mt = 0; mt < 2; mt++) {
                int r0 = (mrb + mt * 16 + g) * 68 + kw + q;
                int r1 = r0 + 8 * 68;
                ah[mt][0] = RHS[r0];     ah[mt][1] = RHS[r1];
                ah[mt][2] = RHS[r0 + 4]; ah[mt][3] = RHS[r1 + 4];
                al[mt][0] = RLS[r0];     al[mt][1] = RLS[r1];
                al[mt][2] = RLS[r0 + 4]; al[mt][3] = RLS[r1 + 4];
            }
            unsigned bh[2][2], bl[2][2];
#pragma unroll
            for (int nt = 0; nt < 2; nt++) {
                int pb = (wq * 16 + nt * 8 + g) * 68 + kw + q;
                bh[nt][0] = XH[pb]; bh[nt][1] = XH[pb + 4];
                bl[nt][0] = XL[pb]; bl[nt][1] = XL[pb + 4];
            }
#pragma unroll
            for (int mt = 0; mt < 2; mt++)
#pragma unroll
                for (int nt = 0; nt < 2; nt++) {
                    mma_f16(sacc[mt][nt], ah[mt], bh[nt]);
                    mma_f16(sacc[mt][nt], ah[mt], bl[nt]);
                    mma_f16(sacc[mt][nt], al[mt], bh[nt]);
                }
        }

        // ---- tanh epilogue -> SSH ----
#pragma unroll
        for (int mt = 0; mt < 2; mt++)
#pragma unroll
            for (int nt = 0; nt < 2; nt++) {
                int row0 = mrb + mt * 16 + g;
                int wcol = wq * 8 + nt * 4 + q;
                float t0 = tanh_fast(sacc[mt][nt][0] * inv_scale);
                float t1 = tanh_fast(sacc[mt][nt][1] * inv_scale);
                float t2 = tanh_fast(sacc[mt][nt][2] * inv_scale);
                float t3 = tanh_fast(sacc[mt][nt][3] * inv_scale);
                SSH[row0 * 36 + wcol] = pack2(t0, t1);
                SSH[(row0 + 8) * 36 + wcol] = pack2(t2, t3);
            }
        __syncthreads();

        // ---- load tile pt+1 into buf[1-cur] (overlaps GEMM2 below) ----
        if (pt + 1 < Nn / 64) {
            int p0n = (pt + 1) * 64;
            unsigned* XHn = smw + A8_XB + (1 - cur) * 8704;
            unsigned* XLn = XHn + 4352;
            unsigned* VHn = smw + A8_VB + (1 - cur) * 4352;
#pragma unroll
            for (int j = 0; j < 4; j++) {
                float4 xv = *(const float4*)(xb + (long)(p0n + x_row) * DFc + x_cw * 2 + j * 4);
                unsigned h0, l0, h1, l1;
                split2(xv.x, xv.y, h0, l0);
                split2(xv.z, xv.w, h1, l1);
                int wi = x_row * 68 + x_cw + j * 2;
                XHn[wi] = h0; XHn[wi + 1] = h1;
                XLn[wi] = l0; XLn[wi + 1] = l1;
            }
            const float* v0p = vb + (long)(p0n + 2 * v_p2) * Ec + v_fc;
            const float* v1p = v0p + Ec;
            float4 a0 = *(const float4*)(v0p);
            float4 a1 = *(const float4*)(v0p + 4);
            float4 c0 = *(const float4*)(v1p);
            float4 c1 = *(const float4*)(v1p + 4);
            int wbase = v_p2 * 136 + v_fc;
            *(uint4*)&VHn[wbase] = make_uint4(
                pack2(a0.x, c0.x), pack2(a0.y, c0.y), pack2(a0.z, c0.z), pack2(a0.w, c0.w));
            *(uint4*)&VHn[wbase + 4] = make_uint4(
                pack2(a1.x, c1.x), pack2(a1.y, c1.y), pack2(a1.z, c1.z), pack2(a1.w, c1.w));
        }

        // ---- GEMM2: m16n8k16 f16, warp m32 x f32, attn x v_hi ----
#pragma unroll
        for (int pc = 0; pc < 4; pc++) {
            int pw = pc * 8;
            unsigned af[2][4];
#pragma unroll
            for (int mt = 0; mt < 2; mt++) {
                int s0 = (mrb + mt * 16 + g) * 36 + pw + q;
                int s1 = s0 + 8 * 36;
                af[mt][0] = SSH[s0];
                af[mt][1] = SSH[s1];
                af[mt][2] = SSH[s0 + 4];
                af[mt][3] = SSH[s1 + 4];
            }
#pragma unroll
            for (int nt = 0; nt < 4; nt++) {
                int fc = wq * 32 + nt * 8 + g;
                unsigned bh2[2];
                bh2[0] = VH[(pw + q) * 136 + fc];
                bh2[1] = VH[(pw + q + 4) * 136 + fc];
#pragma unroll
                for (int mt = 0; mt < 2; mt++)
                    mma_f16(hacc[mt][nt], af[mt], bh2);
            }
        }
    }

    // ---- write h into hcat [b][n][h][f] ----
#pragma unroll
    for (int mt = 0; mt < 2; mt++)
#pragma unroll
        for (int nt = 0; nt < 4; nt++) {
            int mrow = m0 + mrb + mt * 16 + g;
            int fc = wq * 32 + nt * 8 + 2 * q;
            float* hp0 = hcat + (((long)b * Nn + mrow) * Hc + h) * Ec + fc;
            float* hp1 = hcat + (((long)b * Nn + mrow + 8) * Hc + h) * Ec + fc;
            *(float2*)hp0 = make_float2(hacc[mt][nt][0], hacc[mt][nt][1]);
            *(float2*)hp1 = make_float2(hacc[mt][nt][2], hacc[mt][nt][3]);
        }
}

// ---------------- launch ----------------
extern "C" void kernel_launch(void* const* d_in, const int* in_sizes, int n_in,
                              void* d_out, int out_size) {
    const float* x      = (const float*)d_in[0];
    const float* emb1_W = (const float*)d_in[1];
    const float* emb1_b = (const float*)d_in[2];
    const float* wq_W   = (const float*)d_in[3];
    const float* wq_b   = (const float*)d_in[4];
    const float* wv_W   = (const float*)d_in[7];
    const float* wv_b   = (const float*)d_in[8];
    const float* emb2_W = (const float*)d_in[9];
    const float* emb2_b = (const float*)d_in[10];
    float* out = (float*)d_out;

    float *gg, *gemb, *gq, *gv, *gu, *gr, *gh;
    cudaGetSymbolAddress((void**)&gg, g_g);
    cudaGetSymbolAddress((void**)&gemb, g_emb);
    cudaGetSymbolAddress((void**)&gq, g_q);
    cudaGetSymbolAddress((void**)&gv, g_v);
    cudaGetSymbolAddress((void**)&gu, g_u);
    cudaGetSymbolAddress((void**)&gr, g_r);
    cudaGetSymbolAddress((void**)&gh, g_h);

    static int smem_set = 0;
    if (!smem_set) {
        cudaFuncSetAttribute(attn_f16v4_kernel, cudaFuncAttributeMaxDynamicSharedMemorySize,
                             A8_WORDS * sizeof(unsigned));
        smem_set = 1;
    }

    // zero split-K accumulators
    zero_kernel<<<(Bc * Ec * DFc + 255) / 256, 256>>>(gg, Bc * Ec * DFc);
    zero_kernel<<<(Bc * Hc * DFc * Ec + 255) / 256, 256>>>(gu, Bc * Hc * DFc * Ec);

    // stage 1: g[b,e,d] = sum_m W1[e,m] x[b,m,d]   (split-K 16, atomic)
    f16_gemm<<<dim3(1, Bc, 16), 512>>>(emb1_W, 0, Bc, Nn, 1,
                                       x, (long)Nn * DFc, Bc, 1, DFc,
                                       nullptr, 0,
                                       gg, (long)Ec * DFc, Nn, 16, 0);

    // stage 2: emb[b,n,e] = sum_d x[b,n,d] g[b,e,d] + emb1_b[e]
    f16_gemm<<<dim3(16, Bc, 1), 512>>>(x, (long)Nn * DFc, 1, DFc, 1,
                                       gg, (long)Ec * DFc, Bc, DFc, 1,
                                       emb1_b, 0,
                                       gemb, (long)Nn * Ec, DFc, 1, 0);

    // stage 3: q, v projections per (b,h)
    f16_gemm<<<dim3(16, Bc * Hc, 1), 512>>>(gemb, (long)Nn * Ec, Hc, Ec, 1,
                                            wq_W, (long)Ec * Ec, Hc, Ec, 1,
                                            wq_b, Ec,
                                            gq, (long)Nn * Ec, Ec, 1, 0);
    f16_gemm<<<dim3(16, Bc * Hc, 1), 512>>>(gemb, (long)Nn * Ec, Hc, Ec, 1,
                                            wv_W, (long)Ec * Ec, Hc, Ec, 1,
                                            wv_b, Ec,
                                            gv, (long)Nn * Ec, Ec, 1, 0);

    // stage 4: u[b,h,d,f] = sum_n x[b,n,d] v[b,h,n,f]   (split-K 16, atomic)
    f16_gemm<<<dim3(1, Bc * Hc, 16), 512>>>(x, (long)Nn * DFc, Hc, 1, DFc,
                                            gv, (long)Nn * Ec, Bc * Hc, 1, Ec,
                                            nullptr, 0,
                                            gu, (long)DFc * Ec, Nn, 16, 0);

    // stage 5: r[b,h,n,d] = sum_f q[b,h,n,f] u[b,h,d,f]
    f16_gemm<<<dim3(16, Bc * Hc, 1), 512>>>(gq, (long)Nn * Ec, 1, Ec, 1,
                                            gu, (long)DFc * Ec, Bc * Hc, Ec, 1,
                                            nullptr, 0,
                                            gr, (long)Nn * DFc, Ec, 1, 0);

    // stage 6: fused attention (double-buffered fp16)
    attn_f16v4_kernel<<<dim3(Nn / 128, Bc * Hc), 512, A8_WORDS * sizeof(unsigned)>>>(
        gr, x, gv, gh);

    // stage 7: out = relu(hcat @ emb2_W^T + emb2_b)
    f16_gemm<<<dim3(16, Bc, 1), 512>>>(gh, (long)Nn * Hc * Ec, 1, Hc * Ec, 1,
                                       emb2_W, 0, 1, Hc * Ec, 1,
                                       emb2_b, 0,
                                       out, (long)Nn * Ec, Hc * Ec, 1, 1);
}